// round 8
// baseline (speedup 1.0000x reference)
#include <cuda_runtime.h>
#include <cuda_bf16.h>
#include <math.h>
#include <stdint.h>

// Problem constants (fixed shapes from setup_inputs)
#define BATCH 4
#define SEQ   2048
#define DMODEL 1024
#define NHEADS 16
#define FDIM  16
#define HDIM  64
#define NTOK  (BATCH*SEQ)          // 8192
#define QKDIM (NHEADS*FDIM)        // 256
#define VDIM  (NHEADS*HDIM)        // 1024
#define FEAT  273                  // 1 + 16 + 256
#define NCHUNK 16                  // 2048 / 128
#define CHUNK 128
#define KV_ELEMS (BATCH*NHEADS*HDIM*FEAT)   // 1,118,208
#define OUT_ELEMS (NTOK*DMODEL)             // 8,388,608
#define PROW 153                   // 1 + 16 + 136 packed (sym) feature rows
#define SDF_P (PROW*HDIM)          // 9792

// Scratch (device globals; no runtime allocation)
__device__ float g_Q[NTOK*QKDIM];
__device__ float g_K[NTOK*QKDIM];
__device__ float g_V[NTOK*VDIM];
__device__ float g_Y[NTOK*VDIM];
__device__ float g_DS[64*NCHUNK*SDF_P + 1024];   // packed chunk states

__device__ __forceinline__ uint32_t f2tf32(float x) {
    uint32_t u;
    asm("cvt.rna.tf32.f32 %0, %1;" : "=r"(u) : "f"(x));
    return u;
}

// ---------------------------------------------------------------------------
// tf32 GEMM (R4 design): 128x128 block, 4 warps of 64x64, BK=16,
// double-buffered smem [k][row] pad, one sync per K-tile.
// ---------------------------------------------------------------------------
struct GSmem {
    uint32_t As[2][16][132];
    uint32_t Bs[2][16][132];
};

__device__ __forceinline__ void gemm_tile(
    const float* __restrict__ A, const float* __restrict__ B,
    float* __restrict__ C, int N, int K, int bm, int bn, GSmem& sm) {
    const int tid  = threadIdx.x;
    const int warp = tid >> 5, lane = tid & 31;
    const int gid  = lane >> 2, tig = lane & 3;
    const int wm = (warp >> 1) * 64, wn = (warp & 1) * 64;

    const int lr = tid >> 2;
    const int kc = (tid & 3) << 2;
    const float* Ap = A + (size_t)(bm + lr) * K + kc;
    const float* Bp = B + (size_t)(bn + lr) * K + kc;
    const size_t row32 = (size_t)32 * K;

    float acc[4][8][4];
#pragma unroll
    for (int mt = 0; mt < 4; mt++)
#pragma unroll
        for (int nt = 0; nt < 8; nt++)
#pragma unroll
            for (int e = 0; e < 4; e++) acc[mt][nt][e] = 0.f;

    float4 ar[4], br[4];
#pragma unroll
    for (int p = 0; p < 4; p++) {
        ar[p] = *(const float4*)(Ap + p * row32);
        br[p] = *(const float4*)(Bp + p * row32);
    }
#pragma unroll
    for (int p = 0; p < 4; p++) {
        sm.As[0][kc + 0][lr + p * 32] = f2tf32(ar[p].x);
        sm.As[0][kc + 1][lr + p * 32] = f2tf32(ar[p].y);
        sm.As[0][kc + 2][lr + p * 32] = f2tf32(ar[p].z);
        sm.As[0][kc + 3][lr + p * 32] = f2tf32(ar[p].w);
        sm.Bs[0][kc + 0][lr + p * 32] = f2tf32(br[p].x);
        sm.Bs[0][kc + 1][lr + p * 32] = f2tf32(br[p].y);
        sm.Bs[0][kc + 2][lr + p * 32] = f2tf32(br[p].z);
        sm.Bs[0][kc + 3][lr + p * 32] = f2tf32(br[p].w);
    }
    __syncthreads();

    int cur = 0;
    for (int k0 = 0; k0 < K; k0 += 16) {
        const bool more = (k0 + 16 < K);
        if (more) {
#pragma unroll
            for (int p = 0; p < 4; p++) {
                ar[p] = *(const float4*)(Ap + k0 + 16 + p * row32);
                br[p] = *(const float4*)(Bp + k0 + 16 + p * row32);
            }
        }

#pragma unroll
        for (int ks = 0; ks < 2; ks++) {
            const int kk = ks * 8;
            uint32_t af[4][4], bf[8][2];
#pragma unroll
            for (int mt = 0; mt < 4; mt++) {
                const int m = wm + mt * 16 + gid;
                af[mt][0] = sm.As[cur][kk + tig][m];
                af[mt][1] = sm.As[cur][kk + tig][m + 8];
                af[mt][2] = sm.As[cur][kk + tig + 4][m];
                af[mt][3] = sm.As[cur][kk + tig + 4][m + 8];
            }
#pragma unroll
            for (int nt = 0; nt < 8; nt++) {
                const int n = wn + nt * 8 + gid;
                bf[nt][0] = sm.Bs[cur][kk + tig][n];
                bf[nt][1] = sm.Bs[cur][kk + tig + 4][n];
            }
#pragma unroll
            for (int mt = 0; mt < 4; mt++)
#pragma unroll
                for (int nt = 0; nt < 8; nt++) {
                    asm volatile(
                        "mma.sync.aligned.m16n8k8.row.col.f32.tf32.tf32.f32 "
                        "{%0,%1,%2,%3}, {%4,%5,%6,%7}, {%8,%9}, {%0,%1,%2,%3};"
                        : "+f"(acc[mt][nt][0]), "+f"(acc[mt][nt][1]),
                          "+f"(acc[mt][nt][2]), "+f"(acc[mt][nt][3])
                        : "r"(af[mt][0]), "r"(af[mt][1]),
                          "r"(af[mt][2]), "r"(af[mt][3]),
                          "r"(bf[nt][0]), "r"(bf[nt][1]));
                }
        }

        if (more) {
            const int nxt = cur ^ 1;
#pragma unroll
            for (int p = 0; p < 4; p++) {
                sm.As[nxt][kc + 0][lr + p * 32] = f2tf32(ar[p].x);
                sm.As[nxt][kc + 1][lr + p * 32] = f2tf32(ar[p].y);
                sm.As[nxt][kc + 2][lr + p * 32] = f2tf32(ar[p].z);
                sm.As[nxt][kc + 3][lr + p * 32] = f2tf32(ar[p].w);
                sm.Bs[nxt][kc + 0][lr + p * 32] = f2tf32(br[p].x);
                sm.Bs[nxt][kc + 1][lr + p * 32] = f2tf32(br[p].y);
                sm.Bs[nxt][kc + 2][lr + p * 32] = f2tf32(br[p].z);
                sm.Bs[nxt][kc + 3][lr + p * 32] = f2tf32(br[p].w);
            }
            __syncthreads();
        }
        cur ^= 1;
    }

#pragma unroll
    for (int mt = 0; mt < 4; mt++) {
        const int r0 = bm + wm + mt * 16 + gid;
#pragma unroll
        for (int nt = 0; nt < 8; nt++) {
            const int cc = bn + wn + nt * 8 + tig * 2;
            *(float2*)&C[(size_t)r0 * N + cc] =
                make_float2(acc[mt][nt][0], acc[mt][nt][1]);
            *(float2*)&C[(size_t)(r0 + 8) * N + cc] =
                make_float2(acc[mt][nt][2], acc[mt][nt][3]);
        }
    }
}

__global__ __launch_bounds__(128)
void tgemm_nt(const float* __restrict__ A, const float* __restrict__ B,
              float* __restrict__ C, int M, int N, int K) {
    __shared__ GSmem sm;
    gemm_tile(A, B, C, N, K, blockIdx.x * 128, blockIdx.y * 128, sm);
}

// ---------------------------------------------------------------------------
// Kernel A: per-chunk state increment -> PACKED symmetric layout.
// Row 0: sum v. Rows 1+i: 0.5*sum k_i v. Rows 17+p (p=i(i+1)/2+j, j<=i):
// c2*(1 or 2)*sum k_i k_j v.  f split over blockIdx.z.
// ---------------------------------------------------------------------------
__global__ __launch_bounds__(256, 3)
void state_kernel(const float* __restrict__ Km, const float* __restrict__ V,
                  float* __restrict__ DS) {
    __shared__ float ks[32][16];
    __shared__ float vs[32][32];
    const int ck = blockIdx.x;
    const int bh = blockIdx.y;
    const int fh = blockIdx.z;
    const int b = bh >> 4, h = bh & 15;
    const int tid = threadIdx.x;
    const int i = tid >> 4;
    const int fq = tid & 15;
    const int tokb = b * SEQ + ck * CHUNK;
    const int fbase = fh * 32;

    float m2[16][2];
#pragma unroll
    for (int j = 0; j < 16; j++) { m2[j][0] = 0.f; m2[j][1] = 0.f; }
    float m1[2] = {0.f, 0.f};
    float s0[2] = {0.f, 0.f};

    for (int nb = 0; nb < CHUNK; nb += 32) {
        __syncthreads();
        for (int t = tid; t < 128; t += 256) {
            int r = t >> 2, c4 = (t & 3) << 2;
            *(float4*)&ks[r][c4] =
                *(const float4*)&Km[(size_t)(tokb + nb + r) * QKDIM + h * FDIM + c4];
        }
        {
            int r = tid >> 3, c4 = (tid & 7) << 2;
            *(float4*)&vs[r][c4] =
                *(const float4*)&V[(size_t)(tokb + nb + r) * VDIM + h * HDIM + fbase + c4];
        }
        __syncthreads();
#pragma unroll 4
        for (int r = 0; r < 32; r++) {
            const float ki = ks[r][i];
            const float2 v2 = *(const float2*)&vs[r][fq * 2];
            m1[0] = fmaf(ki, v2.x, m1[0]);
            m1[1] = fmaf(ki, v2.y, m1[1]);
            if (i == 0) { s0[0] += v2.x; s0[1] += v2.y; }
#pragma unroll
            for (int j = 0; j < 16; j++) {
                const float kk = ki * ks[r][j];
                m2[j][0] = fmaf(kk, v2.x, m2[j][0]);
                m2[j][1] = fmaf(kk, v2.y, m2[j][1]);
            }
        }
    }

    float* base = DS + (size_t)(bh * NCHUNK + ck) * SDF_P;
    const float c2 = 0.17677669529663687f;   // 1/(4*sqrt(2))
    const int pbase = 17 + i * (i + 1) / 2;
#pragma unroll
    for (int ff = 0; ff < 2; ff++) {
        const int f = fbase + fq * 2 + ff;
#pragma unroll
        for (int j = 0; j < 16; j++) {
            if (j <= i) {
                const float w = (j == i) ? c2 : 2.f * c2;
                base[(pbase + j) * HDIM + f] = m2[j][ff] * w;
            }
        }
        base[(1 + i) * HDIM + f] = m1[ff] * 0.5f;
        if (i == 0) base[f] = s0[ff];
    }
}

// ---------------------------------------------------------------------------
// Kernel B: exclusive scan over packed chunk states; inclusive total ->
// kv_state output (unpacked + mirrored to full [f,273] layout).
// ---------------------------------------------------------------------------
__global__ void scan_kernel(float* __restrict__ DS, float* __restrict__ kv_out) {
    const int bh = blockIdx.y;
    const int e = blockIdx.x * 256 + threadIdx.x;
    if (e >= SDF_P) return;
    size_t base = (size_t)bh * NCHUNK * SDF_P + e;
    float run = 0.f;
#pragma unroll
    for (int c = 0; c < NCHUNK; c++) {
        float v = DS[base + (size_t)c * SDF_P];
        DS[base + (size_t)c * SDF_P] = run;
        run += v;
    }
    if (kv_out) {
        const int dp = e >> 6, f = e & 63;
        float* kb = kv_out + (size_t)bh * (HDIM * FEAT) + (size_t)f * FEAT;
        if (dp < 17) {
            kb[dp] = run;
        } else {
            const int p = dp - 17;
            int i = (int)((sqrtf(8.f * p + 1.f) - 1.f) * 0.5f);
            if ((i + 1) * (i + 2) / 2 <= p) i++;
            if (i * (i + 1) / 2 > p) i--;
            const int j = p - i * (i + 1) / 2;
            const float v = (i == j) ? run : run * 0.5f;
            kb[17 + i * 16 + j] = v;
            kb[17 + j * 16 + i] = v;
        }
    }
}

// ---------------------------------------------------------------------------
// Kernel C: y = qf . S_prev (packed sym) + intra-chunk causal, RMSNorm + g.
// Dynamic smem; double-buffered quad segments, 1 sync per segment.
// ---------------------------------------------------------------------------
#define A_QS(r,c)    dyn[(r)*16+(c)]
#define A_KC(r,c)    dyn[2048+(r)*16+(c)]
#define A_VC(r,c)    dyn[4096+(r)*64+(c)]
#define A_SS0(r,c)   dyn[12288+(r)*64+(c)]
#define A_SSB(b,r,c) dyn[13376+(b)*1024+(r)*64+(c)]
#define A_GS(c)      dyn[15424+(c)]
#define ATTN_SMEM    ((15424+64)*4)   // 61,952 bytes

__global__ __launch_bounds__(256)
void attn_out_kernel(const float* __restrict__ Q, const float* __restrict__ Km,
                     const float* __restrict__ V, const float* __restrict__ Sprev,
                     const float* __restrict__ g, float* __restrict__ Y) {
    extern __shared__ float dyn[];
    __shared__ uchar2 ptab[136];
    const int ck = blockIdx.x;
    const int bh = blockIdx.y;
    const int b = bh >> 4, h = bh & 15;
    const int tid = threadIdx.x;
    const int fg = tid & 7, tg = tid >> 3;
    const int f0 = fg * 8;
    const int t0 = tg * 4;
    const int tok0 = b * SEQ + ck * CHUNK;
    const float SC  = 0.4204482076268573f;    // sqrt(1/(4*sqrt2))
    const float LIN = 1.1892071150027210f;    // 0.5/SC
    const float DOT = 2.3784142300054421f;    // 1/SC
    const float* Sp = Sprev + (size_t)(bh * NCHUNK + ck) * SDF_P;

    // ---- stage Q (scaled), K, V, g, S rows 0..16, seg0 of quad, pair table
    for (int t = tid; t < 512; t += 256) {
        int r = t >> 2, c4 = (t & 3) << 2;
        float4 qv = *(const float4*)&Q[(size_t)(tok0 + r) * QKDIM + h * FDIM + c4];
        A_QS(r, c4 + 0) = qv.x * SC; A_QS(r, c4 + 1) = qv.y * SC;
        A_QS(r, c4 + 2) = qv.z * SC; A_QS(r, c4 + 3) = qv.w * SC;
        *(float4*)&A_KC(r, c4) =
            *(const float4*)&Km[(size_t)(tok0 + r) * QKDIM + h * FDIM + c4];
    }
    for (int t = tid; t < 2048; t += 256) {
        int r = t >> 4, c4 = (t & 15) << 2;
        *(float4*)&A_VC(r, c4) =
            *(const float4*)&V[(size_t)(tok0 + r) * VDIM + h * HDIM + c4];
    }
    if (tid < 64) A_GS(tid) = g[tid];
    for (int t = tid; t < 272; t += 256) {
        int r = t >> 4, c4 = (t & 15) << 2;
        *(float4*)&A_SS0(r, c4) = *(const float4*)&Sp[r * HDIM + c4];
    }
    {   // preload quad segment 0 -> buffer 0 (packed rows 17..32)
        int r = tid >> 4, c4 = (tid & 15) << 2;
        *(float4*)&A_SSB(0, r, c4) = *(const float4*)&Sp[(17 + r) * HDIM + c4];
    }
    if (tid < 136) {
        int p = tid;
        int i = (int)((sqrtf(8.f * p + 1.f) - 1.f) * 0.5f);
        if ((i + 1) * (i + 2) / 2 <= p) i++;
        if (i * (i + 1) / 2 > p) i--;
        ptab[p] = make_uchar2((unsigned char)i,
                              (unsigned char)(p - i * (i + 1) / 2));
    }
    __syncthreads();

    float acc[4][8];

    // ----- inter-chunk: const + linear (rows 0..16) -----
    {
        float sv[8];
        *(float4*)&sv[0] = *(const float4*)&A_SS0(0, f0);
        *(float4*)&sv[4] = *(const float4*)&A_SS0(0, f0 + 4);
#pragma unroll
        for (int t = 0; t < 4; t++)
#pragma unroll
            for (int f = 0; f < 8; f++) acc[t][f] = sv[f];
#pragma unroll
        for (int j = 0; j < 16; j++) {
            *(float4*)&sv[0] = *(const float4*)&A_SS0(1 + j, f0);
            *(float4*)&sv[4] = *(const float4*)&A_SS0(1 + j, f0 + 4);
#pragma unroll
            for (int t = 0; t < 4; t++) {
                const float m = A_QS(t0 + t, j) * LIN;
#pragma unroll
                for (int f = 0; f < 8; f++) acc[t][f] = fmaf(m, sv[f], acc[t][f]);
            }
        }
    }

    // ----- inter-chunk: quadratic (136 packed rows, 9 dbl-buffered segments)
#define QROW(P_, RR_, BUF_)                                                    \
    {                                                                          \
        const uchar2 ij = ptab[P_];                                            \
        float sv[8];                                                           \
        *(float4*)&sv[0] = *(const float4*)&A_SSB(BUF_, RR_, f0);              \
        *(float4*)&sv[4] = *(const float4*)&A_SSB(BUF_, RR_, f0 + 4);          \
        _Pragma("unroll")                                                      \
        for (int t = 0; t < 4; t++) {                                          \
            const float m = A_QS(t0 + t, ij.x) * A_QS(t0 + t, ij.y);           \
            _Pragma("unroll")                                                  \
            for (int f = 0; f < 8; f++) acc[t][f] = fmaf(m, sv[f], acc[t][f]); \
        }                                                                      \
    }

    {
        int buf = 0;
        const int pr = tid >> 4, pc = (tid & 15) << 2;
        for (int s = 0; s < 9; s++) {
            float4 pf;
            bool havepf = false;
            if (s < 8) {
                const int nrows = (s < 7) ? 16 : 8;
                if (pr < nrows) {
                    pf = *(const float4*)&Sp[(17 + 16 * (s + 1) + pr) * HDIM + pc];
                    havepf = true;
                }
            }
            if (s < 8) {
#pragma unroll
                for (int rr = 0; rr < 16; rr++) QROW(16 * s + rr, rr, buf);
            } else {
#pragma unroll
                for (int rr = 0; rr < 8; rr++) QROW(128 + rr, rr, buf);
            }
            if (s < 8) {
                if (havepf)
                    *(float4*)&A_SSB(buf ^ 1, pr, pc) = pf;
                __syncthreads();
                buf ^= 1;
            }
        }
    }

    // ----- intra-chunk causal: A = 1 + s/4 + s^2/32 -----
    float qr[4][16];
#pragma unroll
    for (int t = 0; t < 4; t++)
#pragma unroll
        for (int i = 0; i < 16; i++) qr[t][i] = A_QS(t0 + t, i);

    const int mEnd = ((tid >> 5) + 1) * 16;
    for (int m = 0; m < mEnd; m++) {
        float s[4] = {0.f, 0.f, 0.f, 0.f};
#pragma unroll
        for (int i = 0; i < 16; i++) {
            const float ki = A_KC(m, i);
            s[0] = fmaf(qr[0][i], ki, s[0]);
            s[1] = fmaf(qr[1][i], ki, s[1]);
            s[2] = fmaf(qr[2][i], ki, s[2]);
            s[3] = fmaf(qr[3][i], ki, s[3]);
        }
        float a[4];
#pragma unroll
        for (int t = 0; t < 4; t++) {
            const float sd = s[t] * DOT;
            float av = fmaf(sd, 0.25f, 1.0f);
            av = fmaf(sd * sd, 0.03125f, av);
            a[t] = (m <= t0 + t) ? av : 0.f;
        }
        float v[8];
        *(float4*)&v[0] = *(const float4*)&A_VC(m, f0);
        *(float4*)&v[4] = *(const float4*)&A_VC(m, f0 + 4);
#pragma unroll
        for (int t = 0; t < 4; t++)
#pragma unroll
            for (int f = 0; f < 8; f++)
                acc[t][f] = fmaf(a[t], v[f], acc[t][f]);
    }

    // ----- RMSNorm + gate + store -----
#pragma unroll
    for (int t = 0; t < 4; t++) {
        float ss = 0.f;
#pragma unroll
        for (int f = 0; f < 8; f++) ss = fmaf(acc[t][f], acc[t][f], ss);
        ss += __shfl_xor_sync(0xffffffffu, ss, 1);
        ss += __shfl_xor_sync(0xffffffffu, ss, 2);
        ss += __shfl_xor_sync(0xffffffffu, ss, 4);
        const float rms = rsqrtf(ss * (1.0f / 64.0f) + 1e-5f);
        float* yp = Y + (size_t)(tok0 + t0 + t) * VDIM + h * HDIM + f0;
        float4 o0, o1;
        o0.x = acc[t][0] * rms * A_GS(f0 + 0);
        o0.y = acc[t][1] * rms * A_GS(f0 + 1);
        o0.z = acc[t][2] * rms * A_GS(f0 + 2);
        o0.w = acc[t][3] * rms * A_GS(f0 + 3);
        o1.x = acc[t][4] * rms * A_GS(f0 + 4);
        o1.y = acc[t][5] * rms * A_GS(f0 + 5);
        o1.z = acc[t][6] * rms * A_GS(f0 + 6);
        o1.w = acc[t][7] * rms * A_GS(f0 + 7);
        *(float4*)&yp[0] = o0;
        *(float4*)&yp[4] = o1;
    }
}

// ---------------------------------------------------------------------------
extern "C" void kernel_launch(void* const* d_in, const int* in_sizes, int n_in,
                              void* d_out, int out_size) {
    const float* X  = (const float*)d_in[0];
    const float* Wq = (const float*)d_in[1];
    const float* Wk = (const float*)d_in[2];
    const float* Wv = (const float*)d_in[3];
    const float* Wo = (const float*)d_in[4];
    const float* g  = (const float*)d_in[5];
    float* out = (float*)d_out;

    float *Qb, *Kb, *Vb, *Yb, *Sb;
    cudaGetSymbolAddress((void**)&Qb, g_Q);
    cudaGetSymbolAddress((void**)&Kb, g_K);
    cudaGetSymbolAddress((void**)&Vb, g_V);
    cudaGetSymbolAddress((void**)&Yb, g_Y);
    cudaGetSymbolAddress((void**)&Sb, g_DS);

    static int smem_set = 0;
    if (!smem_set) {
        cudaFuncSetAttribute(attn_out_kernel,
                             cudaFuncAttributeMaxDynamicSharedMemorySize,
                             ATTN_SMEM);
        smem_set = 1;
    }

    // Projections (separate launches — R4 proven config)
    tgemm_nt<<<dim3(NTOK / 128, QKDIM / 128), 128>>>(X, Wq, Qb, NTOK, QKDIM, DMODEL);
    tgemm_nt<<<dim3(NTOK / 128, QKDIM / 128), 128>>>(X, Wk, Kb, NTOK, QKDIM, DMODEL);
    tgemm_nt<<<dim3(NTOK / 128, VDIM / 128),  128>>>(X, Wv, Vb, NTOK, VDIM,  DMODEL);

    // Chunked linear attention (packed symmetric states)
    float* kv_out = (out_size >= OUT_ELEMS + KV_ELEMS) ? (out + OUT_ELEMS) : nullptr;
    state_kernel<<<dim3(NCHUNK, BATCH * NHEADS, 2), 256>>>(Kb, Vb, Sb);
    scan_kernel<<<dim3((SDF_P + 255) / 256, BATCH * NHEADS), 256>>>(Sb, kv_out);
    attn_out_kernel<<<dim3(NCHUNK, BATCH * NHEADS), 256, ATTN_SMEM>>>(
        Qb, Kb, Vb, Sb, g, Yb);

    // Output projection
    tgemm_nt<<<dim3(NTOK / 128, DMODEL / 128), 128>>>(Yb, Wo, out, NTOK, DMODEL, DMODEL);
}

// round 9
// speedup vs baseline: 1.5371x; 1.5371x over previous
#include <cuda_runtime.h>
#include <cuda_bf16.h>
#include <math.h>
#include <stdint.h>

// Problem constants (fixed shapes from setup_inputs)
#define BATCH 4
#define SEQ   2048
#define DMODEL 1024
#define NHEADS 16
#define FDIM  16
#define HDIM  64
#define NTOK  (BATCH*SEQ)          // 8192
#define QKDIM (NHEADS*FDIM)        // 256
#define VDIM  (NHEADS*HDIM)        // 1024
#define FEAT  273                  // 1 + 16 + 256
#define NCHUNK 16                  // 2048 / 128
#define CHUNK 128
#define KV_ELEMS (BATCH*NHEADS*HDIM*FEAT)   // 1,118,208
#define OUT_ELEMS (NTOK*DMODEL)             // 8,388,608
#define SDF (FEAT*HDIM)            // 17472 (divisible by 4)

// Scratch (device globals; no runtime allocation)
__device__ float g_Q[NTOK*QKDIM];
__device__ float g_K[NTOK*QKDIM];
__device__ float g_V[NTOK*VDIM];
__device__ float g_Y[NTOK*VDIM];
__device__ float g_DS[64*NCHUNK*SDF];

__device__ __forceinline__ uint32_t f2tf32(float x) {
    uint32_t u;
    asm("cvt.rna.tf32.f32 %0, %1;" : "=r"(u) : "f"(x));
    return u;
}

// ---------------------------------------------------------------------------
// tf32 GEMM (R4 design, proven): 128x128 block, 4 warps of 64x64, BK=16,
// double-buffered smem [k][row] pad 132, one sync per K-tile.
// ---------------------------------------------------------------------------
struct GSmem {
    uint32_t As[2][16][132];
    uint32_t Bs[2][16][132];
};

__device__ __forceinline__ void gemm_tile(
    const float* __restrict__ A, const float* __restrict__ B,
    float* __restrict__ C, int N, int K, int bm, int bn, GSmem& sm) {
    const int tid  = threadIdx.x;
    const int warp = tid >> 5, lane = tid & 31;
    const int gid  = lane >> 2, tig = lane & 3;
    const int wm = (warp >> 1) * 64, wn = (warp & 1) * 64;

    const int lr = tid >> 2;
    const int kc = (tid & 3) << 2;
    const float* Ap = A + (size_t)(bm + lr) * K + kc;
    const float* Bp = B + (size_t)(bn + lr) * K + kc;
    const size_t row32 = (size_t)32 * K;

    float acc[4][8][4];
#pragma unroll
    for (int mt = 0; mt < 4; mt++)
#pragma unroll
        for (int nt = 0; nt < 8; nt++)
#pragma unroll
            for (int e = 0; e < 4; e++) acc[mt][nt][e] = 0.f;

    float4 ar[4], br[4];
#pragma unroll
    for (int p = 0; p < 4; p++) {
        ar[p] = *(const float4*)(Ap + p * row32);
        br[p] = *(const float4*)(Bp + p * row32);
    }
#pragma unroll
    for (int p = 0; p < 4; p++) {
        sm.As[0][kc + 0][lr + p * 32] = f2tf32(ar[p].x);
        sm.As[0][kc + 1][lr + p * 32] = f2tf32(ar[p].y);
        sm.As[0][kc + 2][lr + p * 32] = f2tf32(ar[p].z);
        sm.As[0][kc + 3][lr + p * 32] = f2tf32(ar[p].w);
        sm.Bs[0][kc + 0][lr + p * 32] = f2tf32(br[p].x);
        sm.Bs[0][kc + 1][lr + p * 32] = f2tf32(br[p].y);
        sm.Bs[0][kc + 2][lr + p * 32] = f2tf32(br[p].z);
        sm.Bs[0][kc + 3][lr + p * 32] = f2tf32(br[p].w);
    }
    __syncthreads();

    int cur = 0;
    for (int k0 = 0; k0 < K; k0 += 16) {
        const bool more = (k0 + 16 < K);
        if (more) {
#pragma unroll
            for (int p = 0; p < 4; p++) {
                ar[p] = *(const float4*)(Ap + k0 + 16 + p * row32);
                br[p] = *(const float4*)(Bp + k0 + 16 + p * row32);
            }
        }

#pragma unroll
        for (int ks = 0; ks < 2; ks++) {
            const int kk = ks * 8;
            uint32_t af[4][4], bf[8][2];
#pragma unroll
            for (int mt = 0; mt < 4; mt++) {
                const int m = wm + mt * 16 + gid;
                af[mt][0] = sm.As[cur][kk + tig][m];
                af[mt][1] = sm.As[cur][kk + tig][m + 8];
                af[mt][2] = sm.As[cur][kk + tig + 4][m];
                af[mt][3] = sm.As[cur][kk + tig + 4][m + 8];
            }
#pragma unroll
            for (int nt = 0; nt < 8; nt++) {
                const int n = wn + nt * 8 + gid;
                bf[nt][0] = sm.Bs[cur][kk + tig][n];
                bf[nt][1] = sm.Bs[cur][kk + tig + 4][n];
            }
#pragma unroll
            for (int mt = 0; mt < 4; mt++)
#pragma unroll
                for (int nt = 0; nt < 8; nt++) {
                    asm volatile(
                        "mma.sync.aligned.m16n8k8.row.col.f32.tf32.tf32.f32 "
                        "{%0,%1,%2,%3}, {%4,%5,%6,%7}, {%8,%9}, {%0,%1,%2,%3};"
                        : "+f"(acc[mt][nt][0]), "+f"(acc[mt][nt][1]),
                          "+f"(acc[mt][nt][2]), "+f"(acc[mt][nt][3])
                        : "r"(af[mt][0]), "r"(af[mt][1]),
                          "r"(af[mt][2]), "r"(af[mt][3]),
                          "r"(bf[nt][0]), "r"(bf[nt][1]));
                }
        }

        if (more) {
            const int nxt = cur ^ 1;
#pragma unroll
            for (int p = 0; p < 4; p++) {
                sm.As[nxt][kc + 0][lr + p * 32] = f2tf32(ar[p].x);
                sm.As[nxt][kc + 1][lr + p * 32] = f2tf32(ar[p].y);
                sm.As[nxt][kc + 2][lr + p * 32] = f2tf32(ar[p].z);
                sm.As[nxt][kc + 3][lr + p * 32] = f2tf32(ar[p].w);
                sm.Bs[nxt][kc + 0][lr + p * 32] = f2tf32(br[p].x);
                sm.Bs[nxt][kc + 1][lr + p * 32] = f2tf32(br[p].y);
                sm.Bs[nxt][kc + 2][lr + p * 32] = f2tf32(br[p].z);
                sm.Bs[nxt][kc + 3][lr + p * 32] = f2tf32(br[p].w);
            }
            __syncthreads();
        }
        cur ^= 1;
    }

#pragma unroll
    for (int mt = 0; mt < 4; mt++) {
        const int r0 = bm + wm + mt * 16 + gid;
#pragma unroll
        for (int nt = 0; nt < 8; nt++) {
            const int cc = bn + wn + nt * 8 + tig * 2;
            *(float2*)&C[(size_t)r0 * N + cc] =
                make_float2(acc[mt][nt][0], acc[mt][nt][1]);
            *(float2*)&C[(size_t)(r0 + 8) * N + cc] =
                make_float2(acc[mt][nt][2], acc[mt][nt][3]);
        }
    }
}

__global__ __launch_bounds__(128)
void tgemm_nt(const float* __restrict__ A, const float* __restrict__ B,
              float* __restrict__ C, int M, int N, int K) {
    __shared__ GSmem sm;
    gemm_tile(A, B, C, N, K, blockIdx.x * 128, blockIdx.y * 128, sm);
}

// Fused Wq+Wk projection: grid (NTOK/128, 4). y<2 -> Q, else -> K.
__global__ __launch_bounds__(128)
void qk_gemm(const float* __restrict__ X,
             const float* __restrict__ Wq, const float* __restrict__ Wk,
             float* __restrict__ Qb, float* __restrict__ Kb) {
    __shared__ GSmem sm;
    const int y = blockIdx.y;
    const float* B = (y < 2) ? Wq : Wk;
    float* C = (y < 2) ? Qb : Kb;
    const int bn = (y & 1) * 128;
    gemm_tile(X, B, C, QKDIM, DMODEL, blockIdx.x * 128, bn, sm);
}

// ---------------------------------------------------------------------------
// Kernel A: per-chunk state increment (unpacked), f split over blockIdx.z
// ---------------------------------------------------------------------------
__global__ __launch_bounds__(256, 3)
void state_kernel(const float* __restrict__ Km, const float* __restrict__ V,
                  float* __restrict__ DS) {
    __shared__ float ks[32][16];
    __shared__ float vs[32][32];
    const int ck = blockIdx.x;
    const int bh = blockIdx.y;
    const int fh = blockIdx.z;
    const int b = bh >> 4, h = bh & 15;
    const int tid = threadIdx.x;
    const int i = tid >> 4;
    const int fq = tid & 15;
    const int tokb = b * SEQ + ck * CHUNK;
    const int fbase = fh * 32;

    float m2[16][2];
#pragma unroll
    for (int j = 0; j < 16; j++) { m2[j][0] = 0.f; m2[j][1] = 0.f; }
    float m1[2] = {0.f, 0.f};
    float s0[2] = {0.f, 0.f};

    for (int nb = 0; nb < CHUNK; nb += 32) {
        __syncthreads();
        for (int t = tid; t < 128; t += 256) {
            int r = t >> 2, c4 = (t & 3) << 2;
            *(float4*)&ks[r][c4] =
                *(const float4*)&Km[(size_t)(tokb + nb + r) * QKDIM + h * FDIM + c4];
        }
        {
            int r = tid >> 3, c4 = (tid & 7) << 2;
            *(float4*)&vs[r][c4] =
                *(const float4*)&V[(size_t)(tokb + nb + r) * VDIM + h * HDIM + fbase + c4];
        }
        __syncthreads();
#pragma unroll 4
        for (int r = 0; r < 32; r++) {
            const float ki = ks[r][i];
            const float2 v2 = *(const float2*)&vs[r][fq * 2];
            m1[0] = fmaf(ki, v2.x, m1[0]);
            m1[1] = fmaf(ki, v2.y, m1[1]);
            if (i == 0) { s0[0] += v2.x; s0[1] += v2.y; }
#pragma unroll
            for (int j = 0; j < 16; j++) {
                const float kk = ki * ks[r][j];
                m2[j][0] = fmaf(kk, v2.x, m2[j][0]);
                m2[j][1] = fmaf(kk, v2.y, m2[j][1]);
            }
        }
    }

    float* base = DS + (size_t)(bh * NCHUNK + ck) * SDF;
    const float c2 = 0.17677669529663687f;   // 1/(4*sqrt(2))
#pragma unroll
    for (int ff = 0; ff < 2; ff++) {
        const int f = fbase + fq * 2 + ff;
#pragma unroll
        for (int j = 0; j < 16; j++)
            base[(17 + i * 16 + j) * HDIM + f] = m2[j][ff] * c2;
        base[(1 + i) * HDIM + f] = m1[ff] * 0.5f;
        if (i == 0) base[f] = s0[ff];
    }
}

// ---------------------------------------------------------------------------
// Kernel B: exclusive scan (float4-vectorized); inclusive total -> kv_state
// ---------------------------------------------------------------------------
__global__ void scan_kernel(float* __restrict__ DS, float* __restrict__ kv_out) {
    const int bh = blockIdx.y;
    const int e4 = (blockIdx.x * 256 + threadIdx.x) * 4;
    if (e4 >= SDF) return;
    size_t base = (size_t)bh * NCHUNK * SDF + e4;
    float4 run = make_float4(0.f, 0.f, 0.f, 0.f);
#pragma unroll
    for (int c = 0; c < NCHUNK; c++) {
        float4 v = *(float4*)&DS[base + (size_t)c * SDF];
        *(float4*)&DS[base + (size_t)c * SDF] = run;
        run.x += v.x; run.y += v.y; run.z += v.z; run.w += v.w;
    }
    if (kv_out) {
        const int d = e4 >> 6, f0 = e4 & 63;
        float* kb = kv_out + (size_t)bh * (HDIM * FEAT) + d;
        kb[(size_t)(f0 + 0) * FEAT] = run.x;
        kb[(size_t)(f0 + 1) * FEAT] = run.y;
        kb[(size_t)(f0 + 2) * FEAT] = run.z;
        kb[(size_t)(f0 + 3) * FEAT] = run.w;
    }
}

// ---------------------------------------------------------------------------
// Kernel C: y = qf . S_prev + intra-chunk causal, RMSNorm + g  (R4-exact)
// ---------------------------------------------------------------------------
__global__ __launch_bounds__(256, 2)
void attn_out_kernel(const float* __restrict__ Q, const float* __restrict__ Km,
                     const float* __restrict__ V, const float* __restrict__ Sprev,
                     const float* __restrict__ g, float* __restrict__ Y) {
    __shared__ float Qs[128][16];
    __shared__ float Kc[128][16];
    __shared__ float Vc[128][64];
    __shared__ float Ss[17][64];
    __shared__ float gs[64];
    const int ck = blockIdx.x;
    const int bh = blockIdx.y;
    const int b = bh >> 4, h = bh & 15;
    const int tid = threadIdx.x;
    const int fg = tid & 7, tg = tid >> 3;
    const int f0 = fg * 8;
    const int t0 = tg * 4;
    const int tok0 = b * SEQ + ck * CHUNK;
    const float SC  = 0.4204482076268573f;
    const float LIN = 1.1892071150027210f;
    const float DOT = 2.3784142300054421f;

    for (int t = tid; t < 512; t += 256) {
        int r = t >> 2, c4 = (t & 3) << 2;
        float4 qv = *(const float4*)&Q[(size_t)(tok0 + r) * QKDIM + h * FDIM + c4];
        Qs[r][c4 + 0] = qv.x * SC; Qs[r][c4 + 1] = qv.y * SC;
        Qs[r][c4 + 2] = qv.z * SC; Qs[r][c4 + 3] = qv.w * SC;
        *(float4*)&Kc[r][c4] =
            *(const float4*)&Km[(size_t)(tok0 + r) * QKDIM + h * FDIM + c4];
    }
    for (int t = tid; t < 2048; t += 256) {
        int r = t >> 4, c4 = (t & 15) << 2;
        *(float4*)&Vc[r][c4] =
            *(const float4*)&V[(size_t)(tok0 + r) * VDIM + h * HDIM + c4];
    }
    if (tid < 64) gs[tid] = g[tid];
    const float* Sp = Sprev + (size_t)(bh * NCHUNK + ck) * SDF;
    for (int t = tid; t < 272; t += 256) {
        int r = t >> 4, c4 = (t & 15) << 2;
        *(float4*)&Ss[r][c4] = *(const float4*)&Sp[r * HDIM + c4];
    }
    __syncthreads();

    float acc[4][8];
    {
        float sv[8];
        *(float4*)&sv[0] = *(const float4*)&Ss[0][f0];
        *(float4*)&sv[4] = *(const float4*)&Ss[0][f0 + 4];
#pragma unroll
        for (int t = 0; t < 4; t++)
#pragma unroll
            for (int f = 0; f < 8; f++) acc[t][f] = sv[f];
#pragma unroll
        for (int j = 0; j < 16; j++) {
            *(float4*)&sv[0] = *(const float4*)&Ss[1 + j][f0];
            *(float4*)&sv[4] = *(const float4*)&Ss[1 + j][f0 + 4];
#pragma unroll
            for (int t = 0; t < 4; t++) {
                const float m = Qs[t0 + t][j] * LIN;
#pragma unroll
                for (int f = 0; f < 8; f++) acc[t][f] = fmaf(m, sv[f], acc[t][f]);
            }
        }
    }

    for (int i = 0; i < 16; i++) {
        __syncthreads();
        {
            int r = tid >> 4, c4 = (tid & 15) << 2;
            *(float4*)&Ss[r][c4] =
                *(const float4*)&Sp[(17 + i * 16 + r) * HDIM + c4];
        }
        __syncthreads();
        float qi[4];
#pragma unroll
        for (int t = 0; t < 4; t++) qi[t] = Qs[t0 + t][i];
#pragma unroll
        for (int j = 0; j < 16; j++) {
            float sv[8];
            *(float4*)&sv[0] = *(const float4*)&Ss[j][f0];
            *(float4*)&sv[4] = *(const float4*)&Ss[j][f0 + 4];
#pragma unroll
            for (int t = 0; t < 4; t++) {
                const float m = qi[t] * Qs[t0 + t][j];
#pragma unroll
                for (int f = 0; f < 8; f++) acc[t][f] = fmaf(m, sv[f], acc[t][f]);
            }
        }
    }

    float qr[4][16];
#pragma unroll
    for (int t = 0; t < 4; t++)
#pragma unroll
        for (int i = 0; i < 16; i++) qr[t][i] = Qs[t0 + t][i];

    const int mEnd = ((tid >> 5) + 1) * 16;
    for (int m = 0; m < mEnd; m++) {
        float s[4] = {0.f, 0.f, 0.f, 0.f};
#pragma unroll
        for (int i = 0; i < 16; i++) {
            const float ki = Kc[m][i];
            s[0] = fmaf(qr[0][i], ki, s[0]);
            s[1] = fmaf(qr[1][i], ki, s[1]);
            s[2] = fmaf(qr[2][i], ki, s[2]);
            s[3] = fmaf(qr[3][i], ki, s[3]);
        }
        float a[4];
#pragma unroll
        for (int t = 0; t < 4; t++) {
            const float sd = s[t] * DOT;
            float av = fmaf(sd, 0.25f, 1.0f);
            av = fmaf(sd * sd, 0.03125f, av);
            a[t] = (m <= t0 + t) ? av : 0.f;
        }
        float v[8];
        *(float4*)&v[0] = *(const float4*)&Vc[m][f0];
        *(float4*)&v[4] = *(const float4*)&Vc[m][f0 + 4];
#pragma unroll
        for (int t = 0; t < 4; t++)
#pragma unroll
            for (int f = 0; f < 8; f++)
                acc[t][f] = fmaf(a[t], v[f], acc[t][f]);
    }

#pragma unroll
    for (int t = 0; t < 4; t++) {
        float ss = 0.f;
#pragma unroll
        for (int f = 0; f < 8; f++) ss = fmaf(acc[t][f], acc[t][f], ss);
        ss += __shfl_xor_sync(0xffffffffu, ss, 1);
        ss += __shfl_xor_sync(0xffffffffu, ss, 2);
        ss += __shfl_xor_sync(0xffffffffu, ss, 4);
        const float rms = rsqrtf(ss * (1.0f / 64.0f) + 1e-5f);
        float* yp = Y + (size_t)(tok0 + t0 + t) * VDIM + h * HDIM + f0;
        float4 o0, o1;
        o0.x = acc[t][0] * rms * gs[f0 + 0];
        o0.y = acc[t][1] * rms * gs[f0 + 1];
        o0.z = acc[t][2] * rms * gs[f0 + 2];
        o0.w = acc[t][3] * rms * gs[f0 + 3];
        o1.x = acc[t][4] * rms * gs[f0 + 4];
        o1.y = acc[t][5] * rms * gs[f0 + 5];
        o1.z = acc[t][6] * rms * gs[f0 + 6];
        o1.w = acc[t][7] * rms * gs[f0 + 7];
        *(float4*)&yp[0] = o0;
        *(float4*)&yp[4] = o1;
    }
}

// ---------------------------------------------------------------------------
extern "C" void kernel_launch(void* const* d_in, const int* in_sizes, int n_in,
                              void* d_out, int out_size) {
    const float* X  = (const float*)d_in[0];
    const float* Wq = (const float*)d_in[1];
    const float* Wk = (const float*)d_in[2];
    const float* Wv = (const float*)d_in[3];
    const float* Wo = (const float*)d_in[4];
    const float* g  = (const float*)d_in[5];
    float* out = (float*)d_out;

    float *Qb, *Kb, *Vb, *Yb, *Sb;
    cudaGetSymbolAddress((void**)&Qb, g_Q);
    cudaGetSymbolAddress((void**)&Kb, g_K);
    cudaGetSymbolAddress((void**)&Vb, g_V);
    cudaGetSymbolAddress((void**)&Yb, g_Y);
    cudaGetSymbolAddress((void**)&Sb, g_DS);

    // Projections: fused Wq+Wk (256 CTAs), then Wv (512 CTAs)
    qk_gemm<<<dim3(NTOK / 128, 4), 128>>>(X, Wq, Wk, Qb, Kb);
    tgemm_nt<<<dim3(NTOK / 128, VDIM / 128), 128>>>(X, Wv, Vb, NTOK, VDIM, DMODEL);

    // Chunked linear attention
    float* kv_out = (out_size >= OUT_ELEMS + KV_ELEMS) ? (out + OUT_ELEMS) : nullptr;
    state_kernel<<<dim3(NCHUNK, BATCH * NHEADS, 2), 256>>>(Kb, Vb, Sb);
    scan_kernel<<<dim3((SDF / 4 + 255) / 256, BATCH * NHEADS), 256>>>(Sb, kv_out);
    attn_out_kernel<<<dim3(NCHUNK, BATCH * NHEADS), 256>>>(Qb, Kb, Vb, Sb, g, Yb);

    // Output projection
    tgemm_nt<<<dim3(NTOK / 128, DMODEL / 128), 128>>>(Yb, Wo, out, NTOK, DMODEL, DMODEL);
}

// round 10
// speedup vs baseline: 1.7018x; 1.1071x over previous
#include <cuda_runtime.h>
#include <cuda_bf16.h>
#include <math.h>
#include <stdint.h>

// Problem constants (fixed shapes from setup_inputs)
#define BATCH 4
#define SEQ   2048
#define DMODEL 1024
#define NHEADS 16
#define FDIM  16
#define HDIM  64
#define NTOK  (BATCH*SEQ)          // 8192
#define QKDIM (NHEADS*FDIM)        // 256
#define VDIM  (NHEADS*HDIM)        // 1024
#define FEAT  273                  // 1 + 16 + 256
#define NCHUNK 16                  // 2048 / 128
#define CHUNK 128
#define KV_ELEMS (BATCH*NHEADS*HDIM*FEAT)   // 1,118,208
#define OUT_ELEMS (NTOK*DMODEL)             // 8,388,608
#define SDF (FEAT*HDIM)            // 17472

// Scratch (device globals; no runtime allocation)
__device__ float g_Q[NTOK*QKDIM];
__device__ float g_K[NTOK*QKDIM];
__device__ float g_V[NTOK*VDIM];
__device__ float g_Y[NTOK*VDIM];
__device__ float g_DS[64*NCHUNK*SDF];

__device__ __forceinline__ uint32_t f2tf32(float x) {
    uint32_t u;
    asm("cvt.rna.tf32.f32 %0, %1;" : "=r"(u) : "f"(x));
    return u;
}

// ---------------------------------------------------------------------------
// tf32 GEMM (R4 design, proven): 128x128 block, 4 warps of 64x64, BK=16,
// double-buffered smem [k][row] pad 132, one sync per K-tile.
// ---------------------------------------------------------------------------
struct GSmem {
    uint32_t As[2][16][132];
    uint32_t Bs[2][16][132];
};

__device__ __forceinline__ void gemm_tile(
    const float* __restrict__ A, const float* __restrict__ B,
    float* __restrict__ C, int N, int K, int bm, int bn, GSmem& sm) {
    const int tid  = threadIdx.x;
    const int warp = tid >> 5, lane = tid & 31;
    const int gid  = lane >> 2, tig = lane & 3;
    const int wm = (warp >> 1) * 64, wn = (warp & 1) * 64;

    const int lr = tid >> 2;
    const int kc = (tid & 3) << 2;
    const float* Ap = A + (size_t)(bm + lr) * K + kc;
    const float* Bp = B + (size_t)(bn + lr) * K + kc;
    const size_t row32 = (size_t)32 * K;

    float acc[4][8][4];
#pragma unroll
    for (int mt = 0; mt < 4; mt++)
#pragma unroll
        for (int nt = 0; nt < 8; nt++)
#pragma unroll
            for (int e = 0; e < 4; e++) acc[mt][nt][e] = 0.f;

    float4 ar[4], br[4];
#pragma unroll
    for (int p = 0; p < 4; p++) {
        ar[p] = *(const float4*)(Ap + p * row32);
        br[p] = *(const float4*)(Bp + p * row32);
    }
#pragma unroll
    for (int p = 0; p < 4; p++) {
        sm.As[0][kc + 0][lr + p * 32] = f2tf32(ar[p].x);
        sm.As[0][kc + 1][lr + p * 32] = f2tf32(ar[p].y);
        sm.As[0][kc + 2][lr + p * 32] = f2tf32(ar[p].z);
        sm.As[0][kc + 3][lr + p * 32] = f2tf32(ar[p].w);
        sm.Bs[0][kc + 0][lr + p * 32] = f2tf32(br[p].x);
        sm.Bs[0][kc + 1][lr + p * 32] = f2tf32(br[p].y);
        sm.Bs[0][kc + 2][lr + p * 32] = f2tf32(br[p].z);
        sm.Bs[0][kc + 3][lr + p * 32] = f2tf32(br[p].w);
    }
    __syncthreads();

    int cur = 0;
    for (int k0 = 0; k0 < K; k0 += 16) {
        const bool more = (k0 + 16 < K);
        if (more) {
#pragma unroll
            for (int p = 0; p < 4; p++) {
                ar[p] = *(const float4*)(Ap + k0 + 16 + p * row32);
                br[p] = *(const float4*)(Bp + k0 + 16 + p * row32);
            }
        }

#pragma unroll
        for (int ks = 0; ks < 2; ks++) {
            const int kk = ks * 8;
            uint32_t af[4][4], bf[8][2];
#pragma unroll
            for (int mt = 0; mt < 4; mt++) {
                const int m = wm + mt * 16 + gid;
                af[mt][0] = sm.As[cur][kk + tig][m];
                af[mt][1] = sm.As[cur][kk + tig][m + 8];
                af[mt][2] = sm.As[cur][kk + tig + 4][m];
                af[mt][3] = sm.As[cur][kk + tig + 4][m + 8];
            }
#pragma unroll
            for (int nt = 0; nt < 8; nt++) {
                const int n = wn + nt * 8 + gid;
                bf[nt][0] = sm.Bs[cur][kk + tig][n];
                bf[nt][1] = sm.Bs[cur][kk + tig + 4][n];
            }
#pragma unroll
            for (int mt = 0; mt < 4; mt++)
#pragma unroll
                for (int nt = 0; nt < 8; nt++) {
                    asm volatile(
                        "mma.sync.aligned.m16n8k8.row.col.f32.tf32.tf32.f32 "
                        "{%0,%1,%2,%3}, {%4,%5,%6,%7}, {%8,%9}, {%0,%1,%2,%3};"
                        : "+f"(acc[mt][nt][0]), "+f"(acc[mt][nt][1]),
                          "+f"(acc[mt][nt][2]), "+f"(acc[mt][nt][3])
                        : "r"(af[mt][0]), "r"(af[mt][1]),
                          "r"(af[mt][2]), "r"(af[mt][3]),
                          "r"(bf[nt][0]), "r"(bf[nt][1]));
                }
        }

        if (more) {
            const int nxt = cur ^ 1;
#pragma unroll
            for (int p = 0; p < 4; p++) {
                sm.As[nxt][kc + 0][lr + p * 32] = f2tf32(ar[p].x);
                sm.As[nxt][kc + 1][lr + p * 32] = f2tf32(ar[p].y);
                sm.As[nxt][kc + 2][lr + p * 32] = f2tf32(ar[p].z);
                sm.As[nxt][kc + 3][lr + p * 32] = f2tf32(ar[p].w);
                sm.Bs[nxt][kc + 0][lr + p * 32] = f2tf32(br[p].x);
                sm.Bs[nxt][kc + 1][lr + p * 32] = f2tf32(br[p].y);
                sm.Bs[nxt][kc + 2][lr + p * 32] = f2tf32(br[p].z);
                sm.Bs[nxt][kc + 3][lr + p * 32] = f2tf32(br[p].w);
            }
            __syncthreads();
        }
        cur ^= 1;
    }

#pragma unroll
    for (int mt = 0; mt < 4; mt++) {
        const int r0 = bm + wm + mt * 16 + gid;
#pragma unroll
        for (int nt = 0; nt < 8; nt++) {
            const int cc = bn + wn + nt * 8 + tig * 2;
            *(float2*)&C[(size_t)r0 * N + cc] =
                make_float2(acc[mt][nt][0], acc[mt][nt][1]);
            *(float2*)&C[(size_t)(r0 + 8) * N + cc] =
                make_float2(acc[mt][nt][2], acc[mt][nt][3]);
        }
    }
}

__global__ __launch_bounds__(128)
void tgemm_nt(const float* __restrict__ A, const float* __restrict__ B,
              float* __restrict__ C, int M, int N, int K) {
    __shared__ GSmem sm;
    gemm_tile(A, B, C, N, K, blockIdx.x * 128, blockIdx.y * 128, sm);
}

// ---------------------------------------------------------------------------
// Kernel A: per-chunk state increment (unpacked), f split over blockIdx.z
// ---------------------------------------------------------------------------
__global__ __launch_bounds__(256, 3)
void state_kernel(const float* __restrict__ Km, const float* __restrict__ V,
                  float* __restrict__ DS) {
    __shared__ float ks[32][16];
    __shared__ float vs[32][32];
    const int ck = blockIdx.x;
    const int bh = blockIdx.y;
    const int fh = blockIdx.z;
    const int b = bh >> 4, h = bh & 15;
    const int tid = threadIdx.x;
    const int i = tid >> 4;
    const int fq = tid & 15;
    const int tokb = b * SEQ + ck * CHUNK;
    const int fbase = fh * 32;

    float m2[16][2];
#pragma unroll
    for (int j = 0; j < 16; j++) { m2[j][0] = 0.f; m2[j][1] = 0.f; }
    float m1[2] = {0.f, 0.f};
    float s0[2] = {0.f, 0.f};

    for (int nb = 0; nb < CHUNK; nb += 32) {
        __syncthreads();
        for (int t = tid; t < 128; t += 256) {
            int r = t >> 2, c4 = (t & 3) << 2;
            *(float4*)&ks[r][c4] =
                *(const float4*)&Km[(size_t)(tokb + nb + r) * QKDIM + h * FDIM + c4];
        }
        {
            int r = tid >> 3, c4 = (tid & 7) << 2;
            *(float4*)&vs[r][c4] =
                *(const float4*)&V[(size_t)(tokb + nb + r) * VDIM + h * HDIM + fbase + c4];
        }
        __syncthreads();
#pragma unroll 4
        for (int r = 0; r < 32; r++) {
            const float ki = ks[r][i];
            const float2 v2 = *(const float2*)&vs[r][fq * 2];
            m1[0] = fmaf(ki, v2.x, m1[0]);
            m1[1] = fmaf(ki, v2.y, m1[1]);
            if (i == 0) { s0[0] += v2.x; s0[1] += v2.y; }
#pragma unroll
            for (int j = 0; j < 16; j++) {
                const float kk = ki * ks[r][j];
                m2[j][0] = fmaf(kk, v2.x, m2[j][0]);
                m2[j][1] = fmaf(kk, v2.y, m2[j][1]);
            }
        }
    }

    float* base = DS + (size_t)(bh * NCHUNK + ck) * SDF;
    const float c2 = 0.17677669529663687f;   // 1/(4*sqrt(2))
#pragma unroll
    for (int ff = 0; ff < 2; ff++) {
        const int f = fbase + fq * 2 + ff;
#pragma unroll
        for (int j = 0; j < 16; j++)
            base[(17 + i * 16 + j) * HDIM + f] = m2[j][ff] * c2;
        base[(1 + i) * HDIM + f] = m1[ff] * 0.5f;
        if (i == 0) base[f] = s0[ff];
    }
}

// ---------------------------------------------------------------------------
// Kernel B: exclusive scan (float4-vectorized); inclusive total -> kv_state
// ---------------------------------------------------------------------------
__global__ void scan_kernel(float* __restrict__ DS, float* __restrict__ kv_out) {
    const int bh = blockIdx.y;
    const int e4 = (blockIdx.x * 256 + threadIdx.x) * 4;
    if (e4 >= SDF) return;
    size_t base = (size_t)bh * NCHUNK * SDF + e4;
    float4 run = make_float4(0.f, 0.f, 0.f, 0.f);
#pragma unroll
    for (int c = 0; c < NCHUNK; c++) {
        float4 v = *(float4*)&DS[base + (size_t)c * SDF];
        *(float4*)&DS[base + (size_t)c * SDF] = run;
        run.x += v.x; run.y += v.y; run.z += v.z; run.w += v.w;
    }
    if (kv_out) {
        const int d = e4 >> 6, f0 = e4 & 63;
        float* kb = kv_out + (size_t)bh * (HDIM * FEAT) + d;
        kb[(size_t)(f0 + 0) * FEAT] = run.x;
        kb[(size_t)(f0 + 1) * FEAT] = run.y;
        kb[(size_t)(f0 + 2) * FEAT] = run.z;
        kb[(size_t)(f0 + 3) * FEAT] = run.w;
    }
}

// ---------------------------------------------------------------------------
// Kernel C: inter-chunk via tf32x3 mma.sync (fp32-grade accuracy), intra-chunk
// causal fp32, fused RMSNorm + g.  273-dim Taylor features generated in regs.
// ---------------------------------------------------------------------------
#define AK_QS(r,c)     dyn[(r)*17+(c)]                 // q*SC, col16 = 1.0
#define AK_KC(r,c)     dyn[2176+(r)*16+(c)]            // raw k
#define AK_VC(r,c)     dyn[4224+(r)*64+(c)]            // v
#define AK_SH(b,r,c)   dyn[12416+(b)*576+(r)*72+(c)]   // S tile hi (tf32)
#define AK_SL(b,r,c)   dyn[13568+(b)*576+(r)*72+(c)]   // S tile lo (tf32)
#define AK_GS(c)       dyn[14720+(c)]
#define ATTN_SMEM      (14784*4)                       // 59,136 bytes

__device__ __forceinline__ float qfeat(const float* dyn, int r, int d) {
    // qf feature d for token row r (Qs scaled by SC, col 16 == 1.0)
    int i, j; float w;
    if (d == 0)        { i = 16; j = 16; w = 1.f; }
    else if (d < 17)   { i = d - 1; j = 16; w = 1.1892071150027210f; } // LIN
    else if (d < 273)  { int p = d - 17; i = p >> 4; j = p & 15; w = 1.f; }
    else               { i = 16; j = 16; w = 0.f; }
    return AK_QS(r, i) * AK_QS(r, j) * w;
}

__global__ __launch_bounds__(256, 2)
void attn_out_kernel(const float* __restrict__ Q, const float* __restrict__ Km,
                     const float* __restrict__ V, const float* __restrict__ Sprev,
                     const float* __restrict__ g, float* __restrict__ Y) {
    extern __shared__ float dyn[];
    const int ck = blockIdx.x;
    const int bh = blockIdx.y;
    const int b = bh >> 4, h = bh & 15;
    const int tid = threadIdx.x;
    const int warp = tid >> 5, lane = tid & 31;
    const int gid = lane >> 2, tig = lane & 3;
    const int tok0 = b * SEQ + ck * CHUNK;
    const float SC  = 0.4204482076268573f;    // sqrt(1/(4*sqrt2))
    const float DOT = 2.3784142300054421f;    // 1/SC
    const float* Sp = Sprev + (size_t)(bh * NCHUNK + ck) * SDF;

    // ---- stage Q (scaled, padded), K, V, g, S step-0 tile ----
    for (int t = tid; t < 512; t += 256) {
        int r = t >> 2, c4 = (t & 3) << 2;
        float4 qv = *(const float4*)&Q[(size_t)(tok0 + r) * QKDIM + h * FDIM + c4];
        AK_QS(r, c4 + 0) = qv.x * SC; AK_QS(r, c4 + 1) = qv.y * SC;
        AK_QS(r, c4 + 2) = qv.z * SC; AK_QS(r, c4 + 3) = qv.w * SC;
        float4 kv = *(const float4*)&Km[(size_t)(tok0 + r) * QKDIM + h * FDIM + c4];
        AK_KC(r, c4 + 0) = kv.x; AK_KC(r, c4 + 1) = kv.y;
        AK_KC(r, c4 + 2) = kv.z; AK_KC(r, c4 + 3) = kv.w;
    }
    if (tid < 128) AK_QS(tid, 16) = 1.0f;
    for (int t = tid; t < 2048; t += 256) {
        int r = t >> 4, c4 = (t & 15) << 2;
        *(float4*)&AK_VC(r, c4) =
            *(const float4*)&V[(size_t)(tok0 + r) * VDIM + h * HDIM + c4];
    }
    if (tid < 64) AK_GS(tid) = g[tid];
    {   // S tile for step 0 (rows 0..7)
        int row = tid >> 5, col = (lane) * 2;
        float2 v = *(const float2*)&Sp[row * HDIM + col];
        uint32_t hx = f2tf32(v.x), hy = f2tf32(v.y);
        AK_SH(0, row, col) = __uint_as_float(hx);
        AK_SH(0, row, col + 1) = __uint_as_float(hy);
        AK_SL(0, row, col) = __uint_as_float(f2tf32(v.x - __uint_as_float(hx)));
        AK_SL(0, row, col + 1) = __uint_as_float(f2tf32(v.y - __uint_as_float(hy)));
    }
    __syncthreads();

    float acc[8][4];
#pragma unroll
    for (int nt = 0; nt < 8; nt++)
#pragma unroll
        for (int e = 0; e < 4; e++) acc[nt][e] = 0.f;

    // ---- inter-chunk: y += qf @ S_prev via tf32x3 MMA, 35 k-steps of 8 ----
    const int r0 = warp * 16 + gid;
    int buf = 0;
    for (int s = 0; s < 35; s++) {
        // prefetch next S tile rows to registers
        float2 nx = make_float2(0.f, 0.f);
        const int prow = tid >> 5, pcol = lane * 2;
        if (s < 34) {
            int nrow = (s + 1) * 8 + prow;
            if (nrow < FEAT) nx = *(const float2*)&Sp[nrow * HDIM + pcol];
        }
        // generate A fragment (hi/lo)
        const int d0 = s * 8 + tig;
        float a0 = qfeat(dyn, r0, d0);
        float a1 = qfeat(dyn, r0 + 8, d0);
        float a2 = qfeat(dyn, r0, d0 + 4);
        float a3 = qfeat(dyn, r0 + 8, d0 + 4);
        uint32_t ah[4], al[4];
        ah[0] = f2tf32(a0); al[0] = f2tf32(a0 - __uint_as_float(ah[0]));
        ah[1] = f2tf32(a1); al[1] = f2tf32(a1 - __uint_as_float(ah[1]));
        ah[2] = f2tf32(a2); al[2] = f2tf32(a2 - __uint_as_float(ah[2]));
        ah[3] = f2tf32(a3); al[3] = f2tf32(a3 - __uint_as_float(ah[3]));
#pragma unroll
        for (int nt = 0; nt < 8; nt++) {
            const int n = nt * 8 + gid;
            uint32_t bh0 = __float_as_uint(AK_SH(buf, tig, n));
            uint32_t bh1 = __float_as_uint(AK_SH(buf, tig + 4, n));
            uint32_t bl0 = __float_as_uint(AK_SL(buf, tig, n));
            uint32_t bl1 = __float_as_uint(AK_SL(buf, tig + 4, n));
            asm volatile(
                "mma.sync.aligned.m16n8k8.row.col.f32.tf32.tf32.f32 "
                "{%0,%1,%2,%3}, {%4,%5,%6,%7}, {%8,%9}, {%0,%1,%2,%3};"
                : "+f"(acc[nt][0]), "+f"(acc[nt][1]),
                  "+f"(acc[nt][2]), "+f"(acc[nt][3])
                : "r"(ah[0]), "r"(ah[1]), "r"(ah[2]), "r"(ah[3]),
                  "r"(bh0), "r"(bh1));
            asm volatile(
                "mma.sync.aligned.m16n8k8.row.col.f32.tf32.tf32.f32 "
                "{%0,%1,%2,%3}, {%4,%5,%6,%7}, {%8,%9}, {%0,%1,%2,%3};"
                : "+f"(acc[nt][0]), "+f"(acc[nt][1]),
                  "+f"(acc[nt][2]), "+f"(acc[nt][3])
                : "r"(ah[0]), "r"(ah[1]), "r"(ah[2]), "r"(ah[3]),
                  "r"(bl0), "r"(bl1));
            asm volatile(
                "mma.sync.aligned.m16n8k8.row.col.f32.tf32.tf32.f32 "
                "{%0,%1,%2,%3}, {%4,%5,%6,%7}, {%8,%9}, {%0,%1,%2,%3};"
                : "+f"(acc[nt][0]), "+f"(acc[nt][1]),
                  "+f"(acc[nt][2]), "+f"(acc[nt][3])
                : "r"(al[0]), "r"(al[1]), "r"(al[2]), "r"(al[3]),
                  "r"(bh0), "r"(bh1));
        }
        // store prefetched tile (hi/lo split) into the other buffer
        if (s < 34) {
            const int nb = buf ^ 1;
            uint32_t hx = f2tf32(nx.x), hy = f2tf32(nx.y);
            AK_SH(nb, prow, pcol) = __uint_as_float(hx);
            AK_SH(nb, prow, pcol + 1) = __uint_as_float(hy);
            AK_SL(nb, prow, pcol) =
                __uint_as_float(f2tf32(nx.x - __uint_as_float(hx)));
            AK_SL(nb, prow, pcol + 1) =
                __uint_as_float(f2tf32(nx.y - __uint_as_float(hy)));
            __syncthreads();
            buf = nb;
        }
    }

    // ---- intra-chunk causal: A = 1 + s/4 + s^2/32, fp32 ----
    float qr0[16], qr1[16];
#pragma unroll
    for (int i = 0; i < 16; i++) {
        qr0[i] = AK_QS(r0, i);
        qr1[i] = AK_QS(r0 + 8, i);
    }
    const int r1 = r0 + 8;
    const int mEnd = 16 * (warp + 1);
    for (int m = 0; m < mEnd; m++) {
        float s0 = 0.f, s1 = 0.f;
#pragma unroll
        for (int i = 0; i < 16; i++) {
            const float ki = AK_KC(m, i);
            s0 = fmaf(qr0[i], ki, s0);
            s1 = fmaf(qr1[i], ki, s1);
        }
        const float sd0 = s0 * DOT, sd1 = s1 * DOT;
        float a0 = fmaf(sd0, 0.25f, 1.0f);
        a0 = fmaf(sd0 * sd0, 0.03125f, a0);
        float a1 = fmaf(sd1, 0.25f, 1.0f);
        a1 = fmaf(sd1 * sd1, 0.03125f, a1);
        a0 = (m <= r0) ? a0 : 0.f;
        a1 = (m <= r1) ? a1 : 0.f;
#pragma unroll
        for (int nt = 0; nt < 8; nt++) {
            const float2 v = *(const float2*)&AK_VC(m, nt * 8 + tig * 2);
            acc[nt][0] = fmaf(a0, v.x, acc[nt][0]);
            acc[nt][1] = fmaf(a0, v.y, acc[nt][1]);
            acc[nt][2] = fmaf(a1, v.x, acc[nt][2]);
            acc[nt][3] = fmaf(a1, v.y, acc[nt][3]);
        }
    }

    // ---- RMSNorm (reduce across tig lanes) + gate + store ----
    float ss0 = 0.f, ss1 = 0.f;
#pragma unroll
    for (int nt = 0; nt < 8; nt++) {
        ss0 = fmaf(acc[nt][0], acc[nt][0], ss0);
        ss0 = fmaf(acc[nt][1], acc[nt][1], ss0);
        ss1 = fmaf(acc[nt][2], acc[nt][2], ss1);
        ss1 = fmaf(acc[nt][3], acc[nt][3], ss1);
    }
    ss0 += __shfl_xor_sync(0xffffffffu, ss0, 1);
    ss0 += __shfl_xor_sync(0xffffffffu, ss0, 2);
    ss1 += __shfl_xor_sync(0xffffffffu, ss1, 1);
    ss1 += __shfl_xor_sync(0xffffffffu, ss1, 2);
    const float rms0 = rsqrtf(ss0 * (1.0f / 64.0f) + 1e-5f);
    const float rms1 = rsqrtf(ss1 * (1.0f / 64.0f) + 1e-5f);
    float* y0 = Y + (size_t)(tok0 + r0) * VDIM + h * HDIM;
    float* y1 = Y + (size_t)(tok0 + r1) * VDIM + h * HDIM;
#pragma unroll
    for (int nt = 0; nt < 8; nt++) {
        const int c = nt * 8 + tig * 2;
        float2 o0, o1;
        o0.x = acc[nt][0] * rms0 * AK_GS(c);
        o0.y = acc[nt][1] * rms0 * AK_GS(c + 1);
        o1.x = acc[nt][2] * rms1 * AK_GS(c);
        o1.y = acc[nt][3] * rms1 * AK_GS(c + 1);
        *(float2*)&y0[c] = o0;
        *(float2*)&y1[c] = o1;
    }
}

// ---------------------------------------------------------------------------
extern "C" void kernel_launch(void* const* d_in, const int* in_sizes, int n_in,
                              void* d_out, int out_size) {
    const float* X  = (const float*)d_in[0];
    const float* Wq = (const float*)d_in[1];
    const float* Wk = (const float*)d_in[2];
    const float* Wv = (const float*)d_in[3];
    const float* Wo = (const float*)d_in[4];
    const float* g  = (const float*)d_in[5];
    float* out = (float*)d_out;

    float *Qb, *Kb, *Vb, *Yb, *Sb;
    cudaGetSymbolAddress((void**)&Qb, g_Q);
    cudaGetSymbolAddress((void**)&Kb, g_K);
    cudaGetSymbolAddress((void**)&Vb, g_V);
    cudaGetSymbolAddress((void**)&Yb, g_Y);
    cudaGetSymbolAddress((void**)&Sb, g_DS);

    static int attn_smem_set = 0;
    if (!attn_smem_set) {
        cudaFuncSetAttribute(attn_out_kernel,
                             cudaFuncAttributeMaxDynamicSharedMemorySize,
                             ATTN_SMEM);
        attn_smem_set = 1;
    }

    // Projections (separate launches — proven fastest config)
    tgemm_nt<<<dim3(NTOK / 128, QKDIM / 128), 128>>>(X, Wq, Qb, NTOK, QKDIM, DMODEL);
    tgemm_nt<<<dim3(NTOK / 128, QKDIM / 128), 128>>>(X, Wk, Kb, NTOK, QKDIM, DMODEL);
    tgemm_nt<<<dim3(NTOK / 128, VDIM / 128),  128>>>(X, Wv, Vb, NTOK, VDIM,  DMODEL);

    // Chunked linear attention
    float* kv_out = (out_size >= OUT_ELEMS + KV_ELEMS) ? (out + OUT_ELEMS) : nullptr;
    state_kernel<<<dim3(NCHUNK, BATCH * NHEADS, 2), 256>>>(Kb, Vb, Sb);
    scan_kernel<<<dim3((SDF / 4 + 255) / 256, BATCH * NHEADS), 256>>>(Sb, kv_out);
    attn_out_kernel<<<dim3(NCHUNK, BATCH * NHEADS), 256, ATTN_SMEM>>>(
        Qb, Kb, Vb, Sb, g, Yb);

    // Output projection
    tgemm_nt<<<dim3(NTOK / 128, DMODEL / 128), 128>>>(Yb, Wo, out, NTOK, DMODEL, DMODEL);
}

// round 11
// speedup vs baseline: 1.7614x; 1.0350x over previous
#include <cuda_runtime.h>
#include <cuda_bf16.h>
#include <math.h>
#include <stdint.h>

// Problem constants (fixed shapes from setup_inputs)
#define BATCH 4
#define SEQ   2048
#define DMODEL 1024
#define NHEADS 16
#define FDIM  16
#define HDIM  64
#define NTOK  (BATCH*SEQ)          // 8192
#define QKDIM (NHEADS*FDIM)        // 256
#define VDIM  (NHEADS*HDIM)        // 1024
#define FEAT  273                  // 1 + 16 + 256
#define NCHUNK 16                  // 2048 / 128
#define CHUNK 128
#define KV_ELEMS (BATCH*NHEADS*HDIM*FEAT)   // 1,118,208
#define OUT_ELEMS (NTOK*DMODEL)             // 8,388,608
#define SDF (FEAT*HDIM)            // 17472

// Scratch (device globals; no runtime allocation)
__device__ float g_Q[NTOK*QKDIM];
__device__ float g_K[NTOK*QKDIM];
__device__ float g_V[NTOK*VDIM];
__device__ float g_Y[NTOK*VDIM];
__device__ float g_DS[64*NCHUNK*SDF];

__device__ __forceinline__ uint32_t f2tf32(float x) {
    uint32_t u;
    asm("cvt.rna.tf32.f32 %0, %1;" : "=r"(u) : "f"(x));
    return u;
}
// bf16 round-to-nearest-even (returns low 16 bits)
__device__ __forceinline__ uint32_t f2bf(float x) {
    uint32_t u = __float_as_uint(x);
    return (u + 0x7fffu + ((u >> 16) & 1u)) >> 16;
}
__device__ __forceinline__ float bfval(uint32_t b) {
    return __uint_as_float(b << 16);
}

// ---------------------------------------------------------------------------
// tf32 GEMM (R4 design, proven): 128x128 block, 4 warps of 64x64, BK=16,
// double-buffered smem [k][row] pad 132, one sync per K-tile.
// ---------------------------------------------------------------------------
struct GSmem {
    uint32_t As[2][16][132];
    uint32_t Bs[2][16][132];
};

__device__ __forceinline__ void gemm_tile(
    const float* __restrict__ A, const float* __restrict__ B,
    float* __restrict__ C, int N, int K, int bm, int bn, GSmem& sm) {
    const int tid  = threadIdx.x;
    const int warp = tid >> 5, lane = tid & 31;
    const int gid  = lane >> 2, tig = lane & 3;
    const int wm = (warp >> 1) * 64, wn = (warp & 1) * 64;

    const int lr = tid >> 2;
    const int kc = (tid & 3) << 2;
    const float* Ap = A + (size_t)(bm + lr) * K + kc;
    const float* Bp = B + (size_t)(bn + lr) * K + kc;
    const size_t row32 = (size_t)32 * K;

    float acc[4][8][4];
#pragma unroll
    for (int mt = 0; mt < 4; mt++)
#pragma unroll
        for (int nt = 0; nt < 8; nt++)
#pragma unroll
            for (int e = 0; e < 4; e++) acc[mt][nt][e] = 0.f;

    float4 ar[4], br[4];
#pragma unroll
    for (int p = 0; p < 4; p++) {
        ar[p] = *(const float4*)(Ap + p * row32);
        br[p] = *(const float4*)(Bp + p * row32);
    }
#pragma unroll
    for (int p = 0; p < 4; p++) {
        sm.As[0][kc + 0][lr + p * 32] = f2tf32(ar[p].x);
        sm.As[0][kc + 1][lr + p * 32] = f2tf32(ar[p].y);
        sm.As[0][kc + 2][lr + p * 32] = f2tf32(ar[p].z);
        sm.As[0][kc + 3][lr + p * 32] = f2tf32(ar[p].w);
        sm.Bs[0][kc + 0][lr + p * 32] = f2tf32(br[p].x);
        sm.Bs[0][kc + 1][lr + p * 32] = f2tf32(br[p].y);
        sm.Bs[0][kc + 2][lr + p * 32] = f2tf32(br[p].z);
        sm.Bs[0][kc + 3][lr + p * 32] = f2tf32(br[p].w);
    }
    __syncthreads();

    int cur = 0;
    for (int k0 = 0; k0 < K; k0 += 16) {
        const bool more = (k0 + 16 < K);
        if (more) {
#pragma unroll
            for (int p = 0; p < 4; p++) {
                ar[p] = *(const float4*)(Ap + k0 + 16 + p * row32);
                br[p] = *(const float4*)(Bp + k0 + 16 + p * row32);
            }
        }

#pragma unroll
        for (int ks = 0; ks < 2; ks++) {
            const int kk = ks * 8;
            uint32_t af[4][4], bf[8][2];
#pragma unroll
            for (int mt = 0; mt < 4; mt++) {
                const int m = wm + mt * 16 + gid;
                af[mt][0] = sm.As[cur][kk + tig][m];
                af[mt][1] = sm.As[cur][kk + tig][m + 8];
                af[mt][2] = sm.As[cur][kk + tig + 4][m];
                af[mt][3] = sm.As[cur][kk + tig + 4][m + 8];
            }
#pragma unroll
            for (int nt = 0; nt < 8; nt++) {
                const int n = wn + nt * 8 + gid;
                bf[nt][0] = sm.Bs[cur][kk + tig][n];
                bf[nt][1] = sm.Bs[cur][kk + tig + 4][n];
            }
#pragma unroll
            for (int mt = 0; mt < 4; mt++)
#pragma unroll
                for (int nt = 0; nt < 8; nt++) {
                    asm volatile(
                        "mma.sync.aligned.m16n8k8.row.col.f32.tf32.tf32.f32 "
                        "{%0,%1,%2,%3}, {%4,%5,%6,%7}, {%8,%9}, {%0,%1,%2,%3};"
                        : "+f"(acc[mt][nt][0]), "+f"(acc[mt][nt][1]),
                          "+f"(acc[mt][nt][2]), "+f"(acc[mt][nt][3])
                        : "r"(af[mt][0]), "r"(af[mt][1]),
                          "r"(af[mt][2]), "r"(af[mt][3]),
                          "r"(bf[nt][0]), "r"(bf[nt][1]));
                }
        }

        if (more) {
            const int nxt = cur ^ 1;
#pragma unroll
            for (int p = 0; p < 4; p++) {
                sm.As[nxt][kc + 0][lr + p * 32] = f2tf32(ar[p].x);
                sm.As[nxt][kc + 1][lr + p * 32] = f2tf32(ar[p].y);
                sm.As[nxt][kc + 2][lr + p * 32] = f2tf32(ar[p].z);
                sm.As[nxt][kc + 3][lr + p * 32] = f2tf32(ar[p].w);
                sm.Bs[nxt][kc + 0][lr + p * 32] = f2tf32(br[p].x);
                sm.Bs[nxt][kc + 1][lr + p * 32] = f2tf32(br[p].y);
                sm.Bs[nxt][kc + 2][lr + p * 32] = f2tf32(br[p].z);
                sm.Bs[nxt][kc + 3][lr + p * 32] = f2tf32(br[p].w);
            }
            __syncthreads();
        }
        cur ^= 1;
    }

#pragma unroll
    for (int mt = 0; mt < 4; mt++) {
        const int r0 = bm + wm + mt * 16 + gid;
#pragma unroll
        for (int nt = 0; nt < 8; nt++) {
            const int cc = bn + wn + nt * 8 + tig * 2;
            *(float2*)&C[(size_t)r0 * N + cc] =
                make_float2(acc[mt][nt][0], acc[mt][nt][1]);
            *(float2*)&C[(size_t)(r0 + 8) * N + cc] =
                make_float2(acc[mt][nt][2], acc[mt][nt][3]);
        }
    }
}

__global__ __launch_bounds__(128)
void tgemm_nt(const float* __restrict__ A, const float* __restrict__ B,
              float* __restrict__ C, int M, int N, int K) {
    __shared__ GSmem sm;
    gemm_tile(A, B, C, N, K, blockIdx.x * 128, blockIdx.y * 128, sm);
}

// ---------------------------------------------------------------------------
// Kernel A: per-chunk state increment (unpacked), f split over blockIdx.z
// ---------------------------------------------------------------------------
__global__ __launch_bounds__(256, 3)
void state_kernel(const float* __restrict__ Km, const float* __restrict__ V,
                  float* __restrict__ DS) {
    __shared__ float ks[32][16];
    __shared__ float vs[32][32];
    const int ck = blockIdx.x;
    const int bh = blockIdx.y;
    const int fh = blockIdx.z;
    const int b = bh >> 4, h = bh & 15;
    const int tid = threadIdx.x;
    const int i = tid >> 4;
    const int fq = tid & 15;
    const int tokb = b * SEQ + ck * CHUNK;
    const int fbase = fh * 32;

    float m2[16][2];
#pragma unroll
    for (int j = 0; j < 16; j++) { m2[j][0] = 0.f; m2[j][1] = 0.f; }
    float m1[2] = {0.f, 0.f};
    float s0[2] = {0.f, 0.f};

    for (int nb = 0; nb < CHUNK; nb += 32) {
        __syncthreads();
        for (int t = tid; t < 128; t += 256) {
            int r = t >> 2, c4 = (t & 3) << 2;
            *(float4*)&ks[r][c4] =
                *(const float4*)&Km[(size_t)(tokb + nb + r) * QKDIM + h * FDIM + c4];
        }
        {
            int r = tid >> 3, c4 = (tid & 7) << 2;
            *(float4*)&vs[r][c4] =
                *(const float4*)&V[(size_t)(tokb + nb + r) * VDIM + h * HDIM + fbase + c4];
        }
        __syncthreads();
#pragma unroll 4
        for (int r = 0; r < 32; r++) {
            const float ki = ks[r][i];
            const float2 v2 = *(const float2*)&vs[r][fq * 2];
            m1[0] = fmaf(ki, v2.x, m1[0]);
            m1[1] = fmaf(ki, v2.y, m1[1]);
            if (i == 0) { s0[0] += v2.x; s0[1] += v2.y; }
#pragma unroll
            for (int j = 0; j < 16; j++) {
                const float kk = ki * ks[r][j];
                m2[j][0] = fmaf(kk, v2.x, m2[j][0]);
                m2[j][1] = fmaf(kk, v2.y, m2[j][1]);
            }
        }
    }

    float* base = DS + (size_t)(bh * NCHUNK + ck) * SDF;
    const float c2 = 0.17677669529663687f;   // 1/(4*sqrt(2))
#pragma unroll
    for (int ff = 0; ff < 2; ff++) {
        const int f = fbase + fq * 2 + ff;
#pragma unroll
        for (int j = 0; j < 16; j++)
            base[(17 + i * 16 + j) * HDIM + f] = m2[j][ff] * c2;
        base[(1 + i) * HDIM + f] = m1[ff] * 0.5f;
        if (i == 0) base[f] = s0[ff];
    }
}

// ---------------------------------------------------------------------------
// Kernel B: exclusive scan (float4-vectorized); inclusive total -> kv_state
// ---------------------------------------------------------------------------
__global__ void scan_kernel(float* __restrict__ DS, float* __restrict__ kv_out) {
    const int bh = blockIdx.y;
    const int e4 = (blockIdx.x * 256 + threadIdx.x) * 4;
    if (e4 >= SDF) return;
    size_t base = (size_t)bh * NCHUNK * SDF + e4;
    float4 run = make_float4(0.f, 0.f, 0.f, 0.f);
#pragma unroll
    for (int c = 0; c < NCHUNK; c++) {
        float4 v = *(float4*)&DS[base + (size_t)c * SDF];
        *(float4*)&DS[base + (size_t)c * SDF] = run;
        run.x += v.x; run.y += v.y; run.z += v.z; run.w += v.w;
    }
    if (kv_out) {
        const int d = e4 >> 6, f0 = e4 & 63;
        float* kb = kv_out + (size_t)bh * (HDIM * FEAT) + d;
        kb[(size_t)(f0 + 0) * FEAT] = run.x;
        kb[(size_t)(f0 + 1) * FEAT] = run.y;
        kb[(size_t)(f0 + 2) * FEAT] = run.z;
        kb[(size_t)(f0 + 3) * FEAT] = run.w;
    }
}

// ---------------------------------------------------------------------------
// Kernel C: inter-chunk via bf16x3 mma.sync m16n8k16 (fp32-grade accuracy),
// intra-chunk causal fp32, fused RMSNorm + g.  Taylor features gen'd in regs.
// ---------------------------------------------------------------------------
#define AK_QS(r,c)     dyn[(r)*17+(c)]                 // q*SC, col16 = 1.0
#define AK_KC(r,c)     dyn[2176+(r)*16+(c)]            // raw k
#define AK_VC(r,c)     dyn[4224+(r)*64+(c)]            // v
#define AK_GS(c)       dyn[14720+(c)]
#define ATTN_SMEM      (14784*4)                       // 59,136 bytes
// packed bf16 S tiles (uint32 views): [buf][8 rowpairs][72]
#define AK_SHW(b,rp,n) shw[(b)*576+(rp)*72+(n)]
#define AK_SLW(b,rp,n) slw[(b)*576+(rp)*72+(n)]

__device__ __forceinline__ float qfeat(const float* dyn, int r, int d) {
    // qf feature d for token row r (Qs scaled by SC, col 16 == 1.0)
    int i, j; float w;
    if (d == 0)        { i = 16; j = 16; w = 1.f; }
    else if (d < 17)   { i = d - 1; j = 16; w = 1.1892071150027210f; } // LIN
    else if (d < 273)  { int p = d - 17; i = p >> 4; j = p & 15; w = 1.f; }
    else               { i = 16; j = 16; w = 0.f; }
    return AK_QS(r, i) * AK_QS(r, j) * w;
}

__global__ __launch_bounds__(256, 2)
void attn_out_kernel(const float* __restrict__ Q, const float* __restrict__ Km,
                     const float* __restrict__ V, const float* __restrict__ Sprev,
                     const float* __restrict__ g, float* __restrict__ Y) {
    extern __shared__ float dyn[];
    uint32_t* shw = (uint32_t*)(dyn + 12416);
    uint32_t* slw = (uint32_t*)(dyn + 13568);
    const int ck = blockIdx.x;
    const int bh = blockIdx.y;
    const int b = bh >> 4, h = bh & 15;
    const int tid = threadIdx.x;
    const int warp = tid >> 5, lane = tid & 31;
    const int gid = lane >> 2, tig = lane & 3;
    const int tok0 = b * SEQ + ck * CHUNK;
    const float SC  = 0.4204482076268573f;    // sqrt(1/(4*sqrt2))
    const float DOT = 2.3784142300054421f;    // 1/SC
    const float* Sp = Sprev + (size_t)(bh * NCHUNK + ck) * SDF;

    // ---- stage Q (scaled, padded), K, V, g ----
    for (int t = tid; t < 512; t += 256) {
        int r = t >> 2, c4 = (t & 3) << 2;
        float4 qv = *(const float4*)&Q[(size_t)(tok0 + r) * QKDIM + h * FDIM + c4];
        AK_QS(r, c4 + 0) = qv.x * SC; AK_QS(r, c4 + 1) = qv.y * SC;
        AK_QS(r, c4 + 2) = qv.z * SC; AK_QS(r, c4 + 3) = qv.w * SC;
        float4 kv = *(const float4*)&Km[(size_t)(tok0 + r) * QKDIM + h * FDIM + c4];
        AK_KC(r, c4 + 0) = kv.x; AK_KC(r, c4 + 1) = kv.y;
        AK_KC(r, c4 + 2) = kv.z; AK_KC(r, c4 + 3) = kv.w;
    }
    if (tid < 128) AK_QS(tid, 16) = 1.0f;
    for (int t = tid; t < 2048; t += 256) {
        int r = t >> 4, c4 = (t & 15) << 2;
        *(float4*)&AK_VC(r, c4) =
            *(const float4*)&V[(size_t)(tok0 + r) * VDIM + h * HDIM + c4];
    }
    if (tid < 64) AK_GS(tid) = g[tid];
    // ---- S tile for step 0 (feature rows 0..15, packed bf16 hi/lo) ----
    {
#pragma unroll
        for (int q = 0; q < 2; q++) {
            const int id = tid + q * 256;       // 0..511
            const int rp = id >> 6, n = id & 63;
            const int fr = 2 * rp;              // 0..14
            float v0 = Sp[fr * HDIM + n];
            float v1 = Sp[(fr + 1) * HDIM + n];
            uint32_t h0 = f2bf(v0), h1 = f2bf(v1);
            AK_SHW(0, rp, n) = h0 | (h1 << 16);
            uint32_t l0 = f2bf(v0 - bfval(h0)), l1 = f2bf(v1 - bfval(h1));
            AK_SLW(0, rp, n) = l0 | (l1 << 16);
        }
    }
    __syncthreads();

    float acc[8][4];
#pragma unroll
    for (int nt = 0; nt < 8; nt++)
#pragma unroll
        for (int e = 0; e < 4; e++) acc[nt][e] = 0.f;

    // ---- inter-chunk: y += qf @ S_prev via bf16x3 MMA, 18 k-steps of 16 ----
    const int r0 = warp * 16 + gid;
    const int r1 = r0 + 8;
    int buf = 0;
    for (int s = 0; s < 18; s++) {
        // prefetch next S tile (2 rowpairs x cols per thread) to registers
        float p00 = 0.f, p01 = 0.f, p10 = 0.f, p11 = 0.f;
        int rpA = 0, nA = 0, rpB = 0, nB = 0;
        if (s < 17) {
            const int fb = 16 * (s + 1);
            int idA = tid;           rpA = idA >> 6; nA = idA & 63;
            int idB = tid + 256;     rpB = idB >> 6; nB = idB & 63;
            int frA = fb + 2 * rpA, frB = fb + 2 * rpB;
            if (frA < FEAT)     p00 = Sp[frA * HDIM + nA];
            if (frA + 1 < FEAT) p01 = Sp[(frA + 1) * HDIM + nA];
            if (frB < FEAT)     p10 = Sp[frB * HDIM + nB];
            if (frB + 1 < FEAT) p11 = Sp[(frB + 1) * HDIM + nB];
        }
        // generate A fragments (bf16 hi/lo, packed pairs along k)
        const int da = 16 * s + 2 * tig;
        const int db = da + 8;
        float f00 = qfeat(dyn, r0, da),     f01 = qfeat(dyn, r0, da + 1);
        float f10 = qfeat(dyn, r1, da),     f11 = qfeat(dyn, r1, da + 1);
        float f02 = qfeat(dyn, r0, db),     f03 = qfeat(dyn, r0, db + 1);
        float f12 = qfeat(dyn, r1, db),     f13 = qfeat(dyn, r1, db + 1);
        uint32_t ah[4], al[4];
        {
            uint32_t h00 = f2bf(f00), h01 = f2bf(f01);
            uint32_t h10 = f2bf(f10), h11 = f2bf(f11);
            uint32_t h02 = f2bf(f02), h03 = f2bf(f03);
            uint32_t h12 = f2bf(f12), h13 = f2bf(f13);
            ah[0] = h00 | (h01 << 16);
            ah[1] = h10 | (h11 << 16);
            ah[2] = h02 | (h03 << 16);
            ah[3] = h12 | (h13 << 16);
            uint32_t l00 = f2bf(f00 - bfval(h00)), l01 = f2bf(f01 - bfval(h01));
            uint32_t l10 = f2bf(f10 - bfval(h10)), l11 = f2bf(f11 - bfval(h11));
            uint32_t l02 = f2bf(f02 - bfval(h02)), l03 = f2bf(f03 - bfval(h03));
            uint32_t l12 = f2bf(f12 - bfval(h12)), l13 = f2bf(f13 - bfval(h13));
            al[0] = l00 | (l01 << 16);
            al[1] = l10 | (l11 << 16);
            al[2] = l02 | (l03 << 16);
            al[3] = l12 | (l13 << 16);
        }
#pragma unroll
        for (int nt = 0; nt < 8; nt++) {
            const int n = nt * 8 + gid;
            uint32_t bh0 = AK_SHW(buf, tig, n);
            uint32_t bh1 = AK_SHW(buf, tig + 4, n);
            uint32_t bl0 = AK_SLW(buf, tig, n);
            uint32_t bl1 = AK_SLW(buf, tig + 4, n);
            asm volatile(
                "mma.sync.aligned.m16n8k16.row.col.f32.bf16.bf16.f32 "
                "{%0,%1,%2,%3}, {%4,%5,%6,%7}, {%8,%9}, {%0,%1,%2,%3};"
                : "+f"(acc[nt][0]), "+f"(acc[nt][1]),
                  "+f"(acc[nt][2]), "+f"(acc[nt][3])
                : "r"(ah[0]), "r"(ah[1]), "r"(ah[2]), "r"(ah[3]),
                  "r"(bh0), "r"(bh1));
            asm volatile(
                "mma.sync.aligned.m16n8k16.row.col.f32.bf16.bf16.f32 "
                "{%0,%1,%2,%3}, {%4,%5,%6,%7}, {%8,%9}, {%0,%1,%2,%3};"
                : "+f"(acc[nt][0]), "+f"(acc[nt][1]),
                  "+f"(acc[nt][2]), "+f"(acc[nt][3])
                : "r"(ah[0]), "r"(ah[1]), "r"(ah[2]), "r"(ah[3]),
                  "r"(bl0), "r"(bl1));
            asm volatile(
                "mma.sync.aligned.m16n8k16.row.col.f32.bf16.bf16.f32 "
                "{%0,%1,%2,%3}, {%4,%5,%6,%7}, {%8,%9}, {%0,%1,%2,%3};"
                : "+f"(acc[nt][0]), "+f"(acc[nt][1]),
                  "+f"(acc[nt][2]), "+f"(acc[nt][3])
                : "r"(al[0]), "r"(al[1]), "r"(al[2]), "r"(al[3]),
                  "r"(bh0), "r"(bh1));
        }
        // store prefetched tile (bf16 hi/lo packed) into the other buffer
        if (s < 17) {
            const int nb = buf ^ 1;
            uint32_t h0 = f2bf(p00), h1 = f2bf(p01);
            AK_SHW(nb, rpA, nA) = h0 | (h1 << 16);
            uint32_t l0 = f2bf(p00 - bfval(h0)), l1 = f2bf(p01 - bfval(h1));
            AK_SLW(nb, rpA, nA) = l0 | (l1 << 16);
            uint32_t h2 = f2bf(p10), h3 = f2bf(p11);
            AK_SHW(nb, rpB, nB) = h2 | (h3 << 16);
            uint32_t l2 = f2bf(p10 - bfval(h2)), l3 = f2bf(p11 - bfval(h3));
            AK_SLW(nb, rpB, nB) = l2 | (l3 << 16);
            __syncthreads();
            buf = nb;
        }
    }

    // ---- intra-chunk causal: A = 1 + s/4 + s^2/32, fp32 ----
    float qr0[16], qr1[16];
#pragma unroll
    for (int i = 0; i < 16; i++) {
        qr0[i] = AK_QS(r0, i);
        qr1[i] = AK_QS(r1, i);
    }
    const int mEnd = 16 * (warp + 1);
    for (int m = 0; m < mEnd; m++) {
        float s0 = 0.f, s1 = 0.f;
#pragma unroll
        for (int i = 0; i < 16; i++) {
            const float ki = AK_KC(m, i);
            s0 = fmaf(qr0[i], ki, s0);
            s1 = fmaf(qr1[i], ki, s1);
        }
        const float sd0 = s0 * DOT, sd1 = s1 * DOT;
        float a0 = fmaf(sd0, 0.25f, 1.0f);
        a0 = fmaf(sd0 * sd0, 0.03125f, a0);
        float a1 = fmaf(sd1, 0.25f, 1.0f);
        a1 = fmaf(sd1 * sd1, 0.03125f, a1);
        a0 = (m <= r0) ? a0 : 0.f;
        a1 = (m <= r1) ? a1 : 0.f;
#pragma unroll
        for (int nt = 0; nt < 8; nt++) {
            const float2 v = *(const float2*)&AK_VC(m, nt * 8 + tig * 2);
            acc[nt][0] = fmaf(a0, v.x, acc[nt][0]);
            acc[nt][1] = fmaf(a0, v.y, acc[nt][1]);
            acc[nt][2] = fmaf(a1, v.x, acc[nt][2]);
            acc[nt][3] = fmaf(a1, v.y, acc[nt][3]);
        }
    }

    // ---- RMSNorm (reduce across tig lanes) + gate + store ----
    float ss0 = 0.f, ss1 = 0.f;
#pragma unroll
    for (int nt = 0; nt < 8; nt++) {
        ss0 = fmaf(acc[nt][0], acc[nt][0], ss0);
        ss0 = fmaf(acc[nt][1], acc[nt][1], ss0);
        ss1 = fmaf(acc[nt][2], acc[nt][2], ss1);
        ss1 = fmaf(acc[nt][3], acc[nt][3], ss1);
    }
    ss0 += __shfl_xor_sync(0xffffffffu, ss0, 1);
    ss0 += __shfl_xor_sync(0xffffffffu, ss0, 2);
    ss1 += __shfl_xor_sync(0xffffffffu, ss1, 1);
    ss1 += __shfl_xor_sync(0xffffffffu, ss1, 2);
    const float rms0 = rsqrtf(ss0 * (1.0f / 64.0f) + 1e-5f);
    const float rms1 = rsqrtf(ss1 * (1.0f / 64.0f) + 1e-5f);
    float* y0 = Y + (size_t)(tok0 + r0) * VDIM + h * HDIM;
    float* y1 = Y + (size_t)(tok0 + r1) * VDIM + h * HDIM;
#pragma unroll
    for (int nt = 0; nt < 8; nt++) {
        const int c = nt * 8 + tig * 2;
        float2 o0, o1;
        o0.x = acc[nt][0] * rms0 * AK_GS(c);
        o0.y = acc[nt][1] * rms0 * AK_GS(c + 1);
        o1.x = acc[nt][2] * rms1 * AK_GS(c);
        o1.y = acc[nt][3] * rms1 * AK_GS(c + 1);
        *(float2*)&y0[c] = o0;
        *(float2*)&y1[c] = o1;
    }
}

// ---------------------------------------------------------------------------
extern "C" void kernel_launch(void* const* d_in, const int* in_sizes, int n_in,
                              void* d_out, int out_size) {
    const float* X  = (const float*)d_in[0];
    const float* Wq = (const float*)d_in[1];
    const float* Wk = (const float*)d_in[2];
    const float* Wv = (const float*)d_in[3];
    const float* Wo = (const float*)d_in[4];
    const float* g  = (const float*)d_in[5];
    float* out = (float*)d_out;

    float *Qb, *Kb, *Vb, *Yb, *Sb;
    cudaGetSymbolAddress((void**)&Qb, g_Q);
    cudaGetSymbolAddress((void**)&Kb, g_K);
    cudaGetSymbolAddress((void**)&Vb, g_V);
    cudaGetSymbolAddress((void**)&Yb, g_Y);
    cudaGetSymbolAddress((void**)&Sb, g_DS);

    static int attn_smem_set = 0;
    if (!attn_smem_set) {
        cudaFuncSetAttribute(attn_out_kernel,
                             cudaFuncAttributeMaxDynamicSharedMemorySize,
                             ATTN_SMEM);
        attn_smem_set = 1;
    }

    // Projections (separate launches — proven fastest config)
    tgemm_nt<<<dim3(NTOK / 128, QKDIM / 128), 128>>>(X, Wq, Qb, NTOK, QKDIM, DMODEL);
    tgemm_nt<<<dim3(NTOK / 128, QKDIM / 128), 128>>>(X, Wk, Kb, NTOK, QKDIM, DMODEL);
    tgemm_nt<<<dim3(NTOK / 128, VDIM / 128),  128>>>(X, Wv, Vb, NTOK, VDIM,  DMODEL);

    // Chunked linear attention
    float* kv_out = (out_size >= OUT_ELEMS + KV_ELEMS) ? (out + OUT_ELEMS) : nullptr;
    state_kernel<<<dim3(NCHUNK, BATCH * NHEADS, 2), 256>>>(Kb, Vb, Sb);
    scan_kernel<<<dim3((SDF / 4 + 255) / 256, BATCH * NHEADS), 256>>>(Sb, kv_out);
    attn_out_kernel<<<dim3(NCHUNK, BATCH * NHEADS), 256, ATTN_SMEM>>>(
        Qb, Kb, Vb, Sb, g, Yb);

    // Output projection
    tgemm_nt<<<dim3(NTOK / 128, DMODEL / 128), 128>>>(Yb, Wo, out, NTOK, DMODEL, DMODEL);
}

// round 12
// speedup vs baseline: 1.8564x; 1.0539x over previous
#include <cuda_runtime.h>
#include <cuda_bf16.h>
#include <math.h>
#include <stdint.h>

// Problem constants (fixed shapes from setup_inputs)
#define BATCH 4
#define SEQ   2048
#define DMODEL 1024
#define NHEADS 16
#define FDIM  16
#define HDIM  64
#define NTOK  (BATCH*SEQ)          // 8192
#define QKDIM (NHEADS*FDIM)        // 256
#define VDIM  (NHEADS*HDIM)        // 1024
#define FEAT  273                  // 1 + 16 + 256
#define NCHUNK 16                  // 2048 / 128
#define CHUNK 128
#define KV_ELEMS (BATCH*NHEADS*HDIM*FEAT)   // 1,118,208
#define OUT_ELEMS (NTOK*DMODEL)             // 8,388,608
#define SDF (FEAT*HDIM)            // 17472
#define PROW 153                   // 1 + 16 + 136 packed symmetric rows
#define SDF_P (PROW*HDIM)          // 9792

// Scratch (device globals; no runtime allocation)
__device__ float g_Q[NTOK*QKDIM];
__device__ float g_K[NTOK*QKDIM];
__device__ float g_V[NTOK*VDIM];
__device__ float g_Y[NTOK*VDIM];
__device__ float g_DS[64*NCHUNK*SDF];     // full chunk states (state_kernel out)
__device__ float g_SP[64*NCHUNK*SDF_P];   // packed exclusive-prefix states

__device__ __forceinline__ uint32_t f2tf32(float x) {
    uint32_t u;
    asm("cvt.rna.tf32.f32 %0, %1;" : "=r"(u) : "f"(x));
    return u;
}
// bf16 round-to-nearest-even (returns low 16 bits)
__device__ __forceinline__ uint32_t f2bf(float x) {
    uint32_t u = __float_as_uint(x);
    return (u + 0x7fffu + ((u >> 16) & 1u)) >> 16;
}
__device__ __forceinline__ float bfval(uint32_t b) {
    return __uint_as_float(b << 16);
}
// packed index p -> (i,j), j<=i  (sqrt trick + correction)
__device__ __forceinline__ void p2ij(int p, int& i, int& j) {
    i = (int)((sqrtf(8.f * p + 1.f) - 1.f) * 0.5f);
    if ((i + 1) * (i + 2) / 2 <= p) i++;
    if (i * (i + 1) / 2 > p) i--;
    j = p - i * (i + 1) / 2;
}

// ---------------------------------------------------------------------------
// tf32 GEMM (R4 design, proven): 128x128 block, 4 warps of 64x64, BK=16,
// double-buffered smem [k][row] pad 132, one sync per K-tile.
// ---------------------------------------------------------------------------
struct GSmem {
    uint32_t As[2][16][132];
    uint32_t Bs[2][16][132];
};

__device__ __forceinline__ void gemm_tile(
    const float* __restrict__ A, const float* __restrict__ B,
    float* __restrict__ C, int N, int K, int bm, int bn, GSmem& sm) {
    const int tid  = threadIdx.x;
    const int warp = tid >> 5, lane = tid & 31;
    const int gid  = lane >> 2, tig = lane & 3;
    const int wm = (warp >> 1) * 64, wn = (warp & 1) * 64;

    const int lr = tid >> 2;
    const int kc = (tid & 3) << 2;
    const float* Ap = A + (size_t)(bm + lr) * K + kc;
    const float* Bp = B + (size_t)(bn + lr) * K + kc;
    const size_t row32 = (size_t)32 * K;

    float acc[4][8][4];
#pragma unroll
    for (int mt = 0; mt < 4; mt++)
#pragma unroll
        for (int nt = 0; nt < 8; nt++)
#pragma unroll
            for (int e = 0; e < 4; e++) acc[mt][nt][e] = 0.f;

    float4 ar[4], br[4];
#pragma unroll
    for (int p = 0; p < 4; p++) {
        ar[p] = *(const float4*)(Ap + p * row32);
        br[p] = *(const float4*)(Bp + p * row32);
    }
#pragma unroll
    for (int p = 0; p < 4; p++) {
        sm.As[0][kc + 0][lr + p * 32] = f2tf32(ar[p].x);
        sm.As[0][kc + 1][lr + p * 32] = f2tf32(ar[p].y);
        sm.As[0][kc + 2][lr + p * 32] = f2tf32(ar[p].z);
        sm.As[0][kc + 3][lr + p * 32] = f2tf32(ar[p].w);
        sm.Bs[0][kc + 0][lr + p * 32] = f2tf32(br[p].x);
        sm.Bs[0][kc + 1][lr + p * 32] = f2tf32(br[p].y);
        sm.Bs[0][kc + 2][lr + p * 32] = f2tf32(br[p].z);
        sm.Bs[0][kc + 3][lr + p * 32] = f2tf32(br[p].w);
    }
    __syncthreads();

    int cur = 0;
    for (int k0 = 0; k0 < K; k0 += 16) {
        const bool more = (k0 + 16 < K);
        if (more) {
#pragma unroll
            for (int p = 0; p < 4; p++) {
                ar[p] = *(const float4*)(Ap + k0 + 16 + p * row32);
                br[p] = *(const float4*)(Bp + k0 + 16 + p * row32);
            }
        }

#pragma unroll
        for (int ks = 0; ks < 2; ks++) {
            const int kk = ks * 8;
            uint32_t af[4][4], bf[8][2];
#pragma unroll
            for (int mt = 0; mt < 4; mt++) {
                const int m = wm + mt * 16 + gid;
                af[mt][0] = sm.As[cur][kk + tig][m];
                af[mt][1] = sm.As[cur][kk + tig][m + 8];
                af[mt][2] = sm.As[cur][kk + tig + 4][m];
                af[mt][3] = sm.As[cur][kk + tig + 4][m + 8];
            }
#pragma unroll
            for (int nt = 0; nt < 8; nt++) {
                const int n = wn + nt * 8 + gid;
                bf[nt][0] = sm.Bs[cur][kk + tig][n];
                bf[nt][1] = sm.Bs[cur][kk + tig + 4][n];
            }
#pragma unroll
            for (int mt = 0; mt < 4; mt++)
#pragma unroll
                for (int nt = 0; nt < 8; nt++) {
                    asm volatile(
                        "mma.sync.aligned.m16n8k8.row.col.f32.tf32.tf32.f32 "
                        "{%0,%1,%2,%3}, {%4,%5,%6,%7}, {%8,%9}, {%0,%1,%2,%3};"
                        : "+f"(acc[mt][nt][0]), "+f"(acc[mt][nt][1]),
                          "+f"(acc[mt][nt][2]), "+f"(acc[mt][nt][3])
                        : "r"(af[mt][0]), "r"(af[mt][1]),
                          "r"(af[mt][2]), "r"(af[mt][3]),
                          "r"(bf[nt][0]), "r"(bf[nt][1]));
                }
        }

        if (more) {
            const int nxt = cur ^ 1;
#pragma unroll
            for (int p = 0; p < 4; p++) {
                sm.As[nxt][kc + 0][lr + p * 32] = f2tf32(ar[p].x);
                sm.As[nxt][kc + 1][lr + p * 32] = f2tf32(ar[p].y);
                sm.As[nxt][kc + 2][lr + p * 32] = f2tf32(ar[p].z);
                sm.As[nxt][kc + 3][lr + p * 32] = f2tf32(ar[p].w);
                sm.Bs[nxt][kc + 0][lr + p * 32] = f2tf32(br[p].x);
                sm.Bs[nxt][kc + 1][lr + p * 32] = f2tf32(br[p].y);
                sm.Bs[nxt][kc + 2][lr + p * 32] = f2tf32(br[p].z);
                sm.Bs[nxt][kc + 3][lr + p * 32] = f2tf32(br[p].w);
            }
            __syncthreads();
        }
        cur ^= 1;
    }

#pragma unroll
    for (int mt = 0; mt < 4; mt++) {
        const int r0 = bm + wm + mt * 16 + gid;
#pragma unroll
        for (int nt = 0; nt < 8; nt++) {
            const int cc = bn + wn + nt * 8 + tig * 2;
            *(float2*)&C[(size_t)r0 * N + cc] =
                make_float2(acc[mt][nt][0], acc[mt][nt][1]);
            *(float2*)&C[(size_t)(r0 + 8) * N + cc] =
                make_float2(acc[mt][nt][2], acc[mt][nt][3]);
        }
    }
}

__global__ __launch_bounds__(128)
void tgemm_nt(const float* __restrict__ A, const float* __restrict__ B,
              float* __restrict__ C, int M, int N, int K) {
    __shared__ GSmem sm;
    gemm_tile(A, B, C, N, K, blockIdx.x * 128, blockIdx.y * 128, sm);
}

// ---------------------------------------------------------------------------
// Kernel A: per-chunk state increment (full 273 rows), f split over blockIdx.z
// ---------------------------------------------------------------------------
__global__ __launch_bounds__(256, 3)
void state_kernel(const float* __restrict__ Km, const float* __restrict__ V,
                  float* __restrict__ DS) {
    __shared__ float ks[32][16];
    __shared__ float vs[32][32];
    const int ck = blockIdx.x;
    const int bh = blockIdx.y;
    const int fh = blockIdx.z;
    const int b = bh >> 4, h = bh & 15;
    const int tid = threadIdx.x;
    const int i = tid >> 4;
    const int fq = tid & 15;
    const int tokb = b * SEQ + ck * CHUNK;
    const int fbase = fh * 32;

    float m2[16][2];
#pragma unroll
    for (int j = 0; j < 16; j++) { m2[j][0] = 0.f; m2[j][1] = 0.f; }
    float m1[2] = {0.f, 0.f};
    float s0[2] = {0.f, 0.f};

    for (int nb = 0; nb < CHUNK; nb += 32) {
        __syncthreads();
        for (int t = tid; t < 128; t += 256) {
            int r = t >> 2, c4 = (t & 3) << 2;
            *(float4*)&ks[r][c4] =
                *(const float4*)&Km[(size_t)(tokb + nb + r) * QKDIM + h * FDIM + c4];
        }
        {
            int r = tid >> 3, c4 = (tid & 7) << 2;
            *(float4*)&vs[r][c4] =
                *(const float4*)&V[(size_t)(tokb + nb + r) * VDIM + h * HDIM + fbase + c4];
        }
        __syncthreads();
#pragma unroll 4
        for (int r = 0; r < 32; r++) {
            const float ki = ks[r][i];
            const float2 v2 = *(const float2*)&vs[r][fq * 2];
            m1[0] = fmaf(ki, v2.x, m1[0]);
            m1[1] = fmaf(ki, v2.y, m1[1]);
            if (i == 0) { s0[0] += v2.x; s0[1] += v2.y; }
#pragma unroll
            for (int j = 0; j < 16; j++) {
                const float kk = ki * ks[r][j];
                m2[j][0] = fmaf(kk, v2.x, m2[j][0]);
                m2[j][1] = fmaf(kk, v2.y, m2[j][1]);
            }
        }
    }

    float* base = DS + (size_t)(bh * NCHUNK + ck) * SDF;
    const float c2 = 0.17677669529663687f;   // 1/(4*sqrt(2))
#pragma unroll
    for (int ff = 0; ff < 2; ff++) {
        const int f = fbase + fq * 2 + ff;
#pragma unroll
        for (int j = 0; j < 16; j++)
            base[(17 + i * 16 + j) * HDIM + f] = m2[j][ff] * c2;
        base[(1 + i) * HDIM + f] = m1[ff] * 0.5f;
        if (i == 0) base[f] = s0[ff];
    }
}

// ---------------------------------------------------------------------------
// Kernel B: exclusive scan over SYMMETRY-PACKED rows (153) into g_SP.
// Off-diagonal quad rows pre-scaled by 2; kv_state mirrored from the
// inclusive total (unscaled).
// ---------------------------------------------------------------------------
__global__ void scan_kernel(const float* __restrict__ DS, float* __restrict__ SP,
                            float* __restrict__ kv_out) {
    const int bh = blockIdx.y;
    const int e4 = blockIdx.x * 256 + threadIdx.x;   // packed element / 4
    if (e4 >= PROW * 16) return;
    const int dp = e4 >> 4, f0 = (e4 & 15) * 4;

    int dsrc, pi = 0, pj = 0;
    float scale;
    if (dp < 17) { dsrc = dp; scale = 1.f; }
    else {
        p2ij(dp - 17, pi, pj);
        dsrc = 17 + pi * 16 + pj;
        scale = (pi == pj) ? 1.f : 2.f;
    }

    const float* src = DS + (size_t)bh * NCHUNK * SDF + (size_t)dsrc * HDIM + f0;
    float* dst = SP + (size_t)bh * NCHUNK * SDF_P + (size_t)dp * HDIM + f0;
    float4 run = make_float4(0.f, 0.f, 0.f, 0.f);
#pragma unroll
    for (int c = 0; c < NCHUNK; c++) {
        float4 v = *(const float4*)(src + (size_t)c * SDF);
        *(float4*)(dst + (size_t)c * SDF_P) =
            make_float4(run.x * scale, run.y * scale, run.z * scale, run.w * scale);
        run.x += v.x; run.y += v.y; run.z += v.z; run.w += v.w;
    }
    if (kv_out) {
        float* kb = kv_out + (size_t)bh * (HDIM * FEAT);
        const float rv[4] = {run.x, run.y, run.z, run.w};
        if (dp < 17) {
#pragma unroll
            for (int ff = 0; ff < 4; ff++)
                kb[(size_t)(f0 + ff) * FEAT + dp] = rv[ff];
        } else {
            const int d1 = 17 + pi * 16 + pj, d2 = 17 + pj * 16 + pi;
#pragma unroll
            for (int ff = 0; ff < 4; ff++) {
                kb[(size_t)(f0 + ff) * FEAT + d1] = rv[ff];
                kb[(size_t)(f0 + ff) * FEAT + d2] = rv[ff];
            }
        }
    }
}

// ---------------------------------------------------------------------------
// Kernel C: inter-chunk via bf16x3 mma.sync m16n8k16 over PACKED S (10 steps),
// intra-chunk causal fp32, fused RMSNorm + g.
// ---------------------------------------------------------------------------
#define AK_QS(r,c)     dyn[(r)*17+(c)]                 // q*SC, col16 = 1.0
#define AK_KC(r,c)     dyn[2176+(r)*16+(c)]            // raw k
#define AK_VC(r,c)     dyn[4224+(r)*64+(c)]            // v
#define AK_GS(c)       dyn[14720+(c)]
#define ATTN_SMEM      (14784*4)                       // 59,136 bytes
// packed bf16 S tiles (uint32 views): [buf][8 rowpairs][72]
#define AK_SHW(b,rp,n) shw[(b)*576+(rp)*72+(n)]
#define AK_SLW(b,rp,n) slw[(b)*576+(rp)*72+(n)]

__device__ __forceinline__ float qfeatp(const float* dyn, const uchar2* ptab,
                                        int r, int d) {
    if (d == 0) return 1.0f;
    if (d < 17) return AK_QS(r, d - 1) * 1.1892071150027210f;   // 0.5/SC folded
    if (d < PROW) {
        const uchar2 ij = ptab[d - 17];
        return AK_QS(r, ij.x) * AK_QS(r, ij.y);
    }
    return 0.f;
}

__global__ __launch_bounds__(256, 2)
void attn_out_kernel(const float* __restrict__ Q, const float* __restrict__ Km,
                     const float* __restrict__ V, const float* __restrict__ Sprev,
                     const float* __restrict__ g, float* __restrict__ Y) {
    extern __shared__ float dyn[];
    __shared__ uchar2 ptab[136];
    uint32_t* shw = (uint32_t*)(dyn + 12416);
    uint32_t* slw = (uint32_t*)(dyn + 13568);
    const int ck = blockIdx.x;
    const int bh = blockIdx.y;
    const int b = bh >> 4, h = bh & 15;
    const int tid = threadIdx.x;
    const int warp = tid >> 5, lane = tid & 31;
    const int gid = lane >> 2, tig = lane & 3;
    const int tok0 = b * SEQ + ck * CHUNK;
    const float SC  = 0.4204482076268573f;    // sqrt(1/(4*sqrt2))
    const float DOT = 2.3784142300054421f;    // 1/SC
    const float* Sp = Sprev + (size_t)(bh * NCHUNK + ck) * SDF_P;

    // ---- stage Q (scaled, padded), K, V, g, pair table ----
    for (int t = tid; t < 512; t += 256) {
        int r = t >> 2, c4 = (t & 3) << 2;
        float4 qv = *(const float4*)&Q[(size_t)(tok0 + r) * QKDIM + h * FDIM + c4];
        AK_QS(r, c4 + 0) = qv.x * SC; AK_QS(r, c4 + 1) = qv.y * SC;
        AK_QS(r, c4 + 2) = qv.z * SC; AK_QS(r, c4 + 3) = qv.w * SC;
        float4 kv = *(const float4*)&Km[(size_t)(tok0 + r) * QKDIM + h * FDIM + c4];
        AK_KC(r, c4 + 0) = kv.x; AK_KC(r, c4 + 1) = kv.y;
        AK_KC(r, c4 + 2) = kv.z; AK_KC(r, c4 + 3) = kv.w;
    }
    if (tid < 128) AK_QS(tid, 16) = 1.0f;
    for (int t = tid; t < 2048; t += 256) {
        int r = t >> 4, c4 = (t & 15) << 2;
        *(float4*)&AK_VC(r, c4) =
            *(const float4*)&V[(size_t)(tok0 + r) * VDIM + h * HDIM + c4];
    }
    if (tid < 64) AK_GS(tid) = g[tid];
    if (tid < 136) {
        int i, j;
        p2ij(tid, i, j);
        ptab[tid] = make_uchar2((unsigned char)i, (unsigned char)j);
    }
    // ---- S tile for step 0 (packed rows 0..15, bf16 hi/lo) ----
    {
#pragma unroll
        for (int q = 0; q < 2; q++) {
            const int id = tid + q * 256;       // 0..511
            const int rp = id >> 6, n = id & 63;
            const int fr = 2 * rp;
            float v0 = Sp[fr * HDIM + n];
            float v1 = Sp[(fr + 1) * HDIM + n];
            uint32_t h0 = f2bf(v0), h1 = f2bf(v1);
            AK_SHW(0, rp, n) = h0 | (h1 << 16);
            uint32_t l0 = f2bf(v0 - bfval(h0)), l1 = f2bf(v1 - bfval(h1));
            AK_SLW(0, rp, n) = l0 | (l1 << 16);
        }
    }
    __syncthreads();

    float acc[8][4];
#pragma unroll
    for (int nt = 0; nt < 8; nt++)
#pragma unroll
        for (int e = 0; e < 4; e++) acc[nt][e] = 0.f;

    // ---- inter-chunk: y += qf @ S_packed via bf16x3 MMA, 10 k-steps of 16 ----
    const int r0 = warp * 16 + gid;
    const int r1 = r0 + 8;
    int buf = 0;
    for (int s = 0; s < 10; s++) {
        // prefetch next S tile (2 rowpairs x cols per thread) to registers
        float p00 = 0.f, p01 = 0.f, p10 = 0.f, p11 = 0.f;
        int rpA = 0, nA = 0, rpB = 0, nB = 0;
        if (s < 9) {
            const int fb = 16 * (s + 1);
            int idA = tid;           rpA = idA >> 6; nA = idA & 63;
            int idB = tid + 256;     rpB = idB >> 6; nB = idB & 63;
            int frA = fb + 2 * rpA, frB = fb + 2 * rpB;
            if (frA < PROW)     p00 = Sp[frA * HDIM + nA];
            if (frA + 1 < PROW) p01 = Sp[(frA + 1) * HDIM + nA];
            if (frB < PROW)     p10 = Sp[frB * HDIM + nB];
            if (frB + 1 < PROW) p11 = Sp[(frB + 1) * HDIM + nB];
        }
        // generate A fragments (bf16 hi/lo, packed pairs along k)
        const int da = 16 * s + 2 * tig;
        const int db = da + 8;
        float f00 = qfeatp(dyn, ptab, r0, da),  f01 = qfeatp(dyn, ptab, r0, da + 1);
        float f10 = qfeatp(dyn, ptab, r1, da),  f11 = qfeatp(dyn, ptab, r1, da + 1);
        float f02 = qfeatp(dyn, ptab, r0, db),  f03 = qfeatp(dyn, ptab, r0, db + 1);
        float f12 = qfeatp(dyn, ptab, r1, db),  f13 = qfeatp(dyn, ptab, r1, db + 1);
        uint32_t ah[4], al[4];
        {
            uint32_t h00 = f2bf(f00), h01 = f2bf(f01);
            uint32_t h10 = f2bf(f10), h11 = f2bf(f11);
            uint32_t h02 = f2bf(f02), h03 = f2bf(f03);
            uint32_t h12 = f2bf(f12), h13 = f2bf(f13);
            ah[0] = h00 | (h01 << 16);
            ah[1] = h10 | (h11 << 16);
            ah[2] = h02 | (h03 << 16);
            ah[3] = h12 | (h13 << 16);
            uint32_t l00 = f2bf(f00 - bfval(h00)), l01 = f2bf(f01 - bfval(h01));
            uint32_t l10 = f2bf(f10 - bfval(h10)), l11 = f2bf(f11 - bfval(h11));
            uint32_t l02 = f2bf(f02 - bfval(h02)), l03 = f2bf(f03 - bfval(h03));
            uint32_t l12 = f2bf(f12 - bfval(h12)), l13 = f2bf(f13 - bfval(h13));
            al[0] = l00 | (l01 << 16);
            al[1] = l10 | (l11 << 16);
            al[2] = l02 | (l03 << 16);
            al[3] = l12 | (l13 << 16);
        }
#pragma unroll
        for (int nt = 0; nt < 8; nt++) {
            const int n = nt * 8 + gid;
            uint32_t bh0 = AK_SHW(buf, tig, n);
            uint32_t bh1 = AK_SHW(buf, tig + 4, n);
            uint32_t bl0 = AK_SLW(buf, tig, n);
            uint32_t bl1 = AK_SLW(buf, tig + 4, n);
            asm volatile(
                "mma.sync.aligned.m16n8k16.row.col.f32.bf16.bf16.f32 "
                "{%0,%1,%2,%3}, {%4,%5,%6,%7}, {%8,%9}, {%0,%1,%2,%3};"
                : "+f"(acc[nt][0]), "+f"(acc[nt][1]),
                  "+f"(acc[nt][2]), "+f"(acc[nt][3])
                : "r"(ah[0]), "r"(ah[1]), "r"(ah[2]), "r"(ah[3]),
                  "r"(bh0), "r"(bh1));
            asm volatile(
                "mma.sync.aligned.m16n8k16.row.col.f32.bf16.bf16.f32 "
                "{%0,%1,%2,%3}, {%4,%5,%6,%7}, {%8,%9}, {%0,%1,%2,%3};"
                : "+f"(acc[nt][0]), "+f"(acc[nt][1]),
                  "+f"(acc[nt][2]), "+f"(acc[nt][3])
                : "r"(ah[0]), "r"(ah[1]), "r"(ah[2]), "r"(ah[3]),
                  "r"(bl0), "r"(bl1));
            asm volatile(
                "mma.sync.aligned.m16n8k16.row.col.f32.bf16.bf16.f32 "
                "{%0,%1,%2,%3}, {%4,%5,%6,%7}, {%8,%9}, {%0,%1,%2,%3};"
                : "+f"(acc[nt][0]), "+f"(acc[nt][1]),
                  "+f"(acc[nt][2]), "+f"(acc[nt][3])
                : "r"(al[0]), "r"(al[1]), "r"(al[2]), "r"(al[3]),
                  "r"(bh0), "r"(bh1));
        }
        // store prefetched tile (bf16 hi/lo packed) into the other buffer
        if (s < 9) {
            const int nb = buf ^ 1;
            uint32_t h0 = f2bf(p00), h1 = f2bf(p01);
            AK_SHW(nb, rpA, nA) = h0 | (h1 << 16);
            uint32_t l0 = f2bf(p00 - bfval(h0)), l1 = f2bf(p01 - bfval(h1));
            AK_SLW(nb, rpA, nA) = l0 | (l1 << 16);
            uint32_t h2 = f2bf(p10), h3 = f2bf(p11);
            AK_SHW(nb, rpB, nB) = h2 | (h3 << 16);
            uint32_t l2 = f2bf(p10 - bfval(h2)), l3 = f2bf(p11 - bfval(h3));
            AK_SLW(nb, rpB, nB) = l2 | (l3 << 16);
            __syncthreads();
            buf = nb;
        }
    }

    // ---- intra-chunk causal: A = 1 + s/4 + s^2/32, fp32 ----
    float qr0[16], qr1[16];
#pragma unroll
    for (int i = 0; i < 16; i++) {
        qr0[i] = AK_QS(r0, i);
        qr1[i] = AK_QS(r1, i);
    }
    const int mEnd = 16 * (warp + 1);
    for (int m = 0; m < mEnd; m++) {
        float s0 = 0.f, s1 = 0.f;
#pragma unroll
        for (int i = 0; i < 16; i++) {
            const float ki = AK_KC(m, i);
            s0 = fmaf(qr0[i], ki, s0);
            s1 = fmaf(qr1[i], ki, s1);
        }
        const float sd0 = s0 * DOT, sd1 = s1 * DOT;
        float a0 = fmaf(sd0, 0.25f, 1.0f);
        a0 = fmaf(sd0 * sd0, 0.03125f, a0);
        float a1 = fmaf(sd1, 0.25f, 1.0f);
        a1 = fmaf(sd1 * sd1, 0.03125f, a1);
        a0 = (m <= r0) ? a0 : 0.f;
        a1 = (m <= r1) ? a1 : 0.f;
#pragma unroll
        for (int nt = 0; nt < 8; nt++) {
            const float2 v = *(const float2*)&AK_VC(m, nt * 8 + tig * 2);
            acc[nt][0] = fmaf(a0, v.x, acc[nt][0]);
            acc[nt][1] = fmaf(a0, v.y, acc[nt][1]);
            acc[nt][2] = fmaf(a1, v.x, acc[nt][2]);
            acc[nt][3] = fmaf(a1, v.y, acc[nt][3]);
        }
    }

    // ---- RMSNorm (reduce across tig lanes) + gate + store ----
    float ss0 = 0.f, ss1 = 0.f;
#pragma unroll
    for (int nt = 0; nt < 8; nt++) {
        ss0 = fmaf(acc[nt][0], acc[nt][0], ss0);
        ss0 = fmaf(acc[nt][1], acc[nt][1], ss0);
        ss1 = fmaf(acc[nt][2], acc[nt][2], ss1);
        ss1 = fmaf(acc[nt][3], acc[nt][3], ss1);
    }
    ss0 += __shfl_xor_sync(0xffffffffu, ss0, 1);
    ss0 += __shfl_xor_sync(0xffffffffu, ss0, 2);
    ss1 += __shfl_xor_sync(0xffffffffu, ss1, 1);
    ss1 += __shfl_xor_sync(0xffffffffu, ss1, 2);
    const float rms0 = rsqrtf(ss0 * (1.0f / 64.0f) + 1e-5f);
    const float rms1 = rsqrtf(ss1 * (1.0f / 64.0f) + 1e-5f);
    float* y0 = Y + (size_t)(tok0 + r0) * VDIM + h * HDIM;
    float* y1 = Y + (size_t)(tok0 + r1) * VDIM + h * HDIM;
#pragma unroll
    for (int nt = 0; nt < 8; nt++) {
        const int c = nt * 8 + tig * 2;
        float2 o0, o1;
        o0.x = acc[nt][0] * rms0 * AK_GS(c);
        o0.y = acc[nt][1] * rms0 * AK_GS(c + 1);
        o1.x = acc[nt][2] * rms1 * AK_GS(c);
        o1.y = acc[nt][3] * rms1 * AK_GS(c + 1);
        *(float2*)&y0[c] = o0;
        *(float2*)&y1[c] = o1;
    }
}

// ---------------------------------------------------------------------------
extern "C" void kernel_launch(void* const* d_in, const int* in_sizes, int n_in,
                              void* d_out, int out_size) {
    const float* X  = (const float*)d_in[0];
    const float* Wq = (const float*)d_in[1];
    const float* Wk = (const float*)d_in[2];
    const float* Wv = (const float*)d_in[3];
    const float* Wo = (const float*)d_in[4];
    const float* g  = (const float*)d_in[5];
    float* out = (float*)d_out;

    float *Qb, *Kb, *Vb, *Yb, *Sb, *SPb;
    cudaGetSymbolAddress((void**)&Qb, g_Q);
    cudaGetSymbolAddress((void**)&Kb, g_K);
    cudaGetSymbolAddress((void**)&Vb, g_V);
    cudaGetSymbolAddress((void**)&Yb, g_Y);
    cudaGetSymbolAddress((void**)&Sb, g_DS);
    cudaGetSymbolAddress((void**)&SPb, g_SP);

    static int attn_smem_set = 0;
    if (!attn_smem_set) {
        cudaFuncSetAttribute(attn_out_kernel,
                             cudaFuncAttributeMaxDynamicSharedMemorySize,
                             ATTN_SMEM);
        attn_smem_set = 1;
    }

    // Projections (separate launches — proven fastest config)
    tgemm_nt<<<dim3(NTOK / 128, QKDIM / 128), 128>>>(X, Wq, Qb, NTOK, QKDIM, DMODEL);
    tgemm_nt<<<dim3(NTOK / 128, QKDIM / 128), 128>>>(X, Wk, Kb, NTOK, QKDIM, DMODEL);
    tgemm_nt<<<dim3(NTOK / 128, VDIM / 128),  128>>>(X, Wv, Vb, NTOK, VDIM,  DMODEL);

    // Chunked linear attention (packed symmetric prefix states)
    float* kv_out = (out_size >= OUT_ELEMS + KV_ELEMS) ? (out + OUT_ELEMS) : nullptr;
    state_kernel<<<dim3(NCHUNK, BATCH * NHEADS, 2), 256>>>(Kb, Vb, Sb);
    scan_kernel<<<dim3((PROW * 16 + 255) / 256, BATCH * NHEADS), 256>>>(
        Sb, SPb, kv_out);
    attn_out_kernel<<<dim3(NCHUNK, BATCH * NHEADS), 256, ATTN_SMEM>>>(
        Qb, Kb, Vb, SPb, g, Yb);

    // Output projection
    tgemm_nt<<<dim3(NTOK / 128, DMODEL / 128), 128>>>(Yb, Wo, out, NTOK, DMODEL, DMODEL);
}

// round 13
// speedup vs baseline: 2.0506x; 1.1046x over previous
#include <cuda_runtime.h>
#include <cuda_bf16.h>
#include <math.h>
#include <stdint.h>

// Problem constants (fixed shapes from setup_inputs)
#define BATCH 4
#define SEQ   2048
#define DMODEL 1024
#define NHEADS 16
#define FDIM  16
#define HDIM  64
#define NTOK  (BATCH*SEQ)          // 8192
#define QKDIM (NHEADS*FDIM)        // 256
#define VDIM  (NHEADS*HDIM)        // 1024
#define FEAT  273                  // 1 + 16 + 256
#define NCHUNK 16                  // 2048 / 128
#define CHUNK 128
#define KV_ELEMS (BATCH*NHEADS*HDIM*FEAT)   // 1,118,208
#define OUT_ELEMS (NTOK*DMODEL)             // 8,388,608
#define PROW 153                   // 1 + 16 + 136 packed symmetric rows
#define SDF_P (PROW*HDIM)          // 9792
#define C2F 0.17677669529663687f   // 1/(4*sqrt(2))

// Scratch (device globals; no runtime allocation)
__device__ float g_Q[NTOK*QKDIM];
__device__ float g_K[NTOK*QKDIM];
__device__ float g_V[NTOK*VDIM];
__device__ float g_Y[NTOK*VDIM];
__device__ float g_DS[64*NCHUNK*SDF_P];   // packed chunk states (state out)
__device__ float g_SP[64*NCHUNK*SDF_P];   // packed exclusive-prefix states

__device__ __forceinline__ uint32_t f2tf32(float x) {
    uint32_t u;
    asm("cvt.rna.tf32.f32 %0, %1;" : "=r"(u) : "f"(x));
    return u;
}
// bf16 round-to-nearest-even (returns low 16 bits)
__device__ __forceinline__ uint32_t f2bf(float x) {
    uint32_t u = __float_as_uint(x);
    return (u + 0x7fffu + ((u >> 16) & 1u)) >> 16;
}
__device__ __forceinline__ float bfval(uint32_t b) {
    return __uint_as_float(b << 16);
}
// packed index p -> (i,j), j<=i  (sqrt trick + correction)
__device__ __forceinline__ void p2ij(int p, int& i, int& j) {
    i = (int)((sqrtf(8.f * p + 1.f) - 1.f) * 0.5f);
    if ((i + 1) * (i + 2) / 2 <= p) i++;
    if (i * (i + 1) / 2 > p) i--;
    j = p - i * (i + 1) / 2;
}

#define MMA_BF16(acc_, a_, b0_, b1_)                                           \
    asm volatile(                                                              \
        "mma.sync.aligned.m16n8k16.row.col.f32.bf16.bf16.f32 "                 \
        "{%0,%1,%2,%3}, {%4,%5,%6,%7}, {%8,%9}, {%0,%1,%2,%3};"                \
        : "+f"((acc_)[0]), "+f"((acc_)[1]), "+f"((acc_)[2]), "+f"((acc_)[3])   \
        : "r"((a_)[0]), "r"((a_)[1]), "r"((a_)[2]), "r"((a_)[3]),              \
          "r"(b0_), "r"(b1_))

// ---------------------------------------------------------------------------
// tf32 GEMM (R4 design, proven): 128x128 block, 4 warps of 64x64, BK=16,
// double-buffered smem [k][row] pad 132, one sync per K-tile.
// ---------------------------------------------------------------------------
struct GSmem {
    uint32_t As[2][16][132];
    uint32_t Bs[2][16][132];
};

__device__ __forceinline__ void gemm_tile(
    const float* __restrict__ A, const float* __restrict__ B,
    float* __restrict__ C, int N, int K, int bm, int bn, GSmem& sm) {
    const int tid  = threadIdx.x;
    const int warp = tid >> 5, lane = tid & 31;
    const int gid  = lane >> 2, tig = lane & 3;
    const int wm = (warp >> 1) * 64, wn = (warp & 1) * 64;

    const int lr = tid >> 2;
    const int kc = (tid & 3) << 2;
    const float* Ap = A + (size_t)(bm + lr) * K + kc;
    const float* Bp = B + (size_t)(bn + lr) * K + kc;
    const size_t row32 = (size_t)32 * K;

    float acc[4][8][4];
#pragma unroll
    for (int mt = 0; mt < 4; mt++)
#pragma unroll
        for (int nt = 0; nt < 8; nt++)
#pragma unroll
            for (int e = 0; e < 4; e++) acc[mt][nt][e] = 0.f;

    float4 ar[4], br[4];
#pragma unroll
    for (int p = 0; p < 4; p++) {
        ar[p] = *(const float4*)(Ap + p * row32);
        br[p] = *(const float4*)(Bp + p * row32);
    }
#pragma unroll
    for (int p = 0; p < 4; p++) {
        sm.As[0][kc + 0][lr + p * 32] = f2tf32(ar[p].x);
        sm.As[0][kc + 1][lr + p * 32] = f2tf32(ar[p].y);
        sm.As[0][kc + 2][lr + p * 32] = f2tf32(ar[p].z);
        sm.As[0][kc + 3][lr + p * 32] = f2tf32(ar[p].w);
        sm.Bs[0][kc + 0][lr + p * 32] = f2tf32(br[p].x);
        sm.Bs[0][kc + 1][lr + p * 32] = f2tf32(br[p].y);
        sm.Bs[0][kc + 2][lr + p * 32] = f2tf32(br[p].z);
        sm.Bs[0][kc + 3][lr + p * 32] = f2tf32(br[p].w);
    }
    __syncthreads();

    int cur = 0;
    for (int k0 = 0; k0 < K; k0 += 16) {
        const bool more = (k0 + 16 < K);
        if (more) {
#pragma unroll
            for (int p = 0; p < 4; p++) {
                ar[p] = *(const float4*)(Ap + k0 + 16 + p * row32);
                br[p] = *(const float4*)(Bp + k0 + 16 + p * row32);
            }
        }

#pragma unroll
        for (int ks = 0; ks < 2; ks++) {
            const int kk = ks * 8;
            uint32_t af[4][4], bf[8][2];
#pragma unroll
            for (int mt = 0; mt < 4; mt++) {
                const int m = wm + mt * 16 + gid;
                af[mt][0] = sm.As[cur][kk + tig][m];
                af[mt][1] = sm.As[cur][kk + tig][m + 8];
                af[mt][2] = sm.As[cur][kk + tig + 4][m];
                af[mt][3] = sm.As[cur][kk + tig + 4][m + 8];
            }
#pragma unroll
            for (int nt = 0; nt < 8; nt++) {
                const int n = wn + nt * 8 + gid;
                bf[nt][0] = sm.Bs[cur][kk + tig][n];
                bf[nt][1] = sm.Bs[cur][kk + tig + 4][n];
            }
#pragma unroll
            for (int mt = 0; mt < 4; mt++)
#pragma unroll
                for (int nt = 0; nt < 8; nt++) {
                    asm volatile(
                        "mma.sync.aligned.m16n8k8.row.col.f32.tf32.tf32.f32 "
                        "{%0,%1,%2,%3}, {%4,%5,%6,%7}, {%8,%9}, {%0,%1,%2,%3};"
                        : "+f"(acc[mt][nt][0]), "+f"(acc[mt][nt][1]),
                          "+f"(acc[mt][nt][2]), "+f"(acc[mt][nt][3])
                        : "r"(af[mt][0]), "r"(af[mt][1]),
                          "r"(af[mt][2]), "r"(af[mt][3]),
                          "r"(bf[nt][0]), "r"(bf[nt][1]));
                }
        }

        if (more) {
            const int nxt = cur ^ 1;
#pragma unroll
            for (int p = 0; p < 4; p++) {
                sm.As[nxt][kc + 0][lr + p * 32] = f2tf32(ar[p].x);
                sm.As[nxt][kc + 1][lr + p * 32] = f2tf32(ar[p].y);
                sm.As[nxt][kc + 2][lr + p * 32] = f2tf32(ar[p].z);
                sm.As[nxt][kc + 3][lr + p * 32] = f2tf32(ar[p].w);
                sm.Bs[nxt][kc + 0][lr + p * 32] = f2tf32(br[p].x);
                sm.Bs[nxt][kc + 1][lr + p * 32] = f2tf32(br[p].y);
                sm.Bs[nxt][kc + 2][lr + p * 32] = f2tf32(br[p].z);
                sm.Bs[nxt][kc + 3][lr + p * 32] = f2tf32(br[p].w);
            }
            __syncthreads();
        }
        cur ^= 1;
    }

#pragma unroll
    for (int mt = 0; mt < 4; mt++) {
        const int r0 = bm + wm + mt * 16 + gid;
#pragma unroll
        for (int nt = 0; nt < 8; nt++) {
            const int cc = bn + wn + nt * 8 + tig * 2;
            *(float2*)&C[(size_t)r0 * N + cc] =
                make_float2(acc[mt][nt][0], acc[mt][nt][1]);
            *(float2*)&C[(size_t)(r0 + 8) * N + cc] =
                make_float2(acc[mt][nt][2], acc[mt][nt][3]);
        }
    }
}

__global__ __launch_bounds__(128)
void tgemm_nt(const float* __restrict__ A, const float* __restrict__ B,
              float* __restrict__ C, int M, int N, int K) {
    __shared__ GSmem sm;
    gemm_tile(A, B, C, N, K, blockIdx.x * 128, blockIdx.y * 128, sm);
}

// ---------------------------------------------------------------------------
// Kernel A: per-chunk state increment via bf16x3 MMA.
// DS_packed[160pad x 64] = kf_features[160 x 128] @ v[128 x 64].
// 8 warps: (row-group wr in {0,1} -> 5 m-tiles of 16) x (col wc -> n16).
// No mainloop syncs; k-features generated in registers from Ks smem.
// ---------------------------------------------------------------------------
__global__ __launch_bounds__(256, 2)
void state_mma_kernel(const float* __restrict__ Km, const float* __restrict__ V,
                      float* __restrict__ DS) {
    __shared__ float ks[128][17];       // raw k, col16 = 1.0
    __shared__ uint32_t vh[64][72];     // packed bf16 token-pairs (hi)
    __shared__ uint32_t vl[64][72];     // packed bf16 token-pairs (lo)
    __shared__ uchar2 ptab[136];
    const int ck = blockIdx.x, bh = blockIdx.y;
    const int b = bh >> 4, h = bh & 15;
    const int tid = threadIdx.x;
    const int warp = tid >> 5, lane = tid & 31;
    const int gid = lane >> 2, tig = lane & 3;
    const int wr = warp >> 2, wc = warp & 3;
    const int tokb = b * SEQ + ck * CHUNK;

    // stage K
    for (int t = tid; t < 512; t += 256) {
        int r = t >> 2, c4 = (t & 3) << 2;
        float4 kv = *(const float4*)&Km[(size_t)(tokb + r) * QKDIM + h * FDIM + c4];
        ks[r][c4 + 0] = kv.x; ks[r][c4 + 1] = kv.y;
        ks[r][c4 + 2] = kv.z; ks[r][c4 + 3] = kv.w;
    }
    if (tid < 128) ks[tid][16] = 1.0f;
    // stage V as packed bf16 token-pairs (hi/lo)
    for (int t = tid; t < 1024; t += 256) {
        int kp = t >> 4, c4 = (t & 15) << 2;
        float4 a = *(const float4*)&V[(size_t)(tokb + 2 * kp) * VDIM + h * HDIM + c4];
        float4 bb = *(const float4*)&V[(size_t)(tokb + 2 * kp + 1) * VDIM + h * HDIM + c4];
        const float av[4] = {a.x, a.y, a.z, a.w};
        const float bv[4] = {bb.x, bb.y, bb.z, bb.w};
#pragma unroll
        for (int e = 0; e < 4; e++) {
            uint32_t h0 = f2bf(av[e]), h1 = f2bf(bv[e]);
            vh[kp][c4 + e] = h0 | (h1 << 16);
            uint32_t l0 = f2bf(av[e] - bfval(h0)), l1 = f2bf(bv[e] - bfval(h1));
            vl[kp][c4 + e] = l0 | (l1 << 16);
        }
    }
    if (tid < 136) {
        int i, j;
        p2ij(tid, i, j);
        ptab[tid] = make_uchar2((unsigned char)i, (unsigned char)j);
    }
    __syncthreads();

    // per-thread feature params (i, j, weight) for the 10 rows it owns
    int ia[5][2], ja[5][2];
    float wt[5][2];
#pragma unroll
    for (int mt = 0; mt < 5; mt++) {
#pragma unroll
        for (int hw = 0; hw < 2; hw++) {
            const int row = wr * 80 + mt * 16 + gid + hw * 8;
            int i, j; float w;
            if (row == 0)        { i = 16; j = 16; w = 1.f; }
            else if (row < 17)   { i = row - 1; j = 16; w = 0.5f; }
            else if (row < PROW) { uchar2 p = ptab[row - 17]; i = p.x; j = p.y; w = C2F; }
            else                 { i = 16; j = 16; w = 0.f; }
            ia[mt][hw] = i; ja[mt][hw] = j; wt[mt][hw] = w;
        }
    }

    float acc[5][2][4];
#pragma unroll
    for (int mt = 0; mt < 5; mt++)
#pragma unroll
        for (int nt = 0; nt < 2; nt++)
#pragma unroll
            for (int e = 0; e < 4; e++) acc[mt][nt][e] = 0.f;

    for (int kss = 0; kss < 8; kss++) {
        uint32_t b_h0[2], b_h1[2], b_l0[2], b_l1[2];
#pragma unroll
        for (int nt = 0; nt < 2; nt++) {
            const int n = wc * 16 + nt * 8 + gid;
            b_h0[nt] = vh[kss * 8 + tig][n];
            b_h1[nt] = vh[kss * 8 + tig + 4][n];
            b_l0[nt] = vl[kss * 8 + tig][n];
            b_l1[nt] = vl[kss * 8 + tig + 4][n];
        }
        const int t0 = kss * 16 + 2 * tig;
        const int t2 = t0 + 8;
#pragma unroll
        for (int mt = 0; mt < 5; mt++) {
            const int i0 = ia[mt][0], j0 = ja[mt][0];
            const int i1 = ia[mt][1], j1 = ja[mt][1];
            const float w0 = wt[mt][0], w1 = wt[mt][1];
            float f00 = w0 * ks[t0][i0] * ks[t0][j0];
            float f01 = w0 * ks[t0 + 1][i0] * ks[t0 + 1][j0];
            float f10 = w1 * ks[t0][i1] * ks[t0][j1];
            float f11 = w1 * ks[t0 + 1][i1] * ks[t0 + 1][j1];
            float f02 = w0 * ks[t2][i0] * ks[t2][j0];
            float f03 = w0 * ks[t2 + 1][i0] * ks[t2 + 1][j0];
            float f12 = w1 * ks[t2][i1] * ks[t2][j1];
            float f13 = w1 * ks[t2 + 1][i1] * ks[t2 + 1][j1];
            uint32_t ah[4], al[4];
            {
                uint32_t h00 = f2bf(f00), h01 = f2bf(f01);
                uint32_t h10 = f2bf(f10), h11 = f2bf(f11);
                uint32_t h02 = f2bf(f02), h03 = f2bf(f03);
                uint32_t h12 = f2bf(f12), h13 = f2bf(f13);
                ah[0] = h00 | (h01 << 16);
                ah[1] = h10 | (h11 << 16);
                ah[2] = h02 | (h03 << 16);
                ah[3] = h12 | (h13 << 16);
                uint32_t l00 = f2bf(f00 - bfval(h00)), l01 = f2bf(f01 - bfval(h01));
                uint32_t l10 = f2bf(f10 - bfval(h10)), l11 = f2bf(f11 - bfval(h11));
                uint32_t l02 = f2bf(f02 - bfval(h02)), l03 = f2bf(f03 - bfval(h03));
                uint32_t l12 = f2bf(f12 - bfval(h12)), l13 = f2bf(f13 - bfval(h13));
                al[0] = l00 | (l01 << 16);
                al[1] = l10 | (l11 << 16);
                al[2] = l02 | (l03 << 16);
                al[3] = l12 | (l13 << 16);
            }
#pragma unroll
            for (int nt = 0; nt < 2; nt++) {
                MMA_BF16(acc[mt][nt], ah, b_h0[nt], b_h1[nt]);
                MMA_BF16(acc[mt][nt], ah, b_l0[nt], b_l1[nt]);
                MMA_BF16(acc[mt][nt], al, b_h0[nt], b_h1[nt]);
            }
        }
    }

    // epilogue: write packed rows < PROW
    float* base = DS + (size_t)(bh * NCHUNK + ck) * SDF_P;
#pragma unroll
    for (int mt = 0; mt < 5; mt++) {
        const int ra = wr * 80 + mt * 16 + gid;
        const int rb = ra + 8;
#pragma unroll
        for (int nt = 0; nt < 2; nt++) {
            const int n = wc * 16 + nt * 8 + tig * 2;
            if (ra < PROW)
                *(float2*)&base[ra * HDIM + n] =
                    make_float2(acc[mt][nt][0], acc[mt][nt][1]);
            if (rb < PROW)
                *(float2*)&base[rb * HDIM + n] =
                    make_float2(acc[mt][nt][2], acc[mt][nt][3]);
        }
    }
}

// ---------------------------------------------------------------------------
// Kernel B: exclusive scan over packed rows (153) into g_SP.
// Off-diagonal quad rows scaled by 2 in SP; kv_state mirrored (unscaled).
// ---------------------------------------------------------------------------
__global__ void scan_kernel(const float* __restrict__ DS, float* __restrict__ SP,
                            float* __restrict__ kv_out) {
    const int bh = blockIdx.y;
    const int e4 = blockIdx.x * 256 + threadIdx.x;   // packed element / 4
    if (e4 >= PROW * 16) return;
    const int dp = e4 >> 4, f0 = (e4 & 15) * 4;

    int pi = 0, pj = 0;
    float scale = 1.f;
    if (dp >= 17) {
        p2ij(dp - 17, pi, pj);
        scale = (pi == pj) ? 1.f : 2.f;
    }

    const float* src = DS + (size_t)bh * NCHUNK * SDF_P + (size_t)dp * HDIM + f0;
    float* dst = SP + (size_t)bh * NCHUNK * SDF_P + (size_t)dp * HDIM + f0;
    float4 run = make_float4(0.f, 0.f, 0.f, 0.f);
#pragma unroll
    for (int c = 0; c < NCHUNK; c++) {
        float4 v = *(const float4*)(src + (size_t)c * SDF_P);
        *(float4*)(dst + (size_t)c * SDF_P) =
            make_float4(run.x * scale, run.y * scale, run.z * scale, run.w * scale);
        run.x += v.x; run.y += v.y; run.z += v.z; run.w += v.w;
    }
    if (kv_out) {
        float* kb = kv_out + (size_t)bh * (HDIM * FEAT);
        const float rv[4] = {run.x, run.y, run.z, run.w};
        if (dp < 17) {
#pragma unroll
            for (int ff = 0; ff < 4; ff++)
                kb[(size_t)(f0 + ff) * FEAT + dp] = rv[ff];
        } else {
            const int d1 = 17 + pi * 16 + pj, d2 = 17 + pj * 16 + pi;
#pragma unroll
            for (int ff = 0; ff < 4; ff++) {
                kb[(size_t)(f0 + ff) * FEAT + d1] = rv[ff];
                kb[(size_t)(f0 + ff) * FEAT + d2] = rv[ff];
            }
        }
    }
}

// ---------------------------------------------------------------------------
// Kernel C: inter-chunk via bf16x3 mma.sync over PACKED S (10 k-steps),
// intra-chunk causal fp32, fused RMSNorm + g.  (R12 proven)
// ---------------------------------------------------------------------------
#define AK_QS(r,c)     dyn[(r)*17+(c)]                 // q*SC, col16 = 1.0
#define AK_KC(r,c)     dyn[2176+(r)*16+(c)]            // raw k
#define AK_VC(r,c)     dyn[4224+(r)*64+(c)]            // v
#define AK_GS(c)       dyn[14720+(c)]
#define ATTN_SMEM      (14784*4)                       // 59,136 bytes
#define AK_SHW(b,rp,n) shw[(b)*576+(rp)*72+(n)]
#define AK_SLW(b,rp,n) slw[(b)*576+(rp)*72+(n)]

__device__ __forceinline__ float qfeatp(const float* dyn, const uchar2* ptab,
                                        int r, int d) {
    if (d == 0) return 1.0f;
    if (d < 17) return AK_QS(r, d - 1) * 1.1892071150027210f;   // 0.5/SC folded
    if (d < PROW) {
        const uchar2 ij = ptab[d - 17];
        return AK_QS(r, ij.x) * AK_QS(r, ij.y);
    }
    return 0.f;
}

__global__ __launch_bounds__(256, 2)
void attn_out_kernel(const float* __restrict__ Q, const float* __restrict__ Km,
                     const float* __restrict__ V, const float* __restrict__ Sprev,
                     const float* __restrict__ g, float* __restrict__ Y) {
    extern __shared__ float dyn[];
    __shared__ uchar2 ptab[136];
    uint32_t* shw = (uint32_t*)(dyn + 12416);
    uint32_t* slw = (uint32_t*)(dyn + 13568);
    const int ck = blockIdx.x;
    const int bh = blockIdx.y;
    const int b = bh >> 4, h = bh & 15;
    const int tid = threadIdx.x;
    const int warp = tid >> 5, lane = tid & 31;
    const int gid = lane >> 2, tig = lane & 3;
    const int tok0 = b * SEQ + ck * CHUNK;
    const float SC  = 0.4204482076268573f;
    const float DOT = 2.3784142300054421f;
    const float* Sp = Sprev + (size_t)(bh * NCHUNK + ck) * SDF_P;

    for (int t = tid; t < 512; t += 256) {
        int r = t >> 2, c4 = (t & 3) << 2;
        float4 qv = *(const float4*)&Q[(size_t)(tok0 + r) * QKDIM + h * FDIM + c4];
        AK_QS(r, c4 + 0) = qv.x * SC; AK_QS(r, c4 + 1) = qv.y * SC;
        AK_QS(r, c4 + 2) = qv.z * SC; AK_QS(r, c4 + 3) = qv.w * SC;
        float4 kv = *(const float4*)&Km[(size_t)(tok0 + r) * QKDIM + h * FDIM + c4];
        AK_KC(r, c4 + 0) = kv.x; AK_KC(r, c4 + 1) = kv.y;
        AK_KC(r, c4 + 2) = kv.z; AK_KC(r, c4 + 3) = kv.w;
    }
    if (tid < 128) AK_QS(tid, 16) = 1.0f;
    for (int t = tid; t < 2048; t += 256) {
        int r = t >> 4, c4 = (t & 15) << 2;
        *(float4*)&AK_VC(r, c4) =
            *(const float4*)&V[(size_t)(tok0 + r) * VDIM + h * HDIM + c4];
    }
    if (tid < 64) AK_GS(tid) = g[tid];
    if (tid < 136) {
        int i, j;
        p2ij(tid, i, j);
        ptab[tid] = make_uchar2((unsigned char)i, (unsigned char)j);
    }
    {
#pragma unroll
        for (int q = 0; q < 2; q++) {
            const int id = tid + q * 256;
            const int rp = id >> 6, n = id & 63;
            const int fr = 2 * rp;
            float v0 = Sp[fr * HDIM + n];
            float v1 = Sp[(fr + 1) * HDIM + n];
            uint32_t h0 = f2bf(v0), h1 = f2bf(v1);
            AK_SHW(0, rp, n) = h0 | (h1 << 16);
            uint32_t l0 = f2bf(v0 - bfval(h0)), l1 = f2bf(v1 - bfval(h1));
            AK_SLW(0, rp, n) = l0 | (l1 << 16);
        }
    }
    __syncthreads();

    float acc[8][4];
#pragma unroll
    for (int nt = 0; nt < 8; nt++)
#pragma unroll
        for (int e = 0; e < 4; e++) acc[nt][e] = 0.f;

    const int r0 = warp * 16 + gid;
    const int r1 = r0 + 8;
    int buf = 0;
    for (int s = 0; s < 10; s++) {
        float p00 = 0.f, p01 = 0.f, p10 = 0.f, p11 = 0.f;
        int rpA = 0, nA = 0, rpB = 0, nB = 0;
        if (s < 9) {
            const int fb = 16 * (s + 1);
            int idA = tid;           rpA = idA >> 6; nA = idA & 63;
            int idB = tid + 256;     rpB = idB >> 6; nB = idB & 63;
            int frA = fb + 2 * rpA, frB = fb + 2 * rpB;
            if (frA < PROW)     p00 = Sp[frA * HDIM + nA];
            if (frA + 1 < PROW) p01 = Sp[(frA + 1) * HDIM + nA];
            if (frB < PROW)     p10 = Sp[frB * HDIM + nB];
            if (frB + 1 < PROW) p11 = Sp[(frB + 1) * HDIM + nB];
        }
        const int da = 16 * s + 2 * tig;
        const int db = da + 8;
        float f00 = qfeatp(dyn, ptab, r0, da),  f01 = qfeatp(dyn, ptab, r0, da + 1);
        float f10 = qfeatp(dyn, ptab, r1, da),  f11 = qfeatp(dyn, ptab, r1, da + 1);
        float f02 = qfeatp(dyn, ptab, r0, db),  f03 = qfeatp(dyn, ptab, r0, db + 1);
        float f12 = qfeatp(dyn, ptab, r1, db),  f13 = qfeatp(dyn, ptab, r1, db + 1);
        uint32_t ah[4], al[4];
        {
            uint32_t h00 = f2bf(f00), h01 = f2bf(f01);
            uint32_t h10 = f2bf(f10), h11 = f2bf(f11);
            uint32_t h02 = f2bf(f02), h03 = f2bf(f03);
            uint32_t h12 = f2bf(f12), h13 = f2bf(f13);
            ah[0] = h00 | (h01 << 16);
            ah[1] = h10 | (h11 << 16);
            ah[2] = h02 | (h03 << 16);
            ah[3] = h12 | (h13 << 16);
            uint32_t l00 = f2bf(f00 - bfval(h00)), l01 = f2bf(f01 - bfval(h01));
            uint32_t l10 = f2bf(f10 - bfval(h10)), l11 = f2bf(f11 - bfval(h11));
            uint32_t l02 = f2bf(f02 - bfval(h02)), l03 = f2bf(f03 - bfval(h03));
            uint32_t l12 = f2bf(f12 - bfval(h12)), l13 = f2bf(f13 - bfval(h13));
            al[0] = l00 | (l01 << 16);
            al[1] = l10 | (l11 << 16);
            al[2] = l02 | (l03 << 16);
            al[3] = l12 | (l13 << 16);
        }
#pragma unroll
        for (int nt = 0; nt < 8; nt++) {
            const int n = nt * 8 + gid;
            uint32_t bh0 = AK_SHW(buf, tig, n);
            uint32_t bh1 = AK_SHW(buf, tig + 4, n);
            uint32_t bl0 = AK_SLW(buf, tig, n);
            uint32_t bl1 = AK_SLW(buf, tig + 4, n);
            MMA_BF16(acc[nt], ah, bh0, bh1);
            MMA_BF16(acc[nt], ah, bl0, bl1);
            MMA_BF16(acc[nt], al, bh0, bh1);
        }
        if (s < 9) {
            const int nb = buf ^ 1;
            uint32_t h0 = f2bf(p00), h1 = f2bf(p01);
            AK_SHW(nb, rpA, nA) = h0 | (h1 << 16);
            uint32_t l0 = f2bf(p00 - bfval(h0)), l1 = f2bf(p01 - bfval(h1));
            AK_SLW(nb, rpA, nA) = l0 | (l1 << 16);
            uint32_t h2 = f2bf(p10), h3 = f2bf(p11);
            AK_SHW(nb, rpB, nB) = h2 | (h3 << 16);
            uint32_t l2 = f2bf(p10 - bfval(h2)), l3 = f2bf(p11 - bfval(h3));
            AK_SLW(nb, rpB, nB) = l2 | (l3 << 16);
            __syncthreads();
            buf = nb;
        }
    }

    // intra-chunk causal fp32
    float qr0[16], qr1[16];
#pragma unroll
    for (int i = 0; i < 16; i++) {
        qr0[i] = AK_QS(r0, i);
        qr1[i] = AK_QS(r1, i);
    }
    const int mEnd = 16 * (warp + 1);
    for (int m = 0; m < mEnd; m++) {
        float s0 = 0.f, s1 = 0.f;
#pragma unroll
        for (int i = 0; i < 16; i++) {
            const float ki = AK_KC(m, i);
            s0 = fmaf(qr0[i], ki, s0);
            s1 = fmaf(qr1[i], ki, s1);
        }
        const float sd0 = s0 * DOT, sd1 = s1 * DOT;
        float a0 = fmaf(sd0, 0.25f, 1.0f);
        a0 = fmaf(sd0 * sd0, 0.03125f, a0);
        float a1 = fmaf(sd1, 0.25f, 1.0f);
        a1 = fmaf(sd1 * sd1, 0.03125f, a1);
        a0 = (m <= r0) ? a0 : 0.f;
        a1 = (m <= r1) ? a1 : 0.f;
#pragma unroll
        for (int nt = 0; nt < 8; nt++) {
            const float2 v = *(const float2*)&AK_VC(m, nt * 8 + tig * 2);
            acc[nt][0] = fmaf(a0, v.x, acc[nt][0]);
            acc[nt][1] = fmaf(a0, v.y, acc[nt][1]);
            acc[nt][2] = fmaf(a1, v.x, acc[nt][2]);
            acc[nt][3] = fmaf(a1, v.y, acc[nt][3]);
        }
    }

    // RMSNorm + gate + store
    float ss0 = 0.f, ss1 = 0.f;
#pragma unroll
    for (int nt = 0; nt < 8; nt++) {
        ss0 = fmaf(acc[nt][0], acc[nt][0], ss0);
        ss0 = fmaf(acc[nt][1], acc[nt][1], ss0);
        ss1 = fmaf(acc[nt][2], acc[nt][2], ss1);
        ss1 = fmaf(acc[nt][3], acc[nt][3], ss1);
    }
    ss0 += __shfl_xor_sync(0xffffffffu, ss0, 1);
    ss0 += __shfl_xor_sync(0xffffffffu, ss0, 2);
    ss1 += __shfl_xor_sync(0xffffffffu, ss1, 1);
    ss1 += __shfl_xor_sync(0xffffffffu, ss1, 2);
    const float rms0 = rsqrtf(ss0 * (1.0f / 64.0f) + 1e-5f);
    const float rms1 = rsqrtf(ss1 * (1.0f / 64.0f) + 1e-5f);
    float* y0 = Y + (size_t)(tok0 + r0) * VDIM + h * HDIM;
    float* y1 = Y + (size_t)(tok0 + r1) * VDIM + h * HDIM;
#pragma unroll
    for (int nt = 0; nt < 8; nt++) {
        const int c = nt * 8 + tig * 2;
        float2 o0, o1;
        o0.x = acc[nt][0] * rms0 * AK_GS(c);
        o0.y = acc[nt][1] * rms0 * AK_GS(c + 1);
        o1.x = acc[nt][2] * rms1 * AK_GS(c);
        o1.y = acc[nt][3] * rms1 * AK_GS(c + 1);
        *(float2*)&y0[c] = o0;
        *(float2*)&y1[c] = o1;
    }
}

// ---------------------------------------------------------------------------
extern "C" void kernel_launch(void* const* d_in, const int* in_sizes, int n_in,
                              void* d_out, int out_size) {
    const float* X  = (const float*)d_in[0];
    const float* Wq = (const float*)d_in[1];
    const float* Wk = (const float*)d_in[2];
    const float* Wv = (const float*)d_in[3];
    const float* Wo = (const float*)d_in[4];
    const float* g  = (const float*)d_in[5];
    float* out = (float*)d_out;

    float *Qb, *Kb, *Vb, *Yb, *Sb, *SPb;
    cudaGetSymbolAddress((void**)&Qb, g_Q);
    cudaGetSymbolAddress((void**)&Kb, g_K);
    cudaGetSymbolAddress((void**)&Vb, g_V);
    cudaGetSymbolAddress((void**)&Yb, g_Y);
    cudaGetSymbolAddress((void**)&Sb, g_DS);
    cudaGetSymbolAddress((void**)&SPb, g_SP);

    static int attn_smem_set = 0;
    if (!attn_smem_set) {
        cudaFuncSetAttribute(attn_out_kernel,
                             cudaFuncAttributeMaxDynamicSharedMemorySize,
                             ATTN_SMEM);
        attn_smem_set = 1;
    }

    // Projections (separate launches — proven fastest config)
    tgemm_nt<<<dim3(NTOK / 128, QKDIM / 128), 128>>>(X, Wq, Qb, NTOK, QKDIM, DMODEL);
    tgemm_nt<<<dim3(NTOK / 128, QKDIM / 128), 128>>>(X, Wk, Kb, NTOK, QKDIM, DMODEL);
    tgemm_nt<<<dim3(NTOK / 128, VDIM / 128),  128>>>(X, Wv, Vb, NTOK, VDIM,  DMODEL);

    // Chunked linear attention (packed symmetric states, MMA state)
    float* kv_out = (out_size >= OUT_ELEMS + KV_ELEMS) ? (out + OUT_ELEMS) : nullptr;
    state_mma_kernel<<<dim3(NCHUNK, BATCH * NHEADS), 256>>>(Kb, Vb, Sb);
    scan_kernel<<<dim3((PROW * 16 + 255) / 256, BATCH * NHEADS), 256>>>(
        Sb, SPb, kv_out);
    attn_out_kernel<<<dim3(NCHUNK, BATCH * NHEADS), 256, ATTN_SMEM>>>(
        Qb, Kb, Vb, SPb, g, Yb);

    // Output projection
    tgemm_nt<<<dim3(NTOK / 128, DMODEL / 128), 128>>>(Yb, Wo, out, NTOK, DMODEL, DMODEL);
}

// round 14
// speedup vs baseline: 2.1024x; 1.0253x over previous
#include <cuda_runtime.h>
#include <cuda_bf16.h>
#include <math.h>
#include <stdint.h>

// Problem constants (fixed shapes from setup_inputs)
#define BATCH 4
#define SEQ   2048
#define DMODEL 1024
#define NHEADS 16
#define FDIM  16
#define HDIM  64
#define NTOK  (BATCH*SEQ)          // 8192
#define QKDIM (NHEADS*FDIM)        // 256
#define VDIM  (NHEADS*HDIM)        // 1024
#define FEAT  273                  // 1 + 16 + 256
#define NCHUNK 16                  // 2048 / 128
#define CHUNK 128
#define KV_ELEMS (BATCH*NHEADS*HDIM*FEAT)   // 1,118,208
#define OUT_ELEMS (NTOK*DMODEL)             // 8,388,608
#define PROW 153                   // 1 + 16 + 136 packed symmetric rows
#define SDF_P (PROW*HDIM)          // 9792
#define C2F 0.17677669529663687f   // 1/(4*sqrt(2))

// Scratch (device globals; no runtime allocation)
__device__ float g_Q[NTOK*QKDIM];
__device__ float g_K[NTOK*QKDIM];
__device__ float g_V[NTOK*VDIM];
__device__ float g_Y[NTOK*VDIM];
__device__ float g_DS[64*NCHUNK*SDF_P];   // packed chunk states (state out)
__device__ float g_SP[64*NCHUNK*SDF_P];   // packed exclusive-prefix states

__device__ __forceinline__ uint32_t f2tf32(float x) {
    uint32_t u;
    asm("cvt.rna.tf32.f32 %0, %1;" : "=r"(u) : "f"(x));
    return u;
}
// HW bf16x2 pack (RNE): lo -> bits[15:0], hi -> bits[31:16]
__device__ __forceinline__ uint32_t pack_bf(float lo, float hi) {
    uint32_t r;
    asm("cvt.rn.bf16x2.f32 %0, %1, %2;" : "=r"(r) : "f"(hi), "f"(lo));
    return r;
}
// unpack bf16x2 halves back to float (exact)
__device__ __forceinline__ float2 unpack_bf(uint32_t p) {
    return make_float2(__uint_as_float(p << 16),
                       __uint_as_float(p & 0xFFFF0000u));
}
// pack pair + residual pair in one helper: h = pack(lo,hi), l = pack(residuals)
__device__ __forceinline__ void split_bf(float a, float b,
                                         uint32_t& h, uint32_t& l) {
    h = pack_bf(a, b);
    float2 hv = unpack_bf(h);
    l = pack_bf(a - hv.x, b - hv.y);
}
// packed index p -> (i,j), j<=i  (sqrt trick + correction)
__device__ __forceinline__ void p2ij(int p, int& i, int& j) {
    i = (int)((sqrtf(8.f * p + 1.f) - 1.f) * 0.5f);
    if ((i + 1) * (i + 2) / 2 <= p) i++;
    if (i * (i + 1) / 2 > p) i--;
    j = p - i * (i + 1) / 2;
}

#define MMA_BF16(acc_, a_, b0_, b1_)                                           \
    asm volatile(                                                              \
        "mma.sync.aligned.m16n8k16.row.col.f32.bf16.bf16.f32 "                 \
        "{%0,%1,%2,%3}, {%4,%5,%6,%7}, {%8,%9}, {%0,%1,%2,%3};"                \
        : "+f"((acc_)[0]), "+f"((acc_)[1]), "+f"((acc_)[2]), "+f"((acc_)[3])   \
        : "r"((a_)[0]), "r"((a_)[1]), "r"((a_)[2]), "r"((a_)[3]),              \
          "r"(b0_), "r"(b1_))

// ---------------------------------------------------------------------------
// tf32 GEMM (R4 design, proven): 128x128 block, 4 warps of 64x64, BK=16,
// double-buffered smem [k][row] pad 132, one sync per K-tile.
// ---------------------------------------------------------------------------
struct GSmem {
    uint32_t As[2][16][132];
    uint32_t Bs[2][16][132];
};

__device__ __forceinline__ void gemm_tile(
    const float* __restrict__ A, const float* __restrict__ B,
    float* __restrict__ C, int N, int K, int bm, int bn, GSmem& sm) {
    const int tid  = threadIdx.x;
    const int warp = tid >> 5, lane = tid & 31;
    const int gid  = lane >> 2, tig = lane & 3;
    const int wm = (warp >> 1) * 64, wn = (warp & 1) * 64;

    const int lr = tid >> 2;
    const int kc = (tid & 3) << 2;
    const float* Ap = A + (size_t)(bm + lr) * K + kc;
    const float* Bp = B + (size_t)(bn + lr) * K + kc;
    const size_t row32 = (size_t)32 * K;

    float acc[4][8][4];
#pragma unroll
    for (int mt = 0; mt < 4; mt++)
#pragma unroll
        for (int nt = 0; nt < 8; nt++)
#pragma unroll
            for (int e = 0; e < 4; e++) acc[mt][nt][e] = 0.f;

    float4 ar[4], br[4];
#pragma unroll
    for (int p = 0; p < 4; p++) {
        ar[p] = *(const float4*)(Ap + p * row32);
        br[p] = *(const float4*)(Bp + p * row32);
    }
#pragma unroll
    for (int p = 0; p < 4; p++) {
        sm.As[0][kc + 0][lr + p * 32] = f2tf32(ar[p].x);
        sm.As[0][kc + 1][lr + p * 32] = f2tf32(ar[p].y);
        sm.As[0][kc + 2][lr + p * 32] = f2tf32(ar[p].z);
        sm.As[0][kc + 3][lr + p * 32] = f2tf32(ar[p].w);
        sm.Bs[0][kc + 0][lr + p * 32] = f2tf32(br[p].x);
        sm.Bs[0][kc + 1][lr + p * 32] = f2tf32(br[p].y);
        sm.Bs[0][kc + 2][lr + p * 32] = f2tf32(br[p].z);
        sm.Bs[0][kc + 3][lr + p * 32] = f2tf32(br[p].w);
    }
    __syncthreads();

    int cur = 0;
    for (int k0 = 0; k0 < K; k0 += 16) {
        const bool more = (k0 + 16 < K);
        if (more) {
#pragma unroll
            for (int p = 0; p < 4; p++) {
                ar[p] = *(const float4*)(Ap + k0 + 16 + p * row32);
                br[p] = *(const float4*)(Bp + k0 + 16 + p * row32);
            }
        }

#pragma unroll
        for (int ks = 0; ks < 2; ks++) {
            const int kk = ks * 8;
            uint32_t af[4][4], bf[8][2];
#pragma unroll
            for (int mt = 0; mt < 4; mt++) {
                const int m = wm + mt * 16 + gid;
                af[mt][0] = sm.As[cur][kk + tig][m];
                af[mt][1] = sm.As[cur][kk + tig][m + 8];
                af[mt][2] = sm.As[cur][kk + tig + 4][m];
                af[mt][3] = sm.As[cur][kk + tig + 4][m + 8];
            }
#pragma unroll
            for (int nt = 0; nt < 8; nt++) {
                const int n = wn + nt * 8 + gid;
                bf[nt][0] = sm.Bs[cur][kk + tig][n];
                bf[nt][1] = sm.Bs[cur][kk + tig + 4][n];
            }
#pragma unroll
            for (int mt = 0; mt < 4; mt++)
#pragma unroll
                for (int nt = 0; nt < 8; nt++) {
                    asm volatile(
                        "mma.sync.aligned.m16n8k8.row.col.f32.tf32.tf32.f32 "
                        "{%0,%1,%2,%3}, {%4,%5,%6,%7}, {%8,%9}, {%0,%1,%2,%3};"
                        : "+f"(acc[mt][nt][0]), "+f"(acc[mt][nt][1]),
                          "+f"(acc[mt][nt][2]), "+f"(acc[mt][nt][3])
                        : "r"(af[mt][0]), "r"(af[mt][1]),
                          "r"(af[mt][2]), "r"(af[mt][3]),
                          "r"(bf[nt][0]), "r"(bf[nt][1]));
                }
        }

        if (more) {
            const int nxt = cur ^ 1;
#pragma unroll
            for (int p = 0; p < 4; p++) {
                sm.As[nxt][kc + 0][lr + p * 32] = f2tf32(ar[p].x);
                sm.As[nxt][kc + 1][lr + p * 32] = f2tf32(ar[p].y);
                sm.As[nxt][kc + 2][lr + p * 32] = f2tf32(ar[p].z);
                sm.As[nxt][kc + 3][lr + p * 32] = f2tf32(ar[p].w);
                sm.Bs[nxt][kc + 0][lr + p * 32] = f2tf32(br[p].x);
                sm.Bs[nxt][kc + 1][lr + p * 32] = f2tf32(br[p].y);
                sm.Bs[nxt][kc + 2][lr + p * 32] = f2tf32(br[p].z);
                sm.Bs[nxt][kc + 3][lr + p * 32] = f2tf32(br[p].w);
            }
            __syncthreads();
        }
        cur ^= 1;
    }

#pragma unroll
    for (int mt = 0; mt < 4; mt++) {
        const int r0 = bm + wm + mt * 16 + gid;
#pragma unroll
        for (int nt = 0; nt < 8; nt++) {
            const int cc = bn + wn + nt * 8 + tig * 2;
            *(float2*)&C[(size_t)r0 * N + cc] =
                make_float2(acc[mt][nt][0], acc[mt][nt][1]);
            *(float2*)&C[(size_t)(r0 + 8) * N + cc] =
                make_float2(acc[mt][nt][2], acc[mt][nt][3]);
        }
    }
}

__global__ __launch_bounds__(128)
void tgemm_nt(const float* __restrict__ A, const float* __restrict__ B,
              float* __restrict__ C, int M, int N, int K) {
    __shared__ GSmem sm;
    gemm_tile(A, B, C, N, K, blockIdx.x * 128, blockIdx.y * 128, sm);
}

// ---------------------------------------------------------------------------
// Kernel A: per-chunk state increment via bf16x3 MMA (HW cvt packing).
// DS_packed[160pad x 64] = kf_features[160 x 128] @ v[128 x 64].
// ---------------------------------------------------------------------------
__global__ __launch_bounds__(256, 2)
void state_mma_kernel(const float* __restrict__ Km, const float* __restrict__ V,
                      float* __restrict__ DS) {
    __shared__ float ks[128][17];       // raw k, col16 = 1.0
    __shared__ uint32_t vh[64][72];     // packed bf16 token-pairs (hi)
    __shared__ uint32_t vl[64][72];     // packed bf16 token-pairs (lo)
    __shared__ uchar2 ptab[136];
    const int ck = blockIdx.x, bh = blockIdx.y;
    const int b = bh >> 4, h = bh & 15;
    const int tid = threadIdx.x;
    const int warp = tid >> 5, lane = tid & 31;
    const int gid = lane >> 2, tig = lane & 3;
    const int wr = warp >> 2, wc = warp & 3;
    const int tokb = b * SEQ + ck * CHUNK;

    // stage K
    for (int t = tid; t < 512; t += 256) {
        int r = t >> 2, c4 = (t & 3) << 2;
        float4 kv = *(const float4*)&Km[(size_t)(tokb + r) * QKDIM + h * FDIM + c4];
        ks[r][c4 + 0] = kv.x; ks[r][c4 + 1] = kv.y;
        ks[r][c4 + 2] = kv.z; ks[r][c4 + 3] = kv.w;
    }
    if (tid < 128) ks[tid][16] = 1.0f;
    // stage V as packed bf16 token-pairs (hi/lo) — HW cvt
    for (int t = tid; t < 1024; t += 256) {
        int kp = t >> 4, c4 = (t & 15) << 2;
        float4 a = *(const float4*)&V[(size_t)(tokb + 2 * kp) * VDIM + h * HDIM + c4];
        float4 bb = *(const float4*)&V[(size_t)(tokb + 2 * kp + 1) * VDIM + h * HDIM + c4];
        const float av[4] = {a.x, a.y, a.z, a.w};
        const float bv[4] = {bb.x, bb.y, bb.z, bb.w};
#pragma unroll
        for (int e = 0; e < 4; e++) {
            uint32_t hp, lp;
            split_bf(av[e], bv[e], hp, lp);
            vh[kp][c4 + e] = hp;
            vl[kp][c4 + e] = lp;
        }
    }
    if (tid < 136) {
        int i, j;
        p2ij(tid, i, j);
        ptab[tid] = make_uchar2((unsigned char)i, (unsigned char)j);
    }
    __syncthreads();

    // per-thread feature params (i, j, weight) for the 10 rows it owns
    int ia[5][2], ja[5][2];
    float wt[5][2];
#pragma unroll
    for (int mt = 0; mt < 5; mt++) {
#pragma unroll
        for (int hw = 0; hw < 2; hw++) {
            const int row = wr * 80 + mt * 16 + gid + hw * 8;
            int i, j; float w;
            if (row == 0)        { i = 16; j = 16; w = 1.f; }
            else if (row < 17)   { i = row - 1; j = 16; w = 0.5f; }
            else if (row < PROW) { uchar2 p = ptab[row - 17]; i = p.x; j = p.y; w = C2F; }
            else                 { i = 16; j = 16; w = 0.f; }
            ia[mt][hw] = i; ja[mt][hw] = j; wt[mt][hw] = w;
        }
    }

    float acc[5][2][4];
#pragma unroll
    for (int mt = 0; mt < 5; mt++)
#pragma unroll
        for (int nt = 0; nt < 2; nt++)
#pragma unroll
            for (int e = 0; e < 4; e++) acc[mt][nt][e] = 0.f;

    for (int kss = 0; kss < 8; kss++) {
        uint32_t b_h0[2], b_h1[2], b_l0[2], b_l1[2];
#pragma unroll
        for (int nt = 0; nt < 2; nt++) {
            const int n = wc * 16 + nt * 8 + gid;
            b_h0[nt] = vh[kss * 8 + tig][n];
            b_h1[nt] = vh[kss * 8 + tig + 4][n];
            b_l0[nt] = vl[kss * 8 + tig][n];
            b_l1[nt] = vl[kss * 8 + tig + 4][n];
        }
        const int t0 = kss * 16 + 2 * tig;
        const int t2 = t0 + 8;
#pragma unroll
        for (int mt = 0; mt < 5; mt++) {
            const int i0 = ia[mt][0], j0 = ja[mt][0];
            const int i1 = ia[mt][1], j1 = ja[mt][1];
            const float w0 = wt[mt][0], w1 = wt[mt][1];
            float f00 = w0 * ks[t0][i0] * ks[t0][j0];
            float f01 = w0 * ks[t0 + 1][i0] * ks[t0 + 1][j0];
            float f10 = w1 * ks[t0][i1] * ks[t0][j1];
            float f11 = w1 * ks[t0 + 1][i1] * ks[t0 + 1][j1];
            float f02 = w0 * ks[t2][i0] * ks[t2][j0];
            float f03 = w0 * ks[t2 + 1][i0] * ks[t2 + 1][j0];
            float f12 = w1 * ks[t2][i1] * ks[t2][j1];
            float f13 = w1 * ks[t2 + 1][i1] * ks[t2 + 1][j1];
            uint32_t ah[4], al[4];
            split_bf(f00, f01, ah[0], al[0]);
            split_bf(f10, f11, ah[1], al[1]);
            split_bf(f02, f03, ah[2], al[2]);
            split_bf(f12, f13, ah[3], al[3]);
#pragma unroll
            for (int nt = 0; nt < 2; nt++) {
                MMA_BF16(acc[mt][nt], ah, b_h0[nt], b_h1[nt]);
                MMA_BF16(acc[mt][nt], ah, b_l0[nt], b_l1[nt]);
                MMA_BF16(acc[mt][nt], al, b_h0[nt], b_h1[nt]);
            }
        }
    }

    // epilogue: write packed rows < PROW
    float* base = DS + (size_t)(bh * NCHUNK + ck) * SDF_P;
#pragma unroll
    for (int mt = 0; mt < 5; mt++) {
        const int ra = wr * 80 + mt * 16 + gid;
        const int rb = ra + 8;
#pragma unroll
        for (int nt = 0; nt < 2; nt++) {
            const int n = wc * 16 + nt * 8 + tig * 2;
            if (ra < PROW)
                *(float2*)&base[ra * HDIM + n] =
                    make_float2(acc[mt][nt][0], acc[mt][nt][1]);
            if (rb < PROW)
                *(float2*)&base[rb * HDIM + n] =
                    make_float2(acc[mt][nt][2], acc[mt][nt][3]);
        }
    }
}

// ---------------------------------------------------------------------------
// Kernel B: exclusive scan over packed rows (153) into g_SP.
// ---------------------------------------------------------------------------
__global__ void scan_kernel(const float* __restrict__ DS, float* __restrict__ SP,
                            float* __restrict__ kv_out) {
    const int bh = blockIdx.y;
    const int e4 = blockIdx.x * 256 + threadIdx.x;   // packed element / 4
    if (e4 >= PROW * 16) return;
    const int dp = e4 >> 4, f0 = (e4 & 15) * 4;

    int pi = 0, pj = 0;
    float scale = 1.f;
    if (dp >= 17) {
        p2ij(dp - 17, pi, pj);
        scale = (pi == pj) ? 1.f : 2.f;
    }

    const float* src = DS + (size_t)bh * NCHUNK * SDF_P + (size_t)dp * HDIM + f0;
    float* dst = SP + (size_t)bh * NCHUNK * SDF_P + (size_t)dp * HDIM + f0;
    float4 run = make_float4(0.f, 0.f, 0.f, 0.f);
#pragma unroll
    for (int c = 0; c < NCHUNK; c++) {
        float4 v = *(const float4*)(src + (size_t)c * SDF_P);
        *(float4*)(dst + (size_t)c * SDF_P) =
            make_float4(run.x * scale, run.y * scale, run.z * scale, run.w * scale);
        run.x += v.x; run.y += v.y; run.z += v.z; run.w += v.w;
    }
    if (kv_out) {
        float* kb = kv_out + (size_t)bh * (HDIM * FEAT);
        const float rv[4] = {run.x, run.y, run.z, run.w};
        if (dp < 17) {
#pragma unroll
            for (int ff = 0; ff < 4; ff++)
                kb[(size_t)(f0 + ff) * FEAT + dp] = rv[ff];
        } else {
            const int d1 = 17 + pi * 16 + pj, d2 = 17 + pj * 16 + pi;
#pragma unroll
            for (int ff = 0; ff < 4; ff++) {
                kb[(size_t)(f0 + ff) * FEAT + d1] = rv[ff];
                kb[(size_t)(f0 + ff) * FEAT + d2] = rv[ff];
            }
        }
    }
}

// ---------------------------------------------------------------------------
// Kernel C: inter-chunk via bf16x3 mma.sync over PACKED S (10 k-steps),
// intra-chunk causal fp32, fused RMSNorm + g.  (HW cvt packing)
// ---------------------------------------------------------------------------
#define AK_QS(r,c)     dyn[(r)*17+(c)]                 // q*SC, col16 = 1.0
#define AK_KC(r,c)     dyn[2176+(r)*16+(c)]            // raw k
#define AK_VC(r,c)     dyn[4224+(r)*64+(c)]            // v
#define AK_GS(c)       dyn[14720+(c)]
#define ATTN_SMEM      (14784*4)                       // 59,136 bytes
#define AK_SHW(b,rp,n) shw[(b)*576+(rp)*72+(n)]
#define AK_SLW(b,rp,n) slw[(b)*576+(rp)*72+(n)]

__device__ __forceinline__ float qfeatp(const float* dyn, const uchar2* ptab,
                                        int r, int d) {
    if (d == 0) return 1.0f;
    if (d < 17) return AK_QS(r, d - 1) * 1.1892071150027210f;   // 0.5/SC folded
    if (d < PROW) {
        const uchar2 ij = ptab[d - 17];
        return AK_QS(r, ij.x) * AK_QS(r, ij.y);
    }
    return 0.f;
}

__global__ __launch_bounds__(256, 2)
void attn_out_kernel(const float* __restrict__ Q, const float* __restrict__ Km,
                     const float* __restrict__ V, const float* __restrict__ Sprev,
                     const float* __restrict__ g, float* __restrict__ Y) {
    extern __shared__ float dyn[];
    __shared__ uchar2 ptab[136];
    uint32_t* shw = (uint32_t*)(dyn + 12416);
    uint32_t* slw = (uint32_t*)(dyn + 13568);
    const int ck = blockIdx.x;
    const int bh = blockIdx.y;
    const int b = bh >> 4, h = bh & 15;
    const int tid = threadIdx.x;
    const int warp = tid >> 5, lane = tid & 31;
    const int gid = lane >> 2, tig = lane & 3;
    const int tok0 = b * SEQ + ck * CHUNK;
    const float SC  = 0.4204482076268573f;
    const float DOT = 2.3784142300054421f;
    const float* Sp = Sprev + (size_t)(bh * NCHUNK + ck) * SDF_P;

    for (int t = tid; t < 512; t += 256) {
        int r = t >> 2, c4 = (t & 3) << 2;
        float4 qv = *(const float4*)&Q[(size_t)(tok0 + r) * QKDIM + h * FDIM + c4];
        AK_QS(r, c4 + 0) = qv.x * SC; AK_QS(r, c4 + 1) = qv.y * SC;
        AK_QS(r, c4 + 2) = qv.z * SC; AK_QS(r, c4 + 3) = qv.w * SC;
        float4 kv = *(const float4*)&Km[(size_t)(tok0 + r) * QKDIM + h * FDIM + c4];
        AK_KC(r, c4 + 0) = kv.x; AK_KC(r, c4 + 1) = kv.y;
        AK_KC(r, c4 + 2) = kv.z; AK_KC(r, c4 + 3) = kv.w;
    }
    if (tid < 128) AK_QS(tid, 16) = 1.0f;
    for (int t = tid; t < 2048; t += 256) {
        int r = t >> 4, c4 = (t & 15) << 2;
        *(float4*)&AK_VC(r, c4) =
            *(const float4*)&V[(size_t)(tok0 + r) * VDIM + h * HDIM + c4];
    }
    if (tid < 64) AK_GS(tid) = g[tid];
    if (tid < 136) {
        int i, j;
        p2ij(tid, i, j);
        ptab[tid] = make_uchar2((unsigned char)i, (unsigned char)j);
    }
    {
#pragma unroll
        for (int q = 0; q < 2; q++) {
            const int id = tid + q * 256;
            const int rp = id >> 6, n = id & 63;
            const int fr = 2 * rp;
            float v0 = Sp[fr * HDIM + n];
            float v1 = Sp[(fr + 1) * HDIM + n];
            uint32_t hp, lp;
            split_bf(v0, v1, hp, lp);
            AK_SHW(0, rp, n) = hp;
            AK_SLW(0, rp, n) = lp;
        }
    }
    __syncthreads();

    float acc[8][4];
#pragma unroll
    for (int nt = 0; nt < 8; nt++)
#pragma unroll
        for (int e = 0; e < 4; e++) acc[nt][e] = 0.f;

    const int r0 = warp * 16 + gid;
    const int r1 = r0 + 8;
    int buf = 0;
    for (int s = 0; s < 10; s++) {
        float p00 = 0.f, p01 = 0.f, p10 = 0.f, p11 = 0.f;
        int rpA = 0, nA = 0, rpB = 0, nB = 0;
        if (s < 9) {
            const int fb = 16 * (s + 1);
            int idA = tid;           rpA = idA >> 6; nA = idA & 63;
            int idB = tid + 256;     rpB = idB >> 6; nB = idB & 63;
            int frA = fb + 2 * rpA, frB = fb + 2 * rpB;
            if (frA < PROW)     p00 = Sp[frA * HDIM + nA];
            if (frA + 1 < PROW) p01 = Sp[(frA + 1) * HDIM + nA];
            if (frB < PROW)     p10 = Sp[frB * HDIM + nB];
            if (frB + 1 < PROW) p11 = Sp[(frB + 1) * HDIM + nB];
        }
        const int da = 16 * s + 2 * tig;
        const int db = da + 8;
        float f00 = qfeatp(dyn, ptab, r0, da),  f01 = qfeatp(dyn, ptab, r0, da + 1);
        float f10 = qfeatp(dyn, ptab, r1, da),  f11 = qfeatp(dyn, ptab, r1, da + 1);
        float f02 = qfeatp(dyn, ptab, r0, db),  f03 = qfeatp(dyn, ptab, r0, db + 1);
        float f12 = qfeatp(dyn, ptab, r1, db),  f13 = qfeatp(dyn, ptab, r1, db + 1);
        uint32_t ah[4], al[4];
        split_bf(f00, f01, ah[0], al[0]);
        split_bf(f10, f11, ah[1], al[1]);
        split_bf(f02, f03, ah[2], al[2]);
        split_bf(f12, f13, ah[3], al[3]);
#pragma unroll
        for (int nt = 0; nt < 8; nt++) {
            const int n = nt * 8 + gid;
            uint32_t bh0 = AK_SHW(buf, tig, n);
            uint32_t bh1 = AK_SHW(buf, tig + 4, n);
            uint32_t bl0 = AK_SLW(buf, tig, n);
            uint32_t bl1 = AK_SLW(buf, tig + 4, n);
            MMA_BF16(acc[nt], ah, bh0, bh1);
            MMA_BF16(acc[nt], ah, bl0, bl1);
            MMA_BF16(acc[nt], al, bh0, bh1);
        }
        if (s < 9) {
            const int nb = buf ^ 1;
            uint32_t hp, lp;
            split_bf(p00, p01, hp, lp);
            AK_SHW(nb, rpA, nA) = hp;
            AK_SLW(nb, rpA, nA) = lp;
            split_bf(p10, p11, hp, lp);
            AK_SHW(nb, rpB, nB) = hp;
            AK_SLW(nb, rpB, nB) = lp;
            __syncthreads();
            buf = nb;
        }
    }

    // intra-chunk causal fp32
    float qr0[16], qr1[16];
#pragma unroll
    for (int i = 0; i < 16; i++) {
        qr0[i] = AK_QS(r0, i);
        qr1[i] = AK_QS(r1, i);
    }
    const int mEnd = 16 * (warp + 1);
    for (int m = 0; m < mEnd; m++) {
        float s0 = 0.f, s1 = 0.f;
#pragma unroll
        for (int i = 0; i < 16; i++) {
            const float ki = AK_KC(m, i);
            s0 = fmaf(qr0[i], ki, s0);
            s1 = fmaf(qr1[i], ki, s1);
        }
        const float sd0 = s0 * DOT, sd1 = s1 * DOT;
        float a0 = fmaf(sd0, 0.25f, 1.0f);
        a0 = fmaf(sd0 * sd0, 0.03125f, a0);
        float a1 = fmaf(sd1, 0.25f, 1.0f);
        a1 = fmaf(sd1 * sd1, 0.03125f, a1);
        a0 = (m <= r0) ? a0 : 0.f;
        a1 = (m <= r1) ? a1 : 0.f;
#pragma unroll
        for (int nt = 0; nt < 8; nt++) {
            const float2 v = *(const float2*)&AK_VC(m, nt * 8 + tig * 2);
            acc[nt][0] = fmaf(a0, v.x, acc[nt][0]);
            acc[nt][1] = fmaf(a0, v.y, acc[nt][1]);
            acc[nt][2] = fmaf(a1, v.x, acc[nt][2]);
            acc[nt][3] = fmaf(a1, v.y, acc[nt][3]);
        }
    }

    // RMSNorm + gate + store
    float ss0 = 0.f, ss1 = 0.f;
#pragma unroll
    for (int nt = 0; nt < 8; nt++) {
        ss0 = fmaf(acc[nt][0], acc[nt][0], ss0);
        ss0 = fmaf(acc[nt][1], acc[nt][1], ss0);
        ss1 = fmaf(acc[nt][2], acc[nt][2], ss1);
        ss1 = fmaf(acc[nt][3], acc[nt][3], ss1);
    }
    ss0 += __shfl_xor_sync(0xffffffffu, ss0, 1);
    ss0 += __shfl_xor_sync(0xffffffffu, ss0, 2);
    ss1 += __shfl_xor_sync(0xffffffffu, ss1, 1);
    ss1 += __shfl_xor_sync(0xffffffffu, ss1, 2);
    const float rms0 = rsqrtf(ss0 * (1.0f / 64.0f) + 1e-5f);
    const float rms1 = rsqrtf(ss1 * (1.0f / 64.0f) + 1e-5f);
    float* y0 = Y + (size_t)(tok0 + r0) * VDIM + h * HDIM;
    float* y1 = Y + (size_t)(tok0 + r1) * VDIM + h * HDIM;
#pragma unroll
    for (int nt = 0; nt < 8; nt++) {
        const int c = nt * 8 + tig * 2;
        float2 o0, o1;
        o0.x = acc[nt][0] * rms0 * AK_GS(c);
        o0.y = acc[nt][1] * rms0 * AK_GS(c + 1);
        o1.x = acc[nt][2] * rms1 * AK_GS(c);
        o1.y = acc[nt][3] * rms1 * AK_GS(c + 1);
        *(float2*)&y0[c] = o0;
        *(float2*)&y1[c] = o1;
    }
}

// ---------------------------------------------------------------------------
extern "C" void kernel_launch(void* const* d_in, const int* in_sizes, int n_in,
                              void* d_out, int out_size) {
    const float* X  = (const float*)d_in[0];
    const float* Wq = (const float*)d_in[1];
    const float* Wk = (const float*)d_in[2];
    const float* Wv = (const float*)d_in[3];
    const float* Wo = (const float*)d_in[4];
    const float* g  = (const float*)d_in[5];
    float* out = (float*)d_out;

    float *Qb, *Kb, *Vb, *Yb, *Sb, *SPb;
    cudaGetSymbolAddress((void**)&Qb, g_Q);
    cudaGetSymbolAddress((void**)&Kb, g_K);
    cudaGetSymbolAddress((void**)&Vb, g_V);
    cudaGetSymbolAddress((void**)&Yb, g_Y);
    cudaGetSymbolAddress((void**)&Sb, g_DS);
    cudaGetSymbolAddress((void**)&SPb, g_SP);

    static int attn_smem_set = 0;
    if (!attn_smem_set) {
        cudaFuncSetAttribute(attn_out_kernel,
                             cudaFuncAttributeMaxDynamicSharedMemorySize,
                             ATTN_SMEM);
        attn_smem_set = 1;
    }

    // Projections (separate launches — proven fastest config)
    tgemm_nt<<<dim3(NTOK / 128, QKDIM / 128), 128>>>(X, Wq, Qb, NTOK, QKDIM, DMODEL);
    tgemm_nt<<<dim3(NTOK / 128, QKDIM / 128), 128>>>(X, Wk, Kb, NTOK, QKDIM, DMODEL);
    tgemm_nt<<<dim3(NTOK / 128, VDIM / 128),  128>>>(X, Wv, Vb, NTOK, VDIM,  DMODEL);

    // Chunked linear attention (packed symmetric states, MMA state)
    float* kv_out = (out_size >= OUT_ELEMS + KV_ELEMS) ? (out + OUT_ELEMS) : nullptr;
    state_mma_kernel<<<dim3(NCHUNK, BATCH * NHEADS), 256>>>(Kb, Vb, Sb);
    scan_kernel<<<dim3((PROW * 16 + 255) / 256, BATCH * NHEADS), 256>>>(
        Sb, SPb, kv_out);
    attn_out_kernel<<<dim3(NCHUNK, BATCH * NHEADS), 256, ATTN_SMEM>>>(
        Qb, Kb, Vb, SPb, g, Yb);

    // Output projection
    tgemm_nt<<<dim3(NTOK / 128, DMODEL / 128), 128>>>(Yb, Wo, out, NTOK, DMODEL, DMODEL);
}

// round 15
// speedup vs baseline: 2.3365x; 1.1113x over previous
#include <cuda_runtime.h>
#include <cuda_bf16.h>
#include <math.h>
#include <stdint.h>

// Problem constants (fixed shapes from setup_inputs)
#define BATCH 4
#define SEQ   2048
#define DMODEL 1024
#define NHEADS 16
#define FDIM  16
#define HDIM  64
#define NTOK  (BATCH*SEQ)          // 8192
#define QKDIM (NHEADS*FDIM)        // 256
#define VDIM  (NHEADS*HDIM)        // 1024
#define FEAT  273                  // 1 + 16 + 256
#define NCHUNK 16                  // 2048 / 128
#define CHUNK 128
#define KV_ELEMS (BATCH*NHEADS*HDIM*FEAT)   // 1,118,208
#define OUT_ELEMS (NTOK*DMODEL)             // 8,388,608
#define PROW 153                   // 1 + 16 + 136 packed symmetric rows
#define SDF_P (PROW*HDIM)          // 9792
#define C2F 0.17677669529663687f   // 1/(4*sqrt(2))

// Scratch (device globals; no runtime allocation)
__device__ float g_Q[NTOK*QKDIM];
__device__ float g_K[NTOK*QKDIM];
__device__ float g_V[NTOK*VDIM];
__device__ float g_Y[NTOK*VDIM];
__device__ float g_DS[64*NCHUNK*SDF_P];   // packed chunk states (state out)
__device__ float g_SP[64*NCHUNK*SDF_P];   // packed exclusive-prefix states

__device__ __forceinline__ uint32_t f2tf32(float x) {
    uint32_t u;
    asm("cvt.rna.tf32.f32 %0, %1;" : "=r"(u) : "f"(x));
    return u;
}
// HW bf16x2 pack (RNE): a -> bits[15:0], b -> bits[31:16]
__device__ __forceinline__ uint32_t pack_bf(float a, float b) {
    uint32_t r;
    asm("cvt.rn.bf16x2.f32 %0, %1, %2;" : "=r"(r) : "f"(b), "f"(a));
    return r;
}
__device__ __forceinline__ float2 unpack_bf(uint32_t p) {
    return make_float2(__uint_as_float(p << 16),
                       __uint_as_float(p & 0xFFFF0000u));
}
__device__ __forceinline__ void split_bf(float a, float b,
                                         uint32_t& h, uint32_t& l) {
    h = pack_bf(a, b);
    float2 hv = unpack_bf(h);
    l = pack_bf(a - hv.x, b - hv.y);
}
// packed index p -> (i,j), j<=i  (sqrt trick + correction)
__device__ __forceinline__ void p2ij(int p, int& i, int& j) {
    i = (int)((sqrtf(8.f * p + 1.f) - 1.f) * 0.5f);
    if ((i + 1) * (i + 2) / 2 <= p) i++;
    if (i * (i + 1) / 2 > p) i--;
    j = p - i * (i + 1) / 2;
}

#define MMA_BF16(acc_, a_, b0_, b1_)                                           \
    asm volatile(                                                              \
        "mma.sync.aligned.m16n8k16.row.col.f32.bf16.bf16.f32 "                 \
        "{%0,%1,%2,%3}, {%4,%5,%6,%7}, {%8,%9}, {%0,%1,%2,%3};"                \
        : "+f"((acc_)[0]), "+f"((acc_)[1]), "+f"((acc_)[2]), "+f"((acc_)[3])   \
        : "r"((a_)[0]), "r"((a_)[1]), "r"((a_)[2]), "r"((a_)[3]),              \
          "r"(b0_), "r"(b1_))

// ---------------------------------------------------------------------------
// tf32 GEMM (R4 design, proven)
// ---------------------------------------------------------------------------
struct GSmem {
    uint32_t As[2][16][132];
    uint32_t Bs[2][16][132];
};

__device__ __forceinline__ void gemm_tile(
    const float* __restrict__ A, const float* __restrict__ B,
    float* __restrict__ C, int N, int K, int bm, int bn, GSmem& sm) {
    const int tid  = threadIdx.x;
    const int warp = tid >> 5, lane = tid & 31;
    const int gid  = lane >> 2, tig = lane & 3;
    const int wm = (warp >> 1) * 64, wn = (warp & 1) * 64;

    const int lr = tid >> 2;
    const int kc = (tid & 3) << 2;
    const float* Ap = A + (size_t)(bm + lr) * K + kc;
    const float* Bp = B + (size_t)(bn + lr) * K + kc;
    const size_t row32 = (size_t)32 * K;

    float acc[4][8][4];
#pragma unroll
    for (int mt = 0; mt < 4; mt++)
#pragma unroll
        for (int nt = 0; nt < 8; nt++)
#pragma unroll
            for (int e = 0; e < 4; e++) acc[mt][nt][e] = 0.f;

    float4 ar[4], br[4];
#pragma unroll
    for (int p = 0; p < 4; p++) {
        ar[p] = *(const float4*)(Ap + p * row32);
        br[p] = *(const float4*)(Bp + p * row32);
    }
#pragma unroll
    for (int p = 0; p < 4; p++) {
        sm.As[0][kc + 0][lr + p * 32] = f2tf32(ar[p].x);
        sm.As[0][kc + 1][lr + p * 32] = f2tf32(ar[p].y);
        sm.As[0][kc + 2][lr + p * 32] = f2tf32(ar[p].z);
        sm.As[0][kc + 3][lr + p * 32] = f2tf32(ar[p].w);
        sm.Bs[0][kc + 0][lr + p * 32] = f2tf32(br[p].x);
        sm.Bs[0][kc + 1][lr + p * 32] = f2tf32(br[p].y);
        sm.Bs[0][kc + 2][lr + p * 32] = f2tf32(br[p].z);
        sm.Bs[0][kc + 3][lr + p * 32] = f2tf32(br[p].w);
    }
    __syncthreads();

    int cur = 0;
    for (int k0 = 0; k0 < K; k0 += 16) {
        const bool more = (k0 + 16 < K);
        if (more) {
#pragma unroll
            for (int p = 0; p < 4; p++) {
                ar[p] = *(const float4*)(Ap + k0 + 16 + p * row32);
                br[p] = *(const float4*)(Bp + k0 + 16 + p * row32);
            }
        }

#pragma unroll
        for (int ks = 0; ks < 2; ks++) {
            const int kk = ks * 8;
            uint32_t af[4][4], bf[8][2];
#pragma unroll
            for (int mt = 0; mt < 4; mt++) {
                const int m = wm + mt * 16 + gid;
                af[mt][0] = sm.As[cur][kk + tig][m];
                af[mt][1] = sm.As[cur][kk + tig][m + 8];
                af[mt][2] = sm.As[cur][kk + tig + 4][m];
                af[mt][3] = sm.As[cur][kk + tig + 4][m + 8];
            }
#pragma unroll
            for (int nt = 0; nt < 8; nt++) {
                const int n = wn + nt * 8 + gid;
                bf[nt][0] = sm.Bs[cur][kk + tig][n];
                bf[nt][1] = sm.Bs[cur][kk + tig + 4][n];
            }
#pragma unroll
            for (int mt = 0; mt < 4; mt++)
#pragma unroll
                for (int nt = 0; nt < 8; nt++) {
                    asm volatile(
                        "mma.sync.aligned.m16n8k8.row.col.f32.tf32.tf32.f32 "
                        "{%0,%1,%2,%3}, {%4,%5,%6,%7}, {%8,%9}, {%0,%1,%2,%3};"
                        : "+f"(acc[mt][nt][0]), "+f"(acc[mt][nt][1]),
                          "+f"(acc[mt][nt][2]), "+f"(acc[mt][nt][3])
                        : "r"(af[mt][0]), "r"(af[mt][1]),
                          "r"(af[mt][2]), "r"(af[mt][3]),
                          "r"(bf[nt][0]), "r"(bf[nt][1]));
                }
        }

        if (more) {
            const int nxt = cur ^ 1;
#pragma unroll
            for (int p = 0; p < 4; p++) {
                sm.As[nxt][kc + 0][lr + p * 32] = f2tf32(ar[p].x);
                sm.As[nxt][kc + 1][lr + p * 32] = f2tf32(ar[p].y);
                sm.As[nxt][kc + 2][lr + p * 32] = f2tf32(ar[p].z);
                sm.As[nxt][kc + 3][lr + p * 32] = f2tf32(ar[p].w);
                sm.Bs[nxt][kc + 0][lr + p * 32] = f2tf32(br[p].x);
                sm.Bs[nxt][kc + 1][lr + p * 32] = f2tf32(br[p].y);
                sm.Bs[nxt][kc + 2][lr + p * 32] = f2tf32(br[p].z);
                sm.Bs[nxt][kc + 3][lr + p * 32] = f2tf32(br[p].w);
            }
            __syncthreads();
        }
        cur ^= 1;
    }

#pragma unroll
    for (int mt = 0; mt < 4; mt++) {
        const int r0 = bm + wm + mt * 16 + gid;
#pragma unroll
        for (int nt = 0; nt < 8; nt++) {
            const int cc = bn + wn + nt * 8 + tig * 2;
            *(float2*)&C[(size_t)r0 * N + cc] =
                make_float2(acc[mt][nt][0], acc[mt][nt][1]);
            *(float2*)&C[(size_t)(r0 + 8) * N + cc] =
                make_float2(acc[mt][nt][2], acc[mt][nt][3]);
        }
    }
}

__global__ __launch_bounds__(128)
void tgemm_nt(const float* __restrict__ A, const float* __restrict__ B,
              float* __restrict__ C, int M, int N, int K) {
    __shared__ GSmem sm;
    gemm_tile(A, B, C, N, K, blockIdx.x * 128, blockIdx.y * 128, sm);
}

// ---------------------------------------------------------------------------
// Kernel A: per-chunk state increment via bf16x3 MMA (R14 proven)
// ---------------------------------------------------------------------------
__global__ __launch_bounds__(256, 2)
void state_mma_kernel(const float* __restrict__ Km, const float* __restrict__ V,
                      float* __restrict__ DS) {
    __shared__ float ks[128][17];
    __shared__ uint32_t vh[64][72];
    __shared__ uint32_t vl[64][72];
    __shared__ uchar2 ptab[136];
    const int ck = blockIdx.x, bh = blockIdx.y;
    const int b = bh >> 4, h = bh & 15;
    const int tid = threadIdx.x;
    const int warp = tid >> 5, lane = tid & 31;
    const int gid = lane >> 2, tig = lane & 3;
    const int wr = warp >> 2, wc = warp & 3;
    const int tokb = b * SEQ + ck * CHUNK;

    for (int t = tid; t < 512; t += 256) {
        int r = t >> 2, c4 = (t & 3) << 2;
        float4 kv = *(const float4*)&Km[(size_t)(tokb + r) * QKDIM + h * FDIM + c4];
        ks[r][c4 + 0] = kv.x; ks[r][c4 + 1] = kv.y;
        ks[r][c4 + 2] = kv.z; ks[r][c4 + 3] = kv.w;
    }
    if (tid < 128) ks[tid][16] = 1.0f;
    for (int t = tid; t < 1024; t += 256) {
        int kp = t >> 4, c4 = (t & 15) << 2;
        float4 a = *(const float4*)&V[(size_t)(tokb + 2 * kp) * VDIM + h * HDIM + c4];
        float4 bb = *(const float4*)&V[(size_t)(tokb + 2 * kp + 1) * VDIM + h * HDIM + c4];
        const float av[4] = {a.x, a.y, a.z, a.w};
        const float bv[4] = {bb.x, bb.y, bb.z, bb.w};
#pragma unroll
        for (int e = 0; e < 4; e++) {
            uint32_t hp, lp;
            split_bf(av[e], bv[e], hp, lp);
            vh[kp][c4 + e] = hp;
            vl[kp][c4 + e] = lp;
        }
    }
    if (tid < 136) {
        int i, j;
        p2ij(tid, i, j);
        ptab[tid] = make_uchar2((unsigned char)i, (unsigned char)j);
    }
    __syncthreads();

    int ia[5][2], ja[5][2];
    float wt[5][2];
#pragma unroll
    for (int mt = 0; mt < 5; mt++) {
#pragma unroll
        for (int hw = 0; hw < 2; hw++) {
            const int row = wr * 80 + mt * 16 + gid + hw * 8;
            int i, j; float w;
            if (row == 0)        { i = 16; j = 16; w = 1.f; }
            else if (row < 17)   { i = row - 1; j = 16; w = 0.5f; }
            else if (row < PROW) { uchar2 p = ptab[row - 17]; i = p.x; j = p.y; w = C2F; }
            else                 { i = 16; j = 16; w = 0.f; }
            ia[mt][hw] = i; ja[mt][hw] = j; wt[mt][hw] = w;
        }
    }

    float acc[5][2][4];
#pragma unroll
    for (int mt = 0; mt < 5; mt++)
#pragma unroll
        for (int nt = 0; nt < 2; nt++)
#pragma unroll
            for (int e = 0; e < 4; e++) acc[mt][nt][e] = 0.f;

    for (int kss = 0; kss < 8; kss++) {
        uint32_t b_h0[2], b_h1[2], b_l0[2], b_l1[2];
#pragma unroll
        for (int nt = 0; nt < 2; nt++) {
            const int n = wc * 16 + nt * 8 + gid;
            b_h0[nt] = vh[kss * 8 + tig][n];
            b_h1[nt] = vh[kss * 8 + tig + 4][n];
            b_l0[nt] = vl[kss * 8 + tig][n];
            b_l1[nt] = vl[kss * 8 + tig + 4][n];
        }
        const int t0 = kss * 16 + 2 * tig;
        const int t2 = t0 + 8;
#pragma unroll
        for (int mt = 0; mt < 5; mt++) {
            const int i0 = ia[mt][0], j0 = ja[mt][0];
            const int i1 = ia[mt][1], j1 = ja[mt][1];
            const float w0 = wt[mt][0], w1 = wt[mt][1];
            float f00 = w0 * ks[t0][i0] * ks[t0][j0];
            float f01 = w0 * ks[t0 + 1][i0] * ks[t0 + 1][j0];
            float f10 = w1 * ks[t0][i1] * ks[t0][j1];
            float f11 = w1 * ks[t0 + 1][i1] * ks[t0 + 1][j1];
            float f02 = w0 * ks[t2][i0] * ks[t2][j0];
            float f03 = w0 * ks[t2 + 1][i0] * ks[t2 + 1][j0];
            float f12 = w1 * ks[t2][i1] * ks[t2][j1];
            float f13 = w1 * ks[t2 + 1][i1] * ks[t2 + 1][j1];
            uint32_t ah[4], al[4];
            split_bf(f00, f01, ah[0], al[0]);
            split_bf(f10, f11, ah[1], al[1]);
            split_bf(f02, f03, ah[2], al[2]);
            split_bf(f12, f13, ah[3], al[3]);
#pragma unroll
            for (int nt = 0; nt < 2; nt++) {
                MMA_BF16(acc[mt][nt], ah, b_h0[nt], b_h1[nt]);
                MMA_BF16(acc[mt][nt], ah, b_l0[nt], b_l1[nt]);
                MMA_BF16(acc[mt][nt], al, b_h0[nt], b_h1[nt]);
            }
        }
    }

    float* base = DS + (size_t)(bh * NCHUNK + ck) * SDF_P;
#pragma unroll
    for (int mt = 0; mt < 5; mt++) {
        const int ra = wr * 80 + mt * 16 + gid;
        const int rb = ra + 8;
#pragma unroll
        for (int nt = 0; nt < 2; nt++) {
            const int n = wc * 16 + nt * 8 + tig * 2;
            if (ra < PROW)
                *(float2*)&base[ra * HDIM + n] =
                    make_float2(acc[mt][nt][0], acc[mt][nt][1]);
            if (rb < PROW)
                *(float2*)&base[rb * HDIM + n] =
                    make_float2(acc[mt][nt][2], acc[mt][nt][3]);
        }
    }
}

// ---------------------------------------------------------------------------
// Kernel B: exclusive scan over packed rows (153) into g_SP.
// ---------------------------------------------------------------------------
__global__ void scan_kernel(const float* __restrict__ DS, float* __restrict__ SP,
                            float* __restrict__ kv_out) {
    const int bh = blockIdx.y;
    const int e4 = blockIdx.x * 256 + threadIdx.x;
    if (e4 >= PROW * 16) return;
    const int dp = e4 >> 4, f0 = (e4 & 15) * 4;

    int pi = 0, pj = 0;
    float scale = 1.f;
    if (dp >= 17) {
        p2ij(dp - 17, pi, pj);
        scale = (pi == pj) ? 1.f : 2.f;
    }

    const float* src = DS + (size_t)bh * NCHUNK * SDF_P + (size_t)dp * HDIM + f0;
    float* dst = SP + (size_t)bh * NCHUNK * SDF_P + (size_t)dp * HDIM + f0;
    float4 run = make_float4(0.f, 0.f, 0.f, 0.f);
#pragma unroll
    for (int c = 0; c < NCHUNK; c++) {
        float4 v = *(const float4*)(src + (size_t)c * SDF_P);
        *(float4*)(dst + (size_t)c * SDF_P) =
            make_float4(run.x * scale, run.y * scale, run.z * scale, run.w * scale);
        run.x += v.x; run.y += v.y; run.z += v.z; run.w += v.w;
    }
    if (kv_out) {
        float* kb = kv_out + (size_t)bh * (HDIM * FEAT);
        const float rv[4] = {run.x, run.y, run.z, run.w};
        if (dp < 17) {
#pragma unroll
            for (int ff = 0; ff < 4; ff++)
                kb[(size_t)(f0 + ff) * FEAT + dp] = rv[ff];
        } else {
            const int d1 = 17 + pi * 16 + pj, d2 = 17 + pj * 16 + pi;
#pragma unroll
            for (int ff = 0; ff < 4; ff++) {
                kb[(size_t)(f0 + ff) * FEAT + d1] = rv[ff];
                kb[(size_t)(f0 + ff) * FEAT + d2] = rv[ff];
            }
        }
    }
}

// ---------------------------------------------------------------------------
// Kernel C: inter-chunk bf16x3 MMA over PACKED S (10 k-steps) + intra-chunk
// causal via two-stage MMA (scores -> poly/mask -> P@V), RMSNorm + g.
// smem floats: QS[0,2176) kh[2176,3328) kl[3328,4480) vh[4480,9088)
//              vl[9088,13696) shw[13696,14848) slw[14848,16000) gs[16000,16064)
// ---------------------------------------------------------------------------
#define AK_QS(r,c)     dyn[(r)*17+(c)]                 // q*SC, col16 = 1.0
#define ATTN_SMEM      (16064*4)                       // 64,256 bytes
#define AK_SHW(b,rp,n) shw[(b)*576+(rp)*72+(n)]
#define AK_SLW(b,rp,n) slw[(b)*576+(rp)*72+(n)]

__device__ __forceinline__ float qfeatp(const float* dyn, const uchar2* ptab,
                                        int r, int d) {
    if (d == 0) return 1.0f;
    if (d < 17) return AK_QS(r, d - 1) * 1.1892071150027210f;   // 0.5/SC folded
    if (d < PROW) {
        const uchar2 ij = ptab[d - 17];
        return AK_QS(r, ij.x) * AK_QS(r, ij.y);
    }
    return 0.f;
}

__global__ __launch_bounds__(256, 2)
void attn_out_kernel(const float* __restrict__ Q, const float* __restrict__ Km,
                     const float* __restrict__ V, const float* __restrict__ Sprev,
                     const float* __restrict__ g, float* __restrict__ Y) {
    extern __shared__ float dyn[];
    __shared__ uchar2 ptab[136];
    uint32_t* kh = (uint32_t*)(dyn + 2176);    // [128][9]
    uint32_t* kl = (uint32_t*)(dyn + 3328);    // [128][9]
    uint32_t* vh = (uint32_t*)(dyn + 4480);    // [64][72]
    uint32_t* vl = (uint32_t*)(dyn + 9088);    // [64][72]
    uint32_t* shw = (uint32_t*)(dyn + 13696);
    uint32_t* slw = (uint32_t*)(dyn + 14848);
    float* gs = dyn + 16000;
    const int ck = blockIdx.x;
    const int bh = blockIdx.y;
    const int b = bh >> 4, h = bh & 15;
    const int tid = threadIdx.x;
    const int warp = tid >> 5, lane = tid & 31;
    const int gid = lane >> 2, tig = lane & 3;
    const int tok0 = b * SEQ + ck * CHUNK;
    const float SC  = 0.4204482076268573f;    // sqrt(1/(4*sqrt2))
    const float DOT = 2.3784142300054421f;    // 1/SC
    const float* Sp = Sprev + (size_t)(bh * NCHUNK + ck) * SDF_P;

    // ---- stage Q (scaled, padded) + K (packed bf16 dim-pairs, stride 9) ----
    for (int t = tid; t < 512; t += 256) {
        int r = t >> 2, c4 = (t & 3) << 2;
        float4 qv = *(const float4*)&Q[(size_t)(tok0 + r) * QKDIM + h * FDIM + c4];
        AK_QS(r, c4 + 0) = qv.x * SC; AK_QS(r, c4 + 1) = qv.y * SC;
        AK_QS(r, c4 + 2) = qv.z * SC; AK_QS(r, c4 + 3) = qv.w * SC;
        float4 kv = *(const float4*)&Km[(size_t)(tok0 + r) * QKDIM + h * FDIM + c4];
        uint32_t hp, lp;
        split_bf(kv.x, kv.y, hp, lp);
        kh[r * 9 + (c4 >> 1)] = hp; kl[r * 9 + (c4 >> 1)] = lp;
        split_bf(kv.z, kv.w, hp, lp);
        kh[r * 9 + (c4 >> 1) + 1] = hp; kl[r * 9 + (c4 >> 1) + 1] = lp;
    }
    if (tid < 128) AK_QS(tid, 16) = 1.0f;
    // ---- stage V packed bf16 token-pairs (hi/lo) ----
    for (int t = tid; t < 1024; t += 256) {
        int kp = t >> 4, c4 = (t & 15) << 2;
        float4 a = *(const float4*)&V[(size_t)(tok0 + 2 * kp) * VDIM + h * HDIM + c4];
        float4 bb = *(const float4*)&V[(size_t)(tok0 + 2 * kp + 1) * VDIM + h * HDIM + c4];
        const float av[4] = {a.x, a.y, a.z, a.w};
        const float bv[4] = {bb.x, bb.y, bb.z, bb.w};
#pragma unroll
        for (int e = 0; e < 4; e++) {
            uint32_t hp, lp;
            split_bf(av[e], bv[e], hp, lp);
            vh[kp * 72 + c4 + e] = hp;
            vl[kp * 72 + c4 + e] = lp;
        }
    }
    if (tid < 64) gs[tid] = g[tid];
    if (tid < 136) {
        int i, j;
        p2ij(tid, i, j);
        ptab[tid] = make_uchar2((unsigned char)i, (unsigned char)j);
    }
    {   // S tile for step 0
#pragma unroll
        for (int q = 0; q < 2; q++) {
            const int id = tid + q * 256;
            const int rp = id >> 6, n = id & 63;
            const int fr = 2 * rp;
            float v0 = Sp[fr * HDIM + n];
            float v1 = Sp[(fr + 1) * HDIM + n];
            uint32_t hp, lp;
            split_bf(v0, v1, hp, lp);
            AK_SHW(0, rp, n) = hp;
            AK_SLW(0, rp, n) = lp;
        }
    }
    __syncthreads();

    float acc[8][4];
#pragma unroll
    for (int nt = 0; nt < 8; nt++)
#pragma unroll
        for (int e = 0; e < 4; e++) acc[nt][e] = 0.f;

    const int r0 = warp * 16 + gid;
    const int r1 = r0 + 8;

    // ---- inter-chunk: y += qf @ S_packed via bf16x3 MMA, 10 k-steps ----
    int buf = 0;
    for (int s = 0; s < 10; s++) {
        float p00 = 0.f, p01 = 0.f, p10 = 0.f, p11 = 0.f;
        int rpA = 0, nA = 0, rpB = 0, nB = 0;
        if (s < 9) {
            const int fb = 16 * (s + 1);
            int idA = tid;           rpA = idA >> 6; nA = idA & 63;
            int idB = tid + 256;     rpB = idB >> 6; nB = idB & 63;
            int frA = fb + 2 * rpA, frB = fb + 2 * rpB;
            if (frA < PROW)     p00 = Sp[frA * HDIM + nA];
            if (frA + 1 < PROW) p01 = Sp[(frA + 1) * HDIM + nA];
            if (frB < PROW)     p10 = Sp[frB * HDIM + nB];
            if (frB + 1 < PROW) p11 = Sp[(frB + 1) * HDIM + nB];
        }
        const int da = 16 * s + 2 * tig;
        const int db = da + 8;
        float f00 = qfeatp(dyn, ptab, r0, da),  f01 = qfeatp(dyn, ptab, r0, da + 1);
        float f10 = qfeatp(dyn, ptab, r1, da),  f11 = qfeatp(dyn, ptab, r1, da + 1);
        float f02 = qfeatp(dyn, ptab, r0, db),  f03 = qfeatp(dyn, ptab, r0, db + 1);
        float f12 = qfeatp(dyn, ptab, r1, db),  f13 = qfeatp(dyn, ptab, r1, db + 1);
        uint32_t ah[4], al[4];
        split_bf(f00, f01, ah[0], al[0]);
        split_bf(f10, f11, ah[1], al[1]);
        split_bf(f02, f03, ah[2], al[2]);
        split_bf(f12, f13, ah[3], al[3]);
#pragma unroll
        for (int nt = 0; nt < 8; nt++) {
            const int n = nt * 8 + gid;
            uint32_t bh0 = AK_SHW(buf, tig, n);
            uint32_t bh1 = AK_SHW(buf, tig + 4, n);
            uint32_t bl0 = AK_SLW(buf, tig, n);
            uint32_t bl1 = AK_SLW(buf, tig + 4, n);
            MMA_BF16(acc[nt], ah, bh0, bh1);
            MMA_BF16(acc[nt], ah, bl0, bl1);
            MMA_BF16(acc[nt], al, bh0, bh1);
        }
        if (s < 9) {
            const int nb = buf ^ 1;
            uint32_t hp, lp;
            split_bf(p00, p01, hp, lp);
            AK_SHW(nb, rpA, nA) = hp;
            AK_SLW(nb, rpA, nA) = lp;
            split_bf(p10, p11, hp, lp);
            AK_SHW(nb, rpB, nB) = hp;
            AK_SLW(nb, rpB, nB) = lp;
            __syncthreads();
            buf = nb;
        }
    }

    // ---- intra-chunk causal via MMA: scores -> poly/mask -> P@V ----
    // loop-invariant score A-fragment (q rows x 16 dims)
    uint32_t qah[4], qal[4];
    split_bf(AK_QS(r0, 2 * tig),     AK_QS(r0, 2 * tig + 1),     qah[0], qal[0]);
    split_bf(AK_QS(r1, 2 * tig),     AK_QS(r1, 2 * tig + 1),     qah[1], qal[1]);
    split_bf(AK_QS(r0, 2 * tig + 8), AK_QS(r0, 2 * tig + 9),     qah[2], qal[2]);
    split_bf(AK_QS(r1, 2 * tig + 8), AK_QS(r1, 2 * tig + 9),     qah[3], qal[3]);

    for (int s = 0; s <= warp; s++) {
        float sc[2][4];
#pragma unroll
        for (int tt = 0; tt < 2; tt++) {
#pragma unroll
            for (int e = 0; e < 4; e++) sc[tt][e] = 0.f;
            const int tokbase = s * 16 + tt * 8;
            uint32_t bh0 = kh[(tokbase + gid) * 9 + tig];
            uint32_t bh1 = kh[(tokbase + gid) * 9 + tig + 4];
            uint32_t bl0 = kl[(tokbase + gid) * 9 + tig];
            uint32_t bl1 = kl[(tokbase + gid) * 9 + tig + 4];
            MMA_BF16(sc[tt], qah, bh0, bh1);
            MMA_BF16(sc[tt], qah, bl0, bl1);
            MMA_BF16(sc[tt], qal, bh0, bh1);
        }
        // poly + causal mask (diag step only)
        const bool diag = (s == warp);
#pragma unroll
        for (int tt = 0; tt < 2; tt++)
#pragma unroll
            for (int e = 0; e < 4; e++) {
                const float sd = sc[tt][e] * DOT;
                float A = fmaf(sd, 0.25f, 1.0f);
                A = fmaf(sd * sd, 0.03125f, A);
                if (diag) {
                    const int tok = tt * 8 + 2 * tig + (e & 1);
                    const int row = gid + ((e >> 1) << 3);
                    A = (tok <= row) ? A : 0.f;
                }
                sc[tt][e] = A;
            }
        // pack P (score accumulators -> A-fragment) and P@V
        uint32_t pah[4], pal[4];
        split_bf(sc[0][0], sc[0][1], pah[0], pal[0]);
        split_bf(sc[0][2], sc[0][3], pah[1], pal[1]);
        split_bf(sc[1][0], sc[1][1], pah[2], pal[2]);
        split_bf(sc[1][2], sc[1][3], pah[3], pal[3]);
#pragma unroll
        for (int ft = 0; ft < 8; ft++) {
            const int f = ft * 8 + gid;
            uint32_t vb0 = vh[(s * 8 + tig) * 72 + f];
            uint32_t vb1 = vh[(s * 8 + tig + 4) * 72 + f];
            uint32_t vc0 = vl[(s * 8 + tig) * 72 + f];
            uint32_t vc1 = vl[(s * 8 + tig + 4) * 72 + f];
            MMA_BF16(acc[ft], pah, vb0, vb1);
            MMA_BF16(acc[ft], pah, vc0, vc1);
            MMA_BF16(acc[ft], pal, vb0, vb1);
        }
    }

    // ---- RMSNorm (reduce across tig lanes) + gate + store ----
    float ss0 = 0.f, ss1 = 0.f;
#pragma unroll
    for (int nt = 0; nt < 8; nt++) {
        ss0 = fmaf(acc[nt][0], acc[nt][0], ss0);
        ss0 = fmaf(acc[nt][1], acc[nt][1], ss0);
        ss1 = fmaf(acc[nt][2], acc[nt][2], ss1);
        ss1 = fmaf(acc[nt][3], acc[nt][3], ss1);
    }
    ss0 += __shfl_xor_sync(0xffffffffu, ss0, 1);
    ss0 += __shfl_xor_sync(0xffffffffu, ss0, 2);
    ss1 += __shfl_xor_sync(0xffffffffu, ss1, 1);
    ss1 += __shfl_xor_sync(0xffffffffu, ss1, 2);
    const float rms0 = rsqrtf(ss0 * (1.0f / 64.0f) + 1e-5f);
    const float rms1 = rsqrtf(ss1 * (1.0f / 64.0f) + 1e-5f);
    float* y0 = Y + (size_t)(tok0 + r0) * VDIM + h * HDIM;
    float* y1 = Y + (size_t)(tok0 + r1) * VDIM + h * HDIM;
#pragma unroll
    for (int nt = 0; nt < 8; nt++) {
        const int c = nt * 8 + tig * 2;
        float2 o0, o1;
        o0.x = acc[nt][0] * rms0 * gs[c];
        o0.y = acc[nt][1] * rms0 * gs[c + 1];
        o1.x = acc[nt][2] * rms1 * gs[c];
        o1.y = acc[nt][3] * rms1 * gs[c + 1];
        *(float2*)&y0[c] = o0;
        *(float2*)&y1[c] = o1;
    }
}

// ---------------------------------------------------------------------------
extern "C" void kernel_launch(void* const* d_in, const int* in_sizes, int n_in,
                              void* d_out, int out_size) {
    const float* X  = (const float*)d_in[0];
    const float* Wq = (const float*)d_in[1];
    const float* Wk = (const float*)d_in[2];
    const float* Wv = (const float*)d_in[3];
    const float* Wo = (const float*)d_in[4];
    const float* g  = (const float*)d_in[5];
    float* out = (float*)d_out;

    float *Qb, *Kb, *Vb, *Yb, *Sb, *SPb;
    cudaGetSymbolAddress((void**)&Qb, g_Q);
    cudaGetSymbolAddress((void**)&Kb, g_K);
    cudaGetSymbolAddress((void**)&Vb, g_V);
    cudaGetSymbolAddress((void**)&Yb, g_Y);
    cudaGetSymbolAddress((void**)&Sb, g_DS);
    cudaGetSymbolAddress((void**)&SPb, g_SP);

    static int attn_smem_set = 0;
    if (!attn_smem_set) {
        cudaFuncSetAttribute(attn_out_kernel,
                             cudaFuncAttributeMaxDynamicSharedMemorySize,
                             ATTN_SMEM);
        attn_smem_set = 1;
    }

    // Projections (separate launches — proven fastest config)
    tgemm_nt<<<dim3(NTOK / 128, QKDIM / 128), 128>>>(X, Wq, Qb, NTOK, QKDIM, DMODEL);
    tgemm_nt<<<dim3(NTOK / 128, QKDIM / 128), 128>>>(X, Wk, Kb, NTOK, QKDIM, DMODEL);
    tgemm_nt<<<dim3(NTOK / 128, VDIM / 128),  128>>>(X, Wv, Vb, NTOK, VDIM,  DMODEL);

    // Chunked linear attention (packed symmetric states, all-MMA)
    float* kv_out = (out_size >= OUT_ELEMS + KV_ELEMS) ? (out + OUT_ELEMS) : nullptr;
    state_mma_kernel<<<dim3(NCHUNK, BATCH * NHEADS), 256>>>(Kb, Vb, Sb);
    scan_kernel<<<dim3((PROW * 16 + 255) / 256, BATCH * NHEADS), 256>>>(
        Sb, SPb, kv_out);
    attn_out_kernel<<<dim3(NCHUNK, BATCH * NHEADS), 256, ATTN_SMEM>>>(
        Qb, Kb, Vb, SPb, g, Yb);

    // Output projection
    tgemm_nt<<<dim3(NTOK / 128, DMODEL / 128), 128>>>(Yb, Wo, out, NTOK, DMODEL, DMODEL);
}